// round 6
// baseline (speedup 1.0000x reference)
#include <cuda_runtime.h>
#include <cuda_bf16.h>
#include <math.h>
#include <stdint.h>

#define B_    16
#define S_    8192
#define D_    128
#define H_    512
#define NROT  3
#define NMAT  (B_ * NROT)          // 48
#define MATSZ (D_ * D_)            // 16384
#define W2ROWS (NROT * D_ * D_)    // 49152

// ---------------- scratch ----------------
__device__ float g_partial[B_ * 8 * D_];
__device__ float g_h[B_ * H_];
__device__ float g_P[B_ * W2ROWS];          // P[b][r]
__device__ float g_Dl[NMAT * MATSZ];        // Delta = expm(g) - I per matrix
__device__ uint32_t g_frag[B_ * 8192];      // bf16 B-fragments of Delta_R per batch

// ---------------- packed f32x2 (pgemm) ----------------
__device__ __forceinline__ unsigned long long dup2(float a) {
    unsigned long long r; asm("mov.b64 %0, {%1, %1};" : "=l"(r) : "f"(a)); return r;
}
__device__ __forceinline__ unsigned long long fma2(unsigned long long a,
                                                   unsigned long long b,
                                                   unsigned long long c) {
    unsigned long long d;
    asm("fma.rn.f32x2 %0, %1, %2, %3;" : "=l"(d) : "l"(a), "l"(b), "l"(c));
    return d;
}
__device__ __forceinline__ float2 unpk(unsigned long long v) {
    float2 f; asm("mov.b64 {%0, %1}, %2;" : "=f"(f.x), "=f"(f.y) : "l"(v)); return f;
}

// ---------------- mma.sync / ldmatrix helpers ----------------
__device__ __forceinline__ uint32_t smem_u32(const void* p) {
    uint32_t a;
    asm("{ .reg .u64 t; cvta.to.shared.u64 t, %1; cvt.u32.u64 %0, t; }" : "=r"(a) : "l"(p));
    return a;
}
__device__ __forceinline__ void ldsm_x4(uint32_t* r, uint32_t addr) {
    asm volatile("ldmatrix.sync.aligned.m8n8.x4.shared.b16 {%0,%1,%2,%3}, [%4];"
                 : "=r"(r[0]), "=r"(r[1]), "=r"(r[2]), "=r"(r[3]) : "r"(addr));
}
__device__ __forceinline__ void ldsm_x2_trans(uint32_t* r, uint32_t addr) {
    asm volatile("ldmatrix.sync.aligned.m8n8.x2.trans.shared.b16 {%0,%1}, [%2];"
                 : "=r"(r[0]), "=r"(r[1]) : "r"(addr));
}
__device__ __forceinline__ void mma16816(float* c, const uint32_t* a, const uint32_t* b) {
    asm volatile("mma.sync.aligned.m16n8k16.row.col.f32.bf16.bf16.f32 "
                 "{%0,%1,%2,%3}, {%4,%5,%6,%7}, {%8,%9}, {%0,%1,%2,%3};"
                 : "+f"(c[0]), "+f"(c[1]), "+f"(c[2]), "+f"(c[3])
                 : "r"(a[0]), "r"(a[1]), "r"(a[2]), "r"(a[3]), "r"(b[0]), "r"(b[1]));
}
__device__ __forceinline__ uint32_t pack_bf2(float a, float b) {
    __nv_bfloat162 h = __floats2bfloat162_rn(a, b);
    return *reinterpret_cast<uint32_t*>(&h);
}

#define LDA 136                      // bf16 plane row stride (elements)
// chain/combine smem layout (bytes)
#define CH_AH 0
#define CH_DH 34816
#define CH_AF 69632                  // fp32 [128][128]
#define CH_ST 135168                 // fp32 [128][132]
#define CH_TOTAL 202752
// apply smem layout
#define AP_XF 0                      // fp32 [128][132] = 67584
#define AP_XH 67584                  // bf16 [128][136] = 34816
#define AP_TOTAL 102400

// 1-pass 128x128x128 bf16 MMA: acc += A(pa) @ B(pb), planes in smem
__device__ __forceinline__ void mma128(uint32_t pa, uint32_t pb,
                                       float acc[2][8][4], int lane, int wid) {
    int m0 = (wid & 3) << 5, n0 = (wid >> 2) << 6;
    int arow = lane & 15, acol = (lane >> 4) << 3;
    #pragma unroll
    for (int ks = 0; ks < 8; ks++) {
        int k0 = ks << 4;
        uint32_t a0[4], a1[4];
        ldsm_x4(a0, pa + (uint32_t)(((m0 + arow) * LDA + k0 + acol) << 1));
        ldsm_x4(a1, pa + (uint32_t)(((m0 + 16 + arow) * LDA + k0 + acol) << 1));
        uint32_t bfr[8][2];
        #pragma unroll
        for (int j = 0; j < 8; j++)
            ldsm_x2_trans(bfr[j], pb + (uint32_t)(((k0 + arow) * LDA + n0 + (j << 3)) << 1));
        #pragma unroll
        for (int j = 0; j < 8; j++) {
            mma16816(acc[0][j], a0, bfr[j]);
            mma16816(acc[1][j], a1, bfr[j]);
        }
    }
}

// ---------------- 1) mean over S (float4) ----------------
__global__ void mean_partial_kernel(const float* __restrict__ x) {
    int b = blockIdx.y, chunk = blockIdx.x;
    int t = threadIdx.x, lane = t & 31, grp = t >> 5;
    const float* xp = x + ((size_t)b * S_ + (size_t)chunk * 1024 + grp) * D_ + lane * 4;
    float4 s = make_float4(0.f, 0.f, 0.f, 0.f);
    #pragma unroll 8
    for (int i = 0; i < 128; i++) {
        float4 v = *(const float4*)xp;
        s.x += v.x; s.y += v.y; s.z += v.z; s.w += v.w;
        xp += 8 * D_;
    }
    __shared__ float4 red[256];
    red[t] = s;
    __syncthreads();
    if (grp < 4) {
        float4 o = red[t + 128];
        red[t] = make_float4(red[t].x + o.x, red[t].y + o.y, red[t].z + o.z, red[t].w + o.w);
    }
    __syncthreads();
    if (grp < 2) {
        float4 o = red[t + 64];
        red[t] = make_float4(red[t].x + o.x, red[t].y + o.y, red[t].z + o.z, red[t].w + o.w);
    }
    __syncthreads();
    if (grp == 0) {
        float4 o = red[t + 32];
        float4 r = make_float4(red[t].x + o.x, red[t].y + o.y, red[t].z + o.z, red[t].w + o.w);
        *(float4*)&g_partial[(b * 8 + chunk) * D_ + lane * 4] = r;
    }
}

// ---------------- 2) h = gelu(pooled @ W1^T + b1) ----------------
__global__ void h_kernel(const float* __restrict__ W1, const float* __restrict__ b1) {
    int b = blockIdx.x, t = threadIdx.x;
    __shared__ float ps[D_];
    if (t < D_) {
        float s = 0.f;
        #pragma unroll
        for (int c = 0; c < 8; c++) s += g_partial[(b * 8 + c) * D_ + t];
        ps[t] = s * (1.0f / (float)S_);
    }
    __syncthreads();
    float acc = b1[t];
    const float* w = W1 + (size_t)t * D_;
    #pragma unroll 8
    for (int k = 0; k < D_; k++) acc = fmaf(ps[k], w[k], acc);
    float z = acc;
    g_h[b * H_ + t] = 0.5f * z * (1.0f + erff(z * 0.70710678118654752f));
}

// ---------------- 3) P = W2 @ h^T + b2 -> P[b][r], 256 threads k-split ----------------
#define WS_LD 68
__global__ __launch_bounds__(256) void pgemm_kernel(const float* __restrict__ W2,
                                                    const float* __restrict__ b2) {
    extern __shared__ float sm[];
    float* hs = sm;                         // [512][16] (also exchange buffer later)
    float* ws = sm + H_ * B_;               // 2 x [128][68]
    int t = threadIdx.x;
    int rloc = t & 127, kh = t >> 7;
    int row0 = blockIdx.x * 128;

    for (int idx = t; idx < H_ * B_; idx += 256) {
        int bb = idx >> 9, k = idx & 511;
        hs[k * B_ + bb] = g_h[idx];
    }

    unsigned long long acc[8];
    #pragma unroll
    for (int j = 0; j < 8; j++) acc[j] = 0ull;

    float* wsh = ws + kh * 128 * WS_LD;
    for (int c = 0; c < 4; c++) {
        int kc = kh * 4 + c;
        __syncthreads();
        for (int idx = rloc; idx < 2048; idx += 128) {
            int rr = idx >> 4, k4 = (idx & 15) << 2;
            *(float4*)&wsh[rr * WS_LD + k4] =
                *(const float4*)&W2[(size_t)(row0 + rr) * H_ + kc * 64 + k4];
        }
        __syncthreads();
        #pragma unroll 4
        for (int k = 0; k < 64; k++) {
            unsigned long long wd = dup2(wsh[rloc * WS_LD + k]);
            const float* hrow = &hs[(kc * 64 + k) * B_];
            ulonglong2 a = *(const ulonglong2*)(hrow);
            ulonglong2 bq = *(const ulonglong2*)(hrow + 4);
            ulonglong2 cc = *(const ulonglong2*)(hrow + 8);
            ulonglong2 dq = *(const ulonglong2*)(hrow + 12);
            acc[0] = fma2(wd, a.x, acc[0]);  acc[1] = fma2(wd, a.y, acc[1]);
            acc[2] = fma2(wd, bq.x, acc[2]); acc[3] = fma2(wd, bq.y, acc[3]);
            acc[4] = fma2(wd, cc.x, acc[4]); acc[5] = fma2(wd, cc.y, acc[5]);
            acc[6] = fma2(wd, dq.x, acc[6]); acc[7] = fma2(wd, dq.y, acc[7]);
        }
    }
    __syncthreads();
    if (kh == 1) {
        float* ex = hs + rloc * 16;
        #pragma unroll
        for (int j = 0; j < 8; j++) {
            float2 f = unpk(acc[j]);
            ex[2 * j] = f.x; ex[2 * j + 1] = f.y;
        }
    }
    __syncthreads();
    if (kh == 0) {
        int r = row0 + rloc;
        float bias = b2[r];
        const float* ex = hs + rloc * 16;
        #pragma unroll
        for (int j = 0; j < 8; j++) {
            float2 f = unpk(acc[j]);
            g_P[(size_t)(2 * j)     * W2ROWS + r] = f.x + ex[2 * j]     + bias;
            g_P[(size_t)(2 * j + 1) * W2ROWS + r] = f.y + ex[2 * j + 1] + bias;
        }
    }
}

// ---------------- 4) fused antisym + expm chain (one launch) ----------------
// A = 0.5*(P - P^T)/8; Delta = expm(8A) - I via order-3 Taylor + 3 squarings.
__global__ __launch_bounds__(256, 1) void expm_chain_kernel() {
    extern __shared__ char smc[];
    uint32_t sb = smem_u32(smc);
    float* AF = (float*)(smc + CH_AF);
    float* ST = (float*)(smc + CH_ST);
    int t = threadIdx.x, lane = t & 31, wid = t >> 5;
    int m = blockIdx.x;
    int b = m / NROT, i = m - b * NROT;
    const float* P = g_P + (size_t)b * W2ROWS + (size_t)i * MATSZ;

    // stage P coalesced into ST
    for (int idx = t; idx < 4096; idx += 256) {
        int row = idx >> 5, c0 = (idx & 31) << 2;
        *(float4*)(ST + row * 132 + c0) = *(const float4*)(P + (row << 7) + c0);
    }
    __syncthreads();
    // A = (P - P^T) * 0.0625 -> AF (fp32) + AH (bf16 plane)
    for (int idx = t; idx < 16384; idx += 256) {
        int d = idx >> 7, e = idx & 127;
        float v = (ST[d * 132 + e] - ST[e * 132 + d]) * 0.0625f;
        AF[(d << 7) + e] = v;
        *(__nv_bfloat16*)(smc + CH_AH + ((d * LDA + e) << 1)) = __float2bfloat16(v);
    }
    __syncthreads();
    // init Delta = A/3
    for (int idx = t; idx < 4096; idx += 256) {
        int row = idx >> 5, c0 = (idx & 31) << 2;
        float4 v = *(const float4*)(AF + (row << 7) + c0);
        *(float4*)(ST + row * 132 + c0) =
            make_float4(v.x * (1.f/3.f), v.y * (1.f/3.f), v.z * (1.f/3.f), v.w * (1.f/3.f));
    }
    __syncthreads();

    int m0 = (wid & 3) << 5, n0 = (wid >> 2) << 6;

    // Horner: Delta <- (A + A@Delta)/c for c = 2, 1
    #pragma unroll 1
    for (int step = 0; step < 2; step++) {
        float invc = (step == 0) ? 0.5f : 1.0f;
        for (int idx = t; idx < 4096; idx += 256) {
            int row = idx >> 5, c0 = (idx & 31) << 2;
            float4 v = *(const float4*)(ST + row * 132 + c0);
            int eo = (row * LDA + c0) << 1;
            *(uint32_t*)(smc + CH_DH + eo)     = pack_bf2(v.x, v.y);
            *(uint32_t*)(smc + CH_DH + eo + 4) = pack_bf2(v.z, v.w);
        }
        __syncthreads();
        float acc[2][8][4];
        #pragma unroll
        for (int mi = 0; mi < 2; mi++)
            #pragma unroll
            for (int j = 0; j < 8; j++)
                #pragma unroll
                for (int q = 0; q < 4; q++) acc[mi][j][q] = 0.f;
        mma128(sb + CH_AH, sb + CH_DH, acc, lane, wid);
        #pragma unroll
        for (int mi = 0; mi < 2; mi++)
            #pragma unroll
            for (int j = 0; j < 8; j++) {
                int r = m0 + (mi << 4) + (lane >> 2);
                int c = n0 + (j << 3) + ((lane & 3) << 1);
                ST[r * 132 + c]           = (AF[(r << 7) + c]           + acc[mi][j][0]) * invc;
                ST[r * 132 + c + 1]       = (AF[(r << 7) + c + 1]       + acc[mi][j][1]) * invc;
                ST[(r + 8) * 132 + c]     = (AF[((r + 8) << 7) + c]     + acc[mi][j][2]) * invc;
                ST[(r + 8) * 132 + c + 1] = (AF[((r + 8) << 7) + c + 1] + acc[mi][j][3]) * invc;
            }
        __syncthreads();
    }

    // Squarings: Delta <- 2*Delta + Delta^2, x3
    #pragma unroll 1
    for (int sq = 0; sq < 3; sq++) {
        for (int idx = t; idx < 4096; idx += 256) {
            int row = idx >> 5, c0 = (idx & 31) << 2;
            float4 v = *(const float4*)(ST + row * 132 + c0);
            int eo = (row * LDA + c0) << 1;
            *(uint32_t*)(smc + CH_DH + eo)     = pack_bf2(v.x, v.y);
            *(uint32_t*)(smc + CH_DH + eo + 4) = pack_bf2(v.z, v.w);
        }
        __syncthreads();
        float acc[2][8][4];
        #pragma unroll
        for (int mi = 0; mi < 2; mi++)
            #pragma unroll
            for (int j = 0; j < 8; j++)
                #pragma unroll
                for (int q = 0; q < 4; q++) acc[mi][j][q] = 0.f;
        mma128(sb + CH_DH, sb + CH_DH, acc, lane, wid);
        #pragma unroll
        for (int mi = 0; mi < 2; mi++)
            #pragma unroll
            for (int j = 0; j < 8; j++) {
                int r = m0 + (mi << 4) + (lane >> 2);
                int c = n0 + (j << 3) + ((lane & 3) << 1);
                ST[r * 132 + c]           = 2.f * ST[r * 132 + c]           + acc[mi][j][0];
                ST[r * 132 + c + 1]       = 2.f * ST[r * 132 + c + 1]       + acc[mi][j][1];
                ST[(r + 8) * 132 + c]     = 2.f * ST[(r + 8) * 132 + c]     + acc[mi][j][2];
                ST[(r + 8) * 132 + c + 1] = 2.f * ST[(r + 8) * 132 + c + 1] + acc[mi][j][3];
            }
        __syncthreads();
    }

    float* out = g_Dl + (size_t)m * MATSZ;
    for (int idx = t; idx < 4096; idx += 256) {
        int row = idx >> 5, c0 = (idx & 31) << 2;
        *(float4*)(out + (row << 7) + c0) = *(const float4*)(ST + row * 132 + c0);
    }
}

// ---------------- 5) combine: Delta_R = D0+D1+D0@D1, then +D2+(.)@D2; emit frags ----
__global__ __launch_bounds__(256, 1) void combine_kernel() {
    extern __shared__ char smc[];
    uint32_t sb = smem_u32(smc);
    float* AF = (float*)(smc + CH_AF);
    float* ST = (float*)(smc + CH_ST);
    int t = threadIdx.x, lane = t & 31, wid = t >> 5;
    int b = blockIdx.x;
    int m0 = (wid & 3) << 5, n0 = (wid >> 2) << 6;

    // phase 1: D0 -> AF + AH;  D1 -> ST + DH
    {
        const float* D0 = g_Dl + (size_t)(b * 3 + 0) * MATSZ;
        const float* D1 = g_Dl + (size_t)(b * 3 + 1) * MATSZ;
        for (int idx = t; idx < 4096; idx += 256) {
            int row = idx >> 5, c0 = (idx & 31) << 2;
            int eo = (row * LDA + c0) << 1;
            float4 v0 = *(const float4*)(D0 + (row << 7) + c0);
            *(float4*)(AF + (row << 7) + c0) = v0;
            *(uint32_t*)(smc + CH_AH + eo)     = pack_bf2(v0.x, v0.y);
            *(uint32_t*)(smc + CH_AH + eo + 4) = pack_bf2(v0.z, v0.w);
            float4 v1 = *(const float4*)(D1 + (row << 7) + c0);
            *(float4*)(ST + row * 132 + c0) = v1;
            *(uint32_t*)(smc + CH_DH + eo)     = pack_bf2(v1.x, v1.y);
            *(uint32_t*)(smc + CH_DH + eo + 4) = pack_bf2(v1.z, v1.w);
        }
        __syncthreads();
        float acc[2][8][4];
        #pragma unroll
        for (int mi = 0; mi < 2; mi++)
            #pragma unroll
            for (int j = 0; j < 8; j++)
                #pragma unroll
                for (int q = 0; q < 4; q++) acc[mi][j][q] = 0.f;
        mma128(sb + CH_AH, sb + CH_DH, acc, lane, wid);
        #pragma unroll
        for (int mi = 0; mi < 2; mi++)
            #pragma unroll
            for (int j = 0; j < 8; j++) {
                int r = m0 + (mi << 4) + (lane >> 2);
                int c = n0 + (j << 3) + ((lane & 3) << 1);
                ST[r * 132 + c]           += AF[(r << 7) + c]           + acc[mi][j][0];
                ST[r * 132 + c + 1]       += AF[(r << 7) + c + 1]       + acc[mi][j][1];
                ST[(r + 8) * 132 + c]     += AF[((r + 8) << 7) + c]     + acc[mi][j][2];
                ST[(r + 8) * 132 + c + 1] += AF[((r + 8) << 7) + c + 1] + acc[mi][j][3];
            }
        __syncthreads();
    }
    // phase 2: A = D01 (from ST) -> AH;  D2 -> AF + DH
    {
        const float* D2 = g_Dl + (size_t)(b * 3 + 2) * MATSZ;
        for (int idx = t; idx < 4096; idx += 256) {
            int row = idx >> 5, c0 = (idx & 31) << 2;
            int eo = (row * LDA + c0) << 1;
            float4 v = *(const float4*)(ST + row * 132 + c0);
            *(uint32_t*)(smc + CH_AH + eo)     = pack_bf2(v.x, v.y);
            *(uint32_t*)(smc + CH_AH + eo + 4) = pack_bf2(v.z, v.w);
            float4 v2 = *(const float4*)(D2 + (row << 7) + c0);
            *(float4*)(AF + (row << 7) + c0) = v2;
            *(uint32_t*)(smc + CH_DH + eo)     = pack_bf2(v2.x, v2.y);
            *(uint32_t*)(smc + CH_DH + eo + 4) = pack_bf2(v2.z, v2.w);
        }
        __syncthreads();
        float acc[2][8][4];
        #pragma unroll
        for (int mi = 0; mi < 2; mi++)
            #pragma unroll
            for (int j = 0; j < 8; j++)
                #pragma unroll
                for (int q = 0; q < 4; q++) acc[mi][j][q] = 0.f;
        mma128(sb + CH_AH, sb + CH_DH, acc, lane, wid);
        #pragma unroll
        for (int mi = 0; mi < 2; mi++)
            #pragma unroll
            for (int j = 0; j < 8; j++) {
                int r = m0 + (mi << 4) + (lane >> 2);
                int c = n0 + (j << 3) + ((lane & 3) << 1);
                ST[r * 132 + c]           += AF[(r << 7) + c]           + acc[mi][j][0];
                ST[r * 132 + c + 1]       += AF[(r << 7) + c + 1]       + acc[mi][j][1];
                ST[(r + 8) * 132 + c]     += AF[((r + 8) << 7) + c]     + acc[mi][j][2];
                ST[(r + 8) * 132 + c + 1] += AF[((r + 8) << 7) + c + 1] + acc[mi][j][3];
            }
        __syncthreads();
    }
    // emit bf16 B-fragments of Delta_R for mma m16n8k16 row.col
    for (int idx = t; idx < 8192; idx += 256) {
        int reg = idx & 1;
        int ln = (idx >> 1) & 31;
        int jg = (idx >> 6) & 15;
        int ks = idx >> 10;
        int k0 = ks * 16 + ((ln & 3) << 1) + reg * 8;
        int n = jg * 8 + (ln >> 2);
        g_frag[(size_t)b * 8192 + idx] = pack_bf2(ST[k0 * 132 + n], ST[(k0 + 1) * 132 + n]);
    }
}

// ---------------- 6) apply: y = x + bf16(x)@Delta_R (1-pass HMMA) ----------------
__global__ __launch_bounds__(256) void apply_kernel(const float* __restrict__ x,
                                                    float* __restrict__ y) {
    extern __shared__ char smc[];
    uint32_t sb = smem_u32(smc);
    float* XF = (float*)smc;          // [128][132] fp32
    int t = threadIdx.x, lane = t & 31, wid = t >> 5;
    int st = blockIdx.x, b = blockIdx.y;
    const float* xp = x + ((size_t)b * S_ + (size_t)st * 128) * D_;

    for (int idx = t; idx < 4096; idx += 256) {
        int row = idx >> 5, c0 = (idx & 31) << 2;
        float4 v = *(const float4*)(xp + (row << 7) + c0);
        *(float4*)(XF + row * 132 + c0) = v;
        int eo = (row * LDA + c0) << 1;
        *(uint32_t*)(smc + AP_XH + eo)     = pack_bf2(v.x, v.y);
        *(uint32_t*)(smc + AP_XH + eo + 4) = pack_bf2(v.z, v.w);
    }
    __syncthreads();

    int m0 = (wid & 3) << 5, n0 = (wid >> 2) << 6;
    int arow = lane & 15, acol = (lane >> 4) << 3;
    int jgbase = (wid >> 2) << 3;

    float acc[2][8][4];
    #pragma unroll
    for (int mi = 0; mi < 2; mi++)
        #pragma unroll
        for (int j = 0; j < 8; j++)
            #pragma unroll
            for (int q = 0; q < 4; q++) acc[mi][j][q] = 0.f;

    const uint2* fp = (const uint2*)(g_frag + (size_t)b * 8192);
    #pragma unroll
    for (int ks = 0; ks < 8; ks++) {
        int k0 = ks << 4;
        uint2 bfr[8];
        #pragma unroll
        for (int j = 0; j < 8; j++)
            bfr[j] = fp[(ks * 16 + jgbase + j) * 32 + lane];
        uint32_t a0[4], a1[4];
        ldsm_x4(a0, sb + AP_XH + (uint32_t)(((m0 + arow) * LDA + k0 + acol) << 1));
        ldsm_x4(a1, sb + AP_XH + (uint32_t)(((m0 + 16 + arow) * LDA + k0 + acol) << 1));
        #pragma unroll
        for (int j = 0; j < 8; j++) {
            mma16816(acc[0][j], a0, (const uint32_t*)&bfr[j]);
            mma16816(acc[1][j], a1, (const uint32_t*)&bfr[j]);
        }
    }

    float* yp = y + ((size_t)b * S_ + (size_t)st * 128) * D_;
    #pragma unroll
    for (int mi = 0; mi < 2; mi++)
        #pragma unroll
        for (int j = 0; j < 8; j++) {
            int r = m0 + (mi << 4) + (lane >> 2);
            int c = n0 + (j << 3) + ((lane & 3) << 1);
            *(float2*)(yp + (r << 7) + c) =
                make_float2(acc[mi][j][0] + XF[r * 132 + c],
                            acc[mi][j][1] + XF[r * 132 + c + 1]);
            *(float2*)(yp + ((r + 8) << 7) + c) =
                make_float2(acc[mi][j][2] + XF[(r + 8) * 132 + c],
                            acc[mi][j][3] + XF[(r + 8) * 132 + c + 1]);
        }
}

// ---------------- launch ----------------
extern "C" void kernel_launch(void* const* d_in, const int* in_sizes, int n_in,
                              void* d_out, int out_size) {
    const float* x  = (const float*)d_in[0];
    const float* W1 = (const float*)d_in[1];
    const float* b1 = (const float*)d_in[2];
    const float* W2 = (const float*)d_in[3];
    const float* b2 = (const float*)d_in[4];
    float* y = (float*)d_out;

    const int smem_pgemm = (H_ * B_ + 2 * 128 * WS_LD) * sizeof(float);   // 102400
    cudaFuncSetAttribute(pgemm_kernel, cudaFuncAttributeMaxDynamicSharedMemorySize, smem_pgemm);
    cudaFuncSetAttribute(expm_chain_kernel, cudaFuncAttributeMaxDynamicSharedMemorySize, CH_TOTAL);
    cudaFuncSetAttribute(combine_kernel, cudaFuncAttributeMaxDynamicSharedMemorySize, CH_TOTAL);
    cudaFuncSetAttribute(apply_kernel, cudaFuncAttributeMaxDynamicSharedMemorySize, AP_TOTAL);

    mean_partial_kernel<<<dim3(8, B_), 256>>>(x);
    h_kernel<<<B_, H_>>>(W1, b1);
    pgemm_kernel<<<W2ROWS / 128, 256, smem_pgemm>>>(W2, b2);
    expm_chain_kernel<<<NMAT, 256, CH_TOTAL>>>();
    combine_kernel<<<B_, 256, CH_TOTAL>>>();
    apply_kernel<<<dim3(S_ / 128, B_), 256, AP_TOTAL>>>(x, y);
}

// round 7
// speedup vs baseline: 1.0854x; 1.0854x over previous
#include <cuda_runtime.h>
#include <cuda_bf16.h>
#include <math.h>
#include <stdint.h>

#define B_    16
#define S_    8192
#define D_    128
#define H_    512
#define NROT  3
#define NMAT  (B_ * NROT)          // 48
#define MATSZ (D_ * D_)            // 16384
#define W2ROWS (NROT * D_ * D_)    // 49152

// ---------------- scratch ----------------
__device__ float g_partial[B_ * 8 * D_];
__device__ float g_h[B_ * H_];
__device__ float g_P[B_ * W2ROWS];          // P[b][r]
__device__ float g_Dl[NMAT * MATSZ];        // Delta = expm(g) - I per matrix
__device__ uint32_t g_frag[B_ * 8192];      // bf16 B-fragments of Delta_R per batch

// ---------------- packed f32x2 (pgemm) ----------------
__device__ __forceinline__ unsigned long long dup2(float a) {
    unsigned long long r; asm("mov.b64 %0, {%1, %1};" : "=l"(r) : "f"(a)); return r;
}
__device__ __forceinline__ unsigned long long fma2(unsigned long long a,
                                                   unsigned long long b,
                                                   unsigned long long c) {
    unsigned long long d;
    asm("fma.rn.f32x2 %0, %1, %2, %3;" : "=l"(d) : "l"(a), "l"(b), "l"(c));
    return d;
}
__device__ __forceinline__ float2 unpk(unsigned long long v) {
    float2 f; asm("mov.b64 {%0, %1}, %2;" : "=f"(f.x), "=f"(f.y) : "l"(v)); return f;
}

// ---------------- mma.sync / ldmatrix helpers ----------------
__device__ __forceinline__ uint32_t smem_u32(const void* p) {
    uint32_t a;
    asm("{ .reg .u64 t; cvta.to.shared.u64 t, %1; cvt.u32.u64 %0, t; }" : "=r"(a) : "l"(p));
    return a;
}
__device__ __forceinline__ void ldsm_x4(uint32_t* r, uint32_t addr) {
    asm volatile("ldmatrix.sync.aligned.m8n8.x4.shared.b16 {%0,%1,%2,%3}, [%4];"
                 : "=r"(r[0]), "=r"(r[1]), "=r"(r[2]), "=r"(r[3]) : "r"(addr));
}
__device__ __forceinline__ void ldsm_x2_trans(uint32_t* r, uint32_t addr) {
    asm volatile("ldmatrix.sync.aligned.m8n8.x2.trans.shared.b16 {%0,%1}, [%2];"
                 : "=r"(r[0]), "=r"(r[1]) : "r"(addr));
}
__device__ __forceinline__ void mma16816(float* c, const uint32_t* a, const uint32_t* b) {
    asm volatile("mma.sync.aligned.m16n8k16.row.col.f32.bf16.bf16.f32 "
                 "{%0,%1,%2,%3}, {%4,%5,%6,%7}, {%8,%9}, {%0,%1,%2,%3};"
                 : "+f"(c[0]), "+f"(c[1]), "+f"(c[2]), "+f"(c[3])
                 : "r"(a[0]), "r"(a[1]), "r"(a[2]), "r"(a[3]), "r"(b[0]), "r"(b[1]));
}
__device__ __forceinline__ uint32_t pack_bf2(float a, float b) {
    __nv_bfloat162 h = __floats2bfloat162_rn(a, b);
    return *reinterpret_cast<uint32_t*>(&h);
}

#define LDA 136                      // bf16 plane row stride (elements)
// chain/combine smem layout (bytes)
#define CH_AH 0
#define CH_DH 34816
#define CH_AF 69632                  // fp32 [128][128]
#define CH_ST 135168                 // fp32 [128][132]
#define CH_TOTAL 202752
// apply smem: XH bf16 plane [0,34816) lives only until MMAs finish,
// then the SAME region is reused as fp32 output stage [128][132] = 67584.
#define AP_TOTAL 67584

// 1-pass 128x128x128 bf16 MMA: acc += A(pa) @ B(pb), planes in smem
__device__ __forceinline__ void mma128(uint32_t pa, uint32_t pb,
                                       float acc[2][8][4], int lane, int wid) {
    int m0 = (wid & 3) << 5, n0 = (wid >> 2) << 6;
    int arow = lane & 15, acol = (lane >> 4) << 3;
    #pragma unroll
    for (int ks = 0; ks < 8; ks++) {
        int k0 = ks << 4;
        uint32_t a0[4], a1[4];
        ldsm_x4(a0, pa + (uint32_t)(((m0 + arow) * LDA + k0 + acol) << 1));
        ldsm_x4(a1, pa + (uint32_t)(((m0 + 16 + arow) * LDA + k0 + acol) << 1));
        uint32_t bfr[8][2];
        #pragma unroll
        for (int j = 0; j < 8; j++)
            ldsm_x2_trans(bfr[j], pb + (uint32_t)(((k0 + arow) * LDA + n0 + (j << 3)) << 1));
        #pragma unroll
        for (int j = 0; j < 8; j++) {
            mma16816(acc[0][j], a0, bfr[j]);
            mma16816(acc[1][j], a1, bfr[j]);
        }
    }
}

// ---------------- 1) mean over S (float4) ----------------
__global__ void mean_partial_kernel(const float* __restrict__ x) {
    int b = blockIdx.y, chunk = blockIdx.x;
    int t = threadIdx.x, lane = t & 31, grp = t >> 5;
    const float* xp = x + ((size_t)b * S_ + (size_t)chunk * 1024 + grp) * D_ + lane * 4;
    float4 s = make_float4(0.f, 0.f, 0.f, 0.f);
    #pragma unroll 8
    for (int i = 0; i < 128; i++) {
        float4 v = *(const float4*)xp;
        s.x += v.x; s.y += v.y; s.z += v.z; s.w += v.w;
        xp += 8 * D_;
    }
    __shared__ float4 red[256];
    red[t] = s;
    __syncthreads();
    if (grp < 4) {
        float4 o = red[t + 128];
        red[t] = make_float4(red[t].x + o.x, red[t].y + o.y, red[t].z + o.z, red[t].w + o.w);
    }
    __syncthreads();
    if (grp < 2) {
        float4 o = red[t + 64];
        red[t] = make_float4(red[t].x + o.x, red[t].y + o.y, red[t].z + o.z, red[t].w + o.w);
    }
    __syncthreads();
    if (grp == 0) {
        float4 o = red[t + 32];
        float4 r = make_float4(red[t].x + o.x, red[t].y + o.y, red[t].z + o.z, red[t].w + o.w);
        *(float4*)&g_partial[(b * 8 + chunk) * D_ + lane * 4] = r;
    }
}

// ---------------- 2) h = gelu(pooled @ W1^T + b1) ----------------
__global__ void h_kernel(const float* __restrict__ W1, const float* __restrict__ b1) {
    int b = blockIdx.x, t = threadIdx.x;
    __shared__ float ps[D_];
    if (t < D_) {
        float s = 0.f;
        #pragma unroll
        for (int c = 0; c < 8; c++) s += g_partial[(b * 8 + c) * D_ + t];
        ps[t] = s * (1.0f / (float)S_);
    }
    __syncthreads();
    float acc = b1[t];
    const float* w = W1 + (size_t)t * D_;
    #pragma unroll 8
    for (int k = 0; k < D_; k++) acc = fmaf(ps[k], w[k], acc);
    float z = acc;
    g_h[b * H_ + t] = 0.5f * z * (1.0f + erff(z * 0.70710678118654752f));
}

// ---------------- 3) P = W2 @ h^T + b2 -> P[b][r] (round-5 form: 128 thr) ----------------
#define WS_LD 68
__global__ __launch_bounds__(128) void pgemm_kernel(const float* __restrict__ W2,
                                                    const float* __restrict__ b2) {
    extern __shared__ float sm[];
    float* hs = sm;                   // [512][16]
    float* ws = sm + H_ * B_;         // [128][68]
    int t = threadIdx.x;
    int row0 = blockIdx.x * 128;

    for (int idx = t; idx < H_ * B_; idx += 128) {
        int bb = idx >> 9, k = idx & 511;
        hs[k * B_ + bb] = g_h[idx];
    }

    unsigned long long acc[8];
    #pragma unroll
    for (int j = 0; j < 8; j++) acc[j] = 0ull;

    for (int kc = 0; kc < 8; kc++) {
        __syncthreads();
        for (int idx = t; idx < 2048; idx += 128) {
            int r = idx >> 4, k4 = (idx & 15) << 2;
            *(float4*)&ws[r * WS_LD + k4] =
                *(const float4*)&W2[(size_t)(row0 + r) * H_ + kc * 64 + k4];
        }
        __syncthreads();
        #pragma unroll 4
        for (int k = 0; k < 64; k++) {
            unsigned long long wd = dup2(ws[t * WS_LD + k]);
            const float* hrow = &hs[(kc * 64 + k) * B_];
            ulonglong2 a = *(const ulonglong2*)(hrow);
            ulonglong2 bq = *(const ulonglong2*)(hrow + 4);
            ulonglong2 c = *(const ulonglong2*)(hrow + 8);
            ulonglong2 dq = *(const ulonglong2*)(hrow + 12);
            acc[0] = fma2(wd, a.x, acc[0]);  acc[1] = fma2(wd, a.y, acc[1]);
            acc[2] = fma2(wd, bq.x, acc[2]); acc[3] = fma2(wd, bq.y, acc[3]);
            acc[4] = fma2(wd, c.x, acc[4]);  acc[5] = fma2(wd, c.y, acc[5]);
            acc[6] = fma2(wd, dq.x, acc[6]); acc[7] = fma2(wd, dq.y, acc[7]);
        }
    }
    int r = row0 + t;
    float bias = b2[r];
    #pragma unroll
    for (int j = 0; j < 8; j++) {
        float2 f = unpk(acc[j]);
        g_P[(size_t)(2 * j)     * W2ROWS + r] = f.x + bias;
        g_P[(size_t)(2 * j + 1) * W2ROWS + r] = f.y + bias;
    }
}

// ---------------- 4) fused antisym + expm chain (one launch) ----------------
__global__ __launch_bounds__(256, 1) void expm_chain_kernel() {
    extern __shared__ char smc[];
    uint32_t sb = smem_u32(smc);
    float* AF = (float*)(smc + CH_AF);
    float* ST = (float*)(smc + CH_ST);
    int t = threadIdx.x, lane = t & 31, wid = t >> 5;
    int m = blockIdx.x;
    int b = m / NROT, i = m - b * NROT;
    const float* P = g_P + (size_t)b * W2ROWS + (size_t)i * MATSZ;

    for (int idx = t; idx < 4096; idx += 256) {
        int row = idx >> 5, c0 = (idx & 31) << 2;
        *(float4*)(ST + row * 132 + c0) = *(const float4*)(P + (row << 7) + c0);
    }
    __syncthreads();
    for (int idx = t; idx < 16384; idx += 256) {
        int d = idx >> 7, e = idx & 127;
        float v = (ST[d * 132 + e] - ST[e * 132 + d]) * 0.0625f;
        AF[(d << 7) + e] = v;
        *(__nv_bfloat16*)(smc + CH_AH + ((d * LDA + e) << 1)) = __float2bfloat16(v);
    }
    __syncthreads();
    for (int idx = t; idx < 4096; idx += 256) {
        int row = idx >> 5, c0 = (idx & 31) << 2;
        float4 v = *(const float4*)(AF + (row << 7) + c0);
        *(float4*)(ST + row * 132 + c0) =
            make_float4(v.x * (1.f/3.f), v.y * (1.f/3.f), v.z * (1.f/3.f), v.w * (1.f/3.f));
    }
    __syncthreads();

    int m0 = (wid & 3) << 5, n0 = (wid >> 2) << 6;

    // Horner: Delta <- (A + A@Delta)/c for c = 2, 1
    #pragma unroll 1
    for (int step = 0; step < 2; step++) {
        float invc = (step == 0) ? 0.5f : 1.0f;
        for (int idx = t; idx < 4096; idx += 256) {
            int row = idx >> 5, c0 = (idx & 31) << 2;
            float4 v = *(const float4*)(ST + row * 132 + c0);
            int eo = (row * LDA + c0) << 1;
            *(uint32_t*)(smc + CH_DH + eo)     = pack_bf2(v.x, v.y);
            *(uint32_t*)(smc + CH_DH + eo + 4) = pack_bf2(v.z, v.w);
        }
        __syncthreads();
        float acc[2][8][4];
        #pragma unroll
        for (int mi = 0; mi < 2; mi++)
            #pragma unroll
            for (int j = 0; j < 8; j++)
                #pragma unroll
                for (int q = 0; q < 4; q++) acc[mi][j][q] = 0.f;
        mma128(sb + CH_AH, sb + CH_DH, acc, lane, wid);
        #pragma unroll
        for (int mi = 0; mi < 2; mi++)
            #pragma unroll
            for (int j = 0; j < 8; j++) {
                int r = m0 + (mi << 4) + (lane >> 2);
                int c = n0 + (j << 3) + ((lane & 3) << 1);
                ST[r * 132 + c]           = (AF[(r << 7) + c]           + acc[mi][j][0]) * invc;
                ST[r * 132 + c + 1]       = (AF[(r << 7) + c + 1]       + acc[mi][j][1]) * invc;
                ST[(r + 8) * 132 + c]     = (AF[((r + 8) << 7) + c]     + acc[mi][j][2]) * invc;
                ST[(r + 8) * 132 + c + 1] = (AF[((r + 8) << 7) + c + 1] + acc[mi][j][3]) * invc;
            }
        __syncthreads();
    }

    // Squarings: Delta <- 2*Delta + Delta^2, x3
    #pragma unroll 1
    for (int sq = 0; sq < 3; sq++) {
        for (int idx = t; idx < 4096; idx += 256) {
            int row = idx >> 5, c0 = (idx & 31) << 2;
            float4 v = *(const float4*)(ST + row * 132 + c0);
            int eo = (row * LDA + c0) << 1;
            *(uint32_t*)(smc + CH_DH + eo)     = pack_bf2(v.x, v.y);
            *(uint32_t*)(smc + CH_DH + eo + 4) = pack_bf2(v.z, v.w);
        }
        __syncthreads();
        float acc[2][8][4];
        #pragma unroll
        for (int mi = 0; mi < 2; mi++)
            #pragma unroll
            for (int j = 0; j < 8; j++)
                #pragma unroll
                for (int q = 0; q < 4; q++) acc[mi][j][q] = 0.f;
        mma128(sb + CH_DH, sb + CH_DH, acc, lane, wid);
        #pragma unroll
        for (int mi = 0; mi < 2; mi++)
            #pragma unroll
            for (int j = 0; j < 8; j++) {
                int r = m0 + (mi << 4) + (lane >> 2);
                int c = n0 + (j << 3) + ((lane & 3) << 1);
                ST[r * 132 + c]           = 2.f * ST[r * 132 + c]           + acc[mi][j][0];
                ST[r * 132 + c + 1]       = 2.f * ST[r * 132 + c + 1]       + acc[mi][j][1];
                ST[(r + 8) * 132 + c]     = 2.f * ST[(r + 8) * 132 + c]     + acc[mi][j][2];
                ST[(r + 8) * 132 + c + 1] = 2.f * ST[(r + 8) * 132 + c + 1] + acc[mi][j][3];
            }
        __syncthreads();
    }

    float* out = g_Dl + (size_t)m * MATSZ;
    for (int idx = t; idx < 4096; idx += 256) {
        int row = idx >> 5, c0 = (idx & 31) << 2;
        *(float4*)(out + (row << 7) + c0) = *(const float4*)(ST + row * 132 + c0);
    }
}

// ---------------- 5) combine: Delta_R = D0+D1+D0@D1, then +D2+(.)@D2; emit frags ----
__global__ __launch_bounds__(256, 1) void combine_kernel() {
    extern __shared__ char smc[];
    uint32_t sb = smem_u32(smc);
    float* AF = (float*)(smc + CH_AF);
    float* ST = (float*)(smc + CH_ST);
    int t = threadIdx.x, lane = t & 31, wid = t >> 5;
    int b = blockIdx.x;
    int m0 = (wid & 3) << 5, n0 = (wid >> 2) << 6;

    {
        const float* D0 = g_Dl + (size_t)(b * 3 + 0) * MATSZ;
        const float* D1 = g_Dl + (size_t)(b * 3 + 1) * MATSZ;
        for (int idx = t; idx < 4096; idx += 256) {
            int row = idx >> 5, c0 = (idx & 31) << 2;
            int eo = (row * LDA + c0) << 1;
            float4 v0 = *(const float4*)(D0 + (row << 7) + c0);
            *(float4*)(AF + (row << 7) + c0) = v0;
            *(uint32_t*)(smc + CH_AH + eo)     = pack_bf2(v0.x, v0.y);
            *(uint32_t*)(smc + CH_AH + eo + 4) = pack_bf2(v0.z, v0.w);
            float4 v1 = *(const float4*)(D1 + (row << 7) + c0);
            *(float4*)(ST + row * 132 + c0) = v1;
            *(uint32_t*)(smc + CH_DH + eo)     = pack_bf2(v1.x, v1.y);
            *(uint32_t*)(smc + CH_DH + eo + 4) = pack_bf2(v1.z, v1.w);
        }
        __syncthreads();
        float acc[2][8][4];
        #pragma unroll
        for (int mi = 0; mi < 2; mi++)
            #pragma unroll
            for (int j = 0; j < 8; j++)
                #pragma unroll
                for (int q = 0; q < 4; q++) acc[mi][j][q] = 0.f;
        mma128(sb + CH_AH, sb + CH_DH, acc, lane, wid);
        #pragma unroll
        for (int mi = 0; mi < 2; mi++)
            #pragma unroll
            for (int j = 0; j < 8; j++) {
                int r = m0 + (mi << 4) + (lane >> 2);
                int c = n0 + (j << 3) + ((lane & 3) << 1);
                ST[r * 132 + c]           += AF[(r << 7) + c]           + acc[mi][j][0];
                ST[r * 132 + c + 1]       += AF[(r << 7) + c + 1]       + acc[mi][j][1];
                ST[(r + 8) * 132 + c]     += AF[((r + 8) << 7) + c]     + acc[mi][j][2];
                ST[(r + 8) * 132 + c + 1] += AF[((r + 8) << 7) + c + 1] + acc[mi][j][3];
            }
        __syncthreads();
    }
    {
        const float* D2 = g_Dl + (size_t)(b * 3 + 2) * MATSZ;
        for (int idx = t; idx < 4096; idx += 256) {
            int row = idx >> 5, c0 = (idx & 31) << 2;
            int eo = (row * LDA + c0) << 1;
            float4 v = *(const float4*)(ST + row * 132 + c0);
            *(uint32_t*)(smc + CH_AH + eo)     = pack_bf2(v.x, v.y);
            *(uint32_t*)(smc + CH_AH + eo + 4) = pack_bf2(v.z, v.w);
            float4 v2 = *(const float4*)(D2 + (row << 7) + c0);
            *(float4*)(AF + (row << 7) + c0) = v2;
            *(uint32_t*)(smc + CH_DH + eo)     = pack_bf2(v2.x, v2.y);
            *(uint32_t*)(smc + CH_DH + eo + 4) = pack_bf2(v2.z, v2.w);
        }
        __syncthreads();
        float acc[2][8][4];
        #pragma unroll
        for (int mi = 0; mi < 2; mi++)
            #pragma unroll
            for (int j = 0; j < 8; j++)
                #pragma unroll
                for (int q = 0; q < 4; q++) acc[mi][j][q] = 0.f;
        mma128(sb + CH_AH, sb + CH_DH, acc, lane, wid);
        #pragma unroll
        for (int mi = 0; mi < 2; mi++)
            #pragma unroll
            for (int j = 0; j < 8; j++) {
                int r = m0 + (mi << 4) + (lane >> 2);
                int c = n0 + (j << 3) + ((lane & 3) << 1);
                ST[r * 132 + c]           += AF[(r << 7) + c]           + acc[mi][j][0];
                ST[r * 132 + c + 1]       += AF[(r << 7) + c + 1]       + acc[mi][j][1];
                ST[(r + 8) * 132 + c]     += AF[((r + 8) << 7) + c]     + acc[mi][j][2];
                ST[(r + 8) * 132 + c + 1] += AF[((r + 8) << 7) + c + 1] + acc[mi][j][3];
            }
        __syncthreads();
    }
    for (int idx = t; idx < 8192; idx += 256) {
        int reg = idx & 1;
        int ln = (idx >> 1) & 31;
        int jg = (idx >> 6) & 15;
        int ks = idx >> 10;
        int k0 = ks * 16 + ((ln & 3) << 1) + reg * 8;
        int n = jg * 8 + (ln >> 2);
        g_frag[(size_t)b * 8192 + idx] = pack_bf2(ST[k0 * 132 + n], ST[(k0 + 1) * 132 + n]);
    }
}

// ---------------- 6) apply: y = x + bf16(x)@Delta_R; coalesced epilogue ----------------
__global__ __launch_bounds__(256) void apply_kernel(const float* __restrict__ x,
                                                    float* __restrict__ y) {
    extern __shared__ char smc[];
    uint32_t sb = smem_u32(smc);
    int t = threadIdx.x, lane = t & 31, wid = t >> 5;
    int st = blockIdx.x, b = blockIdx.y;
    const float* xp = x + ((size_t)b * S_ + (size_t)st * 128) * D_;

    // phase A: x -> bf16 plane at smem[0, 34816)
    for (int idx = t; idx < 4096; idx += 256) {
        int row = idx >> 5, c0 = (idx & 31) << 2;
        float4 v = *(const float4*)(xp + (row << 7) + c0);
        int eo = (row * LDA + c0) << 1;
        *(uint32_t*)(smc + eo)     = pack_bf2(v.x, v.y);
        *(uint32_t*)(smc + eo + 4) = pack_bf2(v.z, v.w);
    }
    __syncthreads();

    int m0 = (wid & 3) << 5, n0 = (wid >> 2) << 6;
    int arow = lane & 15, acol = (lane >> 4) << 3;
    int jgbase = (wid >> 2) << 3;

    float acc[2][8][4];
    #pragma unroll
    for (int mi = 0; mi < 2; mi++)
        #pragma unroll
        for (int j = 0; j < 8; j++)
            #pragma unroll
            for (int q = 0; q < 4; q++) acc[mi][j][q] = 0.f;

    const uint2* fp = (const uint2*)(g_frag + (size_t)b * 8192);
    #pragma unroll
    for (int ks = 0; ks < 8; ks++) {
        int k0 = ks << 4;
        uint2 bfr[8];
        #pragma unroll
        for (int j = 0; j < 8; j++)
            bfr[j] = fp[(ks * 16 + jgbase + j) * 32 + lane];
        uint32_t a0[4], a1[4];
        ldsm_x4(a0, sb + (uint32_t)(((m0 + arow) * LDA + k0 + acol) << 1));
        ldsm_x4(a1, sb + (uint32_t)(((m0 + 16 + arow) * LDA + k0 + acol) << 1));
        #pragma unroll
        for (int j = 0; j < 8; j++) {
            mma16816(acc[0][j], a0, (const uint32_t*)&bfr[j]);
            mma16816(acc[1][j], a1, (const uint32_t*)&bfr[j]);
        }
    }
    __syncthreads();   // XH dead; reuse smem as fp32 output stage [128][132]

    float* stg = (float*)smc;
    #pragma unroll
    for (int mi = 0; mi < 2; mi++)
        #pragma unroll
        for (int j = 0; j < 8; j++) {
            int r = m0 + (mi << 4) + (lane >> 2);
            int c = n0 + (j << 3) + ((lane & 3) << 1);
            *(float2*)(stg + r * 132 + c)       = make_float2(acc[mi][j][0], acc[mi][j][1]);
            *(float2*)(stg + (r + 8) * 132 + c) = make_float2(acc[mi][j][2], acc[mi][j][3]);
        }
    __syncthreads();

    // phase C: y = stage + x (both coalesced float4; x re-read is L2-hot)
    float* yp = y + ((size_t)b * S_ + (size_t)st * 128) * D_;
    for (int idx = t; idx < 4096; idx += 256) {
        int row = idx >> 5, c0 = (idx & 31) << 2;
        float4 d = *(const float4*)(stg + row * 132 + c0);
        float4 v = *(const float4*)(xp + (row << 7) + c0);
        *(float4*)(yp + (row << 7) + c0) =
            make_float4(d.x + v.x, d.y + v.y, d.z + v.z, d.w + v.w);
    }
}

// ---------------- launch ----------------
extern "C" void kernel_launch(void* const* d_in, const int* in_sizes, int n_in,
                              void* d_out, int out_size) {
    const float* x  = (const float*)d_in[0];
    const float* W1 = (const float*)d_in[1];
    const float* b1 = (const float*)d_in[2];
    const float* W2 = (const float*)d_in[3];
    const float* b2 = (const float*)d_in[4];
    float* y = (float*)d_out;

    const int smem_pgemm = (H_ * B_ + 128 * WS_LD) * sizeof(float);   // 67584
    cudaFuncSetAttribute(pgemm_kernel, cudaFuncAttributeMaxDynamicSharedMemorySize, smem_pgemm);
    cudaFuncSetAttribute(expm_chain_kernel, cudaFuncAttributeMaxDynamicSharedMemorySize, CH_TOTAL);
    cudaFuncSetAttribute(combine_kernel, cudaFuncAttributeMaxDynamicSharedMemorySize, CH_TOTAL);
    cudaFuncSetAttribute(apply_kernel, cudaFuncAttributeMaxDynamicSharedMemorySize, AP_TOTAL);

    mean_partial_kernel<<<dim3(8, B_), 256>>>(x);
    h_kernel<<<B_, H_>>>(W1, b1);
    pgemm_kernel<<<W2ROWS / 128, 128, smem_pgemm>>>(W2, b2);
    expm_chain_kernel<<<NMAT, 256, CH_TOTAL>>>();
    combine_kernel<<<B_, 256, CH_TOTAL>>>();
    apply_kernel<<<dim3(S_ / 128, B_), 256, AP_TOTAL>>>(x, y);
}

// round 8
// speedup vs baseline: 1.2107x; 1.1155x over previous
#include <cuda_runtime.h>
#include <cuda_bf16.h>
#include <math.h>
#include <stdint.h>

#define B_    16
#define S_    8192
#define D_    128
#define H_    512
#define NROT  3
#define NMAT  (B_ * NROT)          // 48
#define MATSZ (D_ * D_)            // 16384
#define W2ROWS (NROT * D_ * D_)    // 49152

// ---------------- scratch ----------------
__device__ float g_partial[B_ * 8 * D_];
__device__ float g_h[B_ * H_];
__device__ float g_P[B_ * W2ROWS];          // P[b][r]
__device__ float g_Dl[NMAT * MATSZ];        // Delta = expm(g) - I per matrix
__device__ uint32_t g_frag[B_ * 8192];      // bf16 B-fragments of Delta_R per batch

// ---------------- mma.sync / ldmatrix helpers ----------------
__device__ __forceinline__ uint32_t smem_u32(const void* p) {
    uint32_t a;
    asm("{ .reg .u64 t; cvta.to.shared.u64 t, %1; cvt.u32.u64 %0, t; }" : "=r"(a) : "l"(p));
    return a;
}
__device__ __forceinline__ void ldsm_x4(uint32_t* r, uint32_t addr) {
    asm volatile("ldmatrix.sync.aligned.m8n8.x4.shared.b16 {%0,%1,%2,%3}, [%4];"
                 : "=r"(r[0]), "=r"(r[1]), "=r"(r[2]), "=r"(r[3]) : "r"(addr));
}
__device__ __forceinline__ void ldsm_x2_trans(uint32_t* r, uint32_t addr) {
    asm volatile("ldmatrix.sync.aligned.m8n8.x2.trans.shared.b16 {%0,%1}, [%2];"
                 : "=r"(r[0]), "=r"(r[1]) : "r"(addr));
}
__device__ __forceinline__ void mma16816(float* c, const uint32_t* a, const uint32_t* b) {
    asm volatile("mma.sync.aligned.m16n8k16.row.col.f32.bf16.bf16.f32 "
                 "{%0,%1,%2,%3}, {%4,%5,%6,%7}, {%8,%9}, {%0,%1,%2,%3};"
                 : "+f"(c[0]), "+f"(c[1]), "+f"(c[2]), "+f"(c[3])
                 : "r"(a[0]), "r"(a[1]), "r"(a[2]), "r"(a[3]), "r"(b[0]), "r"(b[1]));
}
__device__ __forceinline__ uint32_t pack_bf2(float a, float b) {
    __nv_bfloat162 h = __floats2bfloat162_rn(a, b);
    return *reinterpret_cast<uint32_t*>(&h);
}

#define LDA 136                      // bf16 plane row stride (elements)
// chain/combine smem layout (bytes)
#define CH_AH 0
#define CH_DH 34816
#define CH_AF 69632                  // fp32 [128][128]
#define CH_ST 135168                 // fp32 [128][132]
#define CH_TOTAL 202752
// apply smem: XH bf16 plane reused as fp32 output stage afterward
#define AP_TOTAL 67584
// pgemm smem: 2 bf16 W2 buffers + packed h
#define PG_BUF 34816
#define PG_HB  (2 * PG_BUF)          // 69632
#define PG_TOTAL (PG_HB + 16 * 256 * 4)   // 86016

// 1-pass 128x128x128 bf16 MMA: acc += A(pa) @ B(pb), planes in smem
__device__ __forceinline__ void mma128(uint32_t pa, uint32_t pb,
                                       float acc[2][8][4], int lane, int wid) {
    int m0 = (wid & 3) << 5, n0 = (wid >> 2) << 6;
    int arow = lane & 15, acol = (lane >> 4) << 3;
    #pragma unroll
    for (int ks = 0; ks < 8; ks++) {
        int k0 = ks << 4;
        uint32_t a0[4], a1[4];
        ldsm_x4(a0, pa + (uint32_t)(((m0 + arow) * LDA + k0 + acol) << 1));
        ldsm_x4(a1, pa + (uint32_t)(((m0 + 16 + arow) * LDA + k0 + acol) << 1));
        uint32_t bfr[8][2];
        #pragma unroll
        for (int j = 0; j < 8; j++)
            ldsm_x2_trans(bfr[j], pb + (uint32_t)(((k0 + arow) * LDA + n0 + (j << 3)) << 1));
        #pragma unroll
        for (int j = 0; j < 8; j++) {
            mma16816(acc[0][j], a0, bfr[j]);
            mma16816(acc[1][j], a1, bfr[j]);
        }
    }
}

// ---------------- 1) mean over S (float4) ----------------
__global__ void mean_partial_kernel(const float* __restrict__ x) {
    int b = blockIdx.y, chunk = blockIdx.x;
    int t = threadIdx.x, lane = t & 31, grp = t >> 5;
    const float* xp = x + ((size_t)b * S_ + (size_t)chunk * 1024 + grp) * D_ + lane * 4;
    float4 s = make_float4(0.f, 0.f, 0.f, 0.f);
    #pragma unroll 8
    for (int i = 0; i < 128; i++) {
        float4 v = *(const float4*)xp;
        s.x += v.x; s.y += v.y; s.z += v.z; s.w += v.w;
        xp += 8 * D_;
    }
    __shared__ float4 red[256];
    red[t] = s;
    __syncthreads();
    if (grp < 4) {
        float4 o = red[t + 128];
        red[t] = make_float4(red[t].x + o.x, red[t].y + o.y, red[t].z + o.z, red[t].w + o.w);
    }
    __syncthreads();
    if (grp < 2) {
        float4 o = red[t + 64];
        red[t] = make_float4(red[t].x + o.x, red[t].y + o.y, red[t].z + o.z, red[t].w + o.w);
    }
    __syncthreads();
    if (grp == 0) {
        float4 o = red[t + 32];
        float4 r = make_float4(red[t].x + o.x, red[t].y + o.y, red[t].z + o.z, red[t].w + o.w);
        *(float4*)&g_partial[(b * 8 + chunk) * D_ + lane * 4] = r;
    }
}

// ---------------- 2) h = gelu(pooled @ W1^T + b1) ----------------
__global__ void h_kernel(const float* __restrict__ W1, const float* __restrict__ b1) {
    int b = blockIdx.x, t = threadIdx.x;
    __shared__ float ps[D_];
    if (t < D_) {
        float s = 0.f;
        #pragma unroll
        for (int c = 0; c < 8; c++) s += g_partial[(b * 8 + c) * D_ + t];
        ps[t] = s * (1.0f / (float)S_);
    }
    __syncthreads();
    float acc = b1[t];
    const float* w = W1 + (size_t)t * D_;
    #pragma unroll 8
    for (int k = 0; k < D_; k++) acc = fmaf(ps[k], w[k], acc);
    float z = acc;
    g_h[b * H_ + t] = 0.5f * z * (1.0f + erff(z * 0.70710678118654752f));
}

// ---------------- 3) P = W2 @ h^T + b2 via tensor cores, double-buffered ----------------
// grid 384 x 256 threads; each block computes 128 rows x 16 batches over K=512.
__global__ __launch_bounds__(256) void pgemm_tc_kernel(const float* __restrict__ W2,
                                                       const float* __restrict__ b2) {
    extern __shared__ char smc[];
    uint32_t sb = smem_u32(smc);
    uint32_t* hbf = (uint32_t*)(smc + PG_HB);
    int t = threadIdx.x, lane = t & 31, wid = t >> 5;
    int row0 = blockIdx.x * 128;

    // h -> packed bf16 pairs: hbf[n*256 + k/2] = pack(h[n][k], h[n][k+1])
    for (int idx = t; idx < 16 * 256; idx += 256) {
        int n = idx >> 8, kp = idx & 255;
        float2 v = *(const float2*)&g_h[n * H_ + kp * 2];
        hbf[idx] = pack_bf2(v.x, v.y);
    }

    // prefetch chunk 0 (128 k) into registers
    float4 pf[16];
    #pragma unroll
    for (int i = 0; i < 16; i++) {
        int idx = t + (i << 8);
        int row = idx >> 5, k4 = (idx & 31) << 2;
        pf[i] = *(const float4*)&W2[(size_t)(row0 + row) * H_ + k4];
    }

    float acc[2][4] = {};
    int mrow = lane & 15, mcol = (lane >> 4) << 3;

    for (int c = 0; c < 4; c++) {
        char* buf = smc + (c & 1) * PG_BUF;
        #pragma unroll
        for (int i = 0; i < 16; i++) {
            int idx = t + (i << 8);
            int row = idx >> 5, k4 = (idx & 31) << 2;
            int eo = (row * LDA + k4) << 1;
            *(uint32_t*)(buf + eo)     = pack_bf2(pf[i].x, pf[i].y);
            *(uint32_t*)(buf + eo + 4) = pack_bf2(pf[i].z, pf[i].w);
        }
        __syncthreads();
        if (c < 3) {
            #pragma unroll
            for (int i = 0; i < 16; i++) {
                int idx = t + (i << 8);
                int row = idx >> 5, k4 = (idx & 31) << 2;
                pf[i] = *(const float4*)&W2[(size_t)(row0 + row) * H_ + (c + 1) * 128 + k4];
            }
        }
        // B fragments for this chunk (from packed h)
        uint32_t bfrag[2][8][2];
        #pragma unroll
        for (int jn = 0; jn < 2; jn++) {
            int n = jn * 8 + (lane >> 2);
            #pragma unroll
            for (int ks = 0; ks < 8; ks++) {
                #pragma unroll
                for (int rg = 0; rg < 2; rg++) {
                    int kp = c * 64 + ks * 8 + rg * 4 + (lane & 3);
                    bfrag[jn][ks][rg] = hbf[n * 256 + kp];
                }
            }
        }
        uint32_t bufb = sb + (c & 1) * PG_BUF;
        #pragma unroll
        for (int ks = 0; ks < 8; ks++) {
            uint32_t a[4];
            ldsm_x4(a, bufb + (uint32_t)(((wid * 16 + mrow) * LDA + ks * 16 + mcol) << 1));
            mma16816(acc[0], a, bfrag[0][ks]);
            mma16816(acc[1], a, bfrag[1][ks]);
        }
        __syncthreads();
    }

    // store P[b][r] + bias(r)
    #pragma unroll
    for (int mi = 0; mi < 2; mi++) {
        int r = row0 + wid * 16 + mi * 8 + (lane >> 2);
        float bias = b2[r];
        #pragma unroll
        for (int jn = 0; jn < 2; jn++) {
            int b0 = jn * 8 + ((lane & 3) << 1);
            g_P[(size_t)b0 * W2ROWS + r]       = acc[jn][mi * 2]     + bias;
            g_P[(size_t)(b0 + 1) * W2ROWS + r] = acc[jn][mi * 2 + 1] + bias;
        }
    }
}

// ---------------- 4) fused antisym + expm (order-5 Taylor, no scaling) ----------------
// g = 0.5*(P - P^T), ||g|| ~ 0.33; Delta = expm(g) - I via 4 Horner matmuls.
__global__ __launch_bounds__(256, 1) void expm_chain_kernel() {
    extern __shared__ char smc[];
    uint32_t sb = smem_u32(smc);
    float* AF = (float*)(smc + CH_AF);
    float* ST = (float*)(smc + CH_ST);
    int t = threadIdx.x, lane = t & 31, wid = t >> 5;
    int m = blockIdx.x;
    int b = m / NROT, i = m - b * NROT;
    const float* P = g_P + (size_t)b * W2ROWS + (size_t)i * MATSZ;

    for (int idx = t; idx < 4096; idx += 256) {
        int row = idx >> 5, c0 = (idx & 31) << 2;
        *(float4*)(ST + row * 132 + c0) = *(const float4*)(P + (row << 7) + c0);
    }
    __syncthreads();
    // A = 0.5*(P - P^T) -> AF (fp32) + AH (bf16 plane)
    for (int idx = t; idx < 16384; idx += 256) {
        int d = idx >> 7, e = idx & 127;
        float v = (ST[d * 132 + e] - ST[e * 132 + d]) * 0.5f;
        AF[(d << 7) + e] = v;
        *(__nv_bfloat16*)(smc + CH_AH + ((d * LDA + e) << 1)) = __float2bfloat16(v);
    }
    __syncthreads();
    // init Delta = A/5
    for (int idx = t; idx < 4096; idx += 256) {
        int row = idx >> 5, c0 = (idx & 31) << 2;
        float4 v = *(const float4*)(AF + (row << 7) + c0);
        *(float4*)(ST + row * 132 + c0) =
            make_float4(v.x * 0.2f, v.y * 0.2f, v.z * 0.2f, v.w * 0.2f);
    }
    __syncthreads();

    int m0 = (wid & 3) << 5, n0 = (wid >> 2) << 6;

    // Horner: Delta <- (A + A@Delta)/c for c = 4, 3, 2, 1
    #pragma unroll 1
    for (int step = 0; step < 4; step++) {
        float invc = (step == 0) ? 0.25f
                   : (step == 1) ? (1.f / 3.f)
                   : (step == 2) ? 0.5f : 1.0f;
        for (int idx = t; idx < 4096; idx += 256) {
            int row = idx >> 5, c0 = (idx & 31) << 2;
            float4 v = *(const float4*)(ST + row * 132 + c0);
            int eo = (row * LDA + c0) << 1;
            *(uint32_t*)(smc + CH_DH + eo)     = pack_bf2(v.x, v.y);
            *(uint32_t*)(smc + CH_DH + eo + 4) = pack_bf2(v.z, v.w);
        }
        __syncthreads();
        float acc[2][8][4];
        #pragma unroll
        for (int mi = 0; mi < 2; mi++)
            #pragma unroll
            for (int j = 0; j < 8; j++)
                #pragma unroll
                for (int q = 0; q < 4; q++) acc[mi][j][q] = 0.f;
        mma128(sb + CH_AH, sb + CH_DH, acc, lane, wid);
        #pragma unroll
        for (int mi = 0; mi < 2; mi++)
            #pragma unroll
            for (int j = 0; j < 8; j++) {
                int r = m0 + (mi << 4) + (lane >> 2);
                int c = n0 + (j << 3) + ((lane & 3) << 1);
                ST[r * 132 + c]           = (AF[(r << 7) + c]           + acc[mi][j][0]) * invc;
                ST[r * 132 + c + 1]       = (AF[(r << 7) + c + 1]       + acc[mi][j][1]) * invc;
                ST[(r + 8) * 132 + c]     = (AF[((r + 8) << 7) + c]     + acc[mi][j][2]) * invc;
                ST[(r + 8) * 132 + c + 1] = (AF[((r + 8) << 7) + c + 1] + acc[mi][j][3]) * invc;
            }
        __syncthreads();
    }

    float* out = g_Dl + (size_t)m * MATSZ;
    for (int idx = t; idx < 4096; idx += 256) {
        int row = idx >> 5, c0 = (idx & 31) << 2;
        *(float4*)(out + (row << 7) + c0) = *(const float4*)(ST + row * 132 + c0);
    }
}

// ---------------- 5) combine: Delta_R = D0+D1+D0@D1, then +D2+(.)@D2; emit frags ----
__global__ __launch_bounds__(256, 1) void combine_kernel() {
    extern __shared__ char smc[];
    uint32_t sb = smem_u32(smc);
    float* AF = (float*)(smc + CH_AF);
    float* ST = (float*)(smc + CH_ST);
    int t = threadIdx.x, lane = t & 31, wid = t >> 5;
    int b = blockIdx.x;
    int m0 = (wid & 3) << 5, n0 = (wid >> 2) << 6;

    {
        const float* D0 = g_Dl + (size_t)(b * 3 + 0) * MATSZ;
        const float* D1 = g_Dl + (size_t)(b * 3 + 1) * MATSZ;
        for (int idx = t; idx < 4096; idx += 256) {
            int row = idx >> 5, c0 = (idx & 31) << 2;
            int eo = (row * LDA + c0) << 1;
            float4 v0 = *(const float4*)(D0 + (row << 7) + c0);
            *(float4*)(AF + (row << 7) + c0) = v0;
            *(uint32_t*)(smc + CH_AH + eo)     = pack_bf2(v0.x, v0.y);
            *(uint32_t*)(smc + CH_AH + eo + 4) = pack_bf2(v0.z, v0.w);
            float4 v1 = *(const float4*)(D1 + (row << 7) + c0);
            *(float4*)(ST + row * 132 + c0) = v1;
            *(uint32_t*)(smc + CH_DH + eo)     = pack_bf2(v1.x, v1.y);
            *(uint32_t*)(smc + CH_DH + eo + 4) = pack_bf2(v1.z, v1.w);
        }
        __syncthreads();
        float acc[2][8][4];
        #pragma unroll
        for (int mi = 0; mi < 2; mi++)
            #pragma unroll
            for (int j = 0; j < 8; j++)
                #pragma unroll
                for (int q = 0; q < 4; q++) acc[mi][j][q] = 0.f;
        mma128(sb + CH_AH, sb + CH_DH, acc, lane, wid);
        #pragma unroll
        for (int mi = 0; mi < 2; mi++)
            #pragma unroll
            for (int j = 0; j < 8; j++) {
                int r = m0 + (mi << 4) + (lane >> 2);
                int c = n0 + (j << 3) + ((lane & 3) << 1);
                ST[r * 132 + c]           += AF[(r << 7) + c]           + acc[mi][j][0];
                ST[r * 132 + c + 1]       += AF[(r << 7) + c + 1]       + acc[mi][j][1];
                ST[(r + 8) * 132 + c]     += AF[((r + 8) << 7) + c]     + acc[mi][j][2];
                ST[(r + 8) * 132 + c + 1] += AF[((r + 8) << 7) + c + 1] + acc[mi][j][3];
            }
        __syncthreads();
    }
    {
        const float* D2 = g_Dl + (size_t)(b * 3 + 2) * MATSZ;
        for (int idx = t; idx < 4096; idx += 256) {
            int row = idx >> 5, c0 = (idx & 31) << 2;
            int eo = (row * LDA + c0) << 1;
            float4 v = *(const float4*)(ST + row * 132 + c0);
            *(uint32_t*)(smc + CH_AH + eo)     = pack_bf2(v.x, v.y);
            *(uint32_t*)(smc + CH_AH + eo + 4) = pack_bf2(v.z, v.w);
            float4 v2 = *(const float4*)(D2 + (row << 7) + c0);
            *(float4*)(AF + (row << 7) + c0) = v2;
            *(uint32_t*)(smc + CH_DH + eo)     = pack_bf2(v2.x, v2.y);
            *(uint32_t*)(smc + CH_DH + eo + 4) = pack_bf2(v2.z, v2.w);
        }
        __syncthreads();
        float acc[2][8][4];
        #pragma unroll
        for (int mi = 0; mi < 2; mi++)
            #pragma unroll
            for (int j = 0; j < 8; j++)
                #pragma unroll
                for (int q = 0; q < 4; q++) acc[mi][j][q] = 0.f;
        mma128(sb + CH_AH, sb + CH_DH, acc, lane, wid);
        #pragma unroll
        for (int mi = 0; mi < 2; mi++)
            #pragma unroll
            for (int j = 0; j < 8; j++) {
                int r = m0 + (mi << 4) + (lane >> 2);
                int c = n0 + (j << 3) + ((lane & 3) << 1);
                ST[r * 132 + c]           += AF[(r << 7) + c]           + acc[mi][j][0];
                ST[r * 132 + c + 1]       += AF[(r << 7) + c + 1]       + acc[mi][j][1];
                ST[(r + 8) * 132 + c]     += AF[((r + 8) << 7) + c]     + acc[mi][j][2];
                ST[(r + 8) * 132 + c + 1] += AF[((r + 8) << 7) + c + 1] + acc[mi][j][3];
            }
        __syncthreads();
    }
    for (int idx = t; idx < 8192; idx += 256) {
        int reg = idx & 1;
        int ln = (idx >> 1) & 31;
        int jg = (idx >> 6) & 15;
        int ks = idx >> 10;
        int k0 = ks * 16 + ((ln & 3) << 1) + reg * 8;
        int n = jg * 8 + (ln >> 2);
        g_frag[(size_t)b * 8192 + idx] = pack_bf2(ST[k0 * 132 + n], ST[(k0 + 1) * 132 + n]);
    }
}

// ---------------- 6) apply: y = x + bf16(x)@Delta_R; coalesced epilogue ----------------
__global__ __launch_bounds__(256) void apply_kernel(const float* __restrict__ x,
                                                    float* __restrict__ y) {
    extern __shared__ char smc[];
    uint32_t sb = smem_u32(smc);
    int t = threadIdx.x, lane = t & 31, wid = t >> 5;
    int st = blockIdx.x, b = blockIdx.y;
    const float* xp = x + ((size_t)b * S_ + (size_t)st * 128) * D_;

    for (int idx = t; idx < 4096; idx += 256) {
        int row = idx >> 5, c0 = (idx & 31) << 2;
        float4 v = *(const float4*)(xp + (row << 7) + c0);
        int eo = (row * LDA + c0) << 1;
        *(uint32_t*)(smc + eo)     = pack_bf2(v.x, v.y);
        *(uint32_t*)(smc + eo + 4) = pack_bf2(v.z, v.w);
    }
    __syncthreads();

    int m0 = (wid & 3) << 5, n0 = (wid >> 2) << 6;
    int arow = lane & 15, acol = (lane >> 4) << 3;
    int jgbase = (wid >> 2) << 3;

    float acc[2][8][4];
    #pragma unroll
    for (int mi = 0; mi < 2; mi++)
        #pragma unroll
        for (int j = 0; j < 8; j++)
            #pragma unroll
            for (int q = 0; q < 4; q++) acc[mi][j][q] = 0.f;

    const uint2* fp = (const uint2*)(g_frag + (size_t)b * 8192);
    #pragma unroll
    for (int ks = 0; ks < 8; ks++) {
        int k0 = ks << 4;
        uint2 bfr[8];
        #pragma unroll
        for (int j = 0; j < 8; j++)
            bfr[j] = fp[(ks * 16 + jgbase + j) * 32 + lane];
        uint32_t a0[4], a1[4];
        ldsm_x4(a0, sb + (uint32_t)(((m0 + arow) * LDA + k0 + acol) << 1));
        ldsm_x4(a1, sb + (uint32_t)(((m0 + 16 + arow) * LDA + k0 + acol) << 1));
        #pragma unroll
        for (int j = 0; j < 8; j++) {
            mma16816(acc[0][j], a0, (const uint32_t*)&bfr[j]);
            mma16816(acc[1][j], a1, (const uint32_t*)&bfr[j]);
        }
    }
    __syncthreads();   // XH dead; reuse smem as fp32 output stage [128][132]

    float* stg = (float*)smc;
    #pragma unroll
    for (int mi = 0; mi < 2; mi++)
        #pragma unroll
        for (int j = 0; j < 8; j++) {
            int r = m0 + (mi << 4) + (lane >> 2);
            int c = n0 + (j << 3) + ((lane & 3) << 1);
            *(float2*)(stg + r * 132 + c)       = make_float2(acc[mi][j][0], acc[mi][j][1]);
            *(float2*)(stg + (r + 8) * 132 + c) = make_float2(acc[mi][j][2], acc[mi][j][3]);
        }
    __syncthreads();

    float* yp = y + ((size_t)b * S_ + (size_t)st * 128) * D_;
    for (int idx = t; idx < 4096; idx += 256) {
        int row = idx >> 5, c0 = (idx & 31) << 2;
        float4 d = *(const float4*)(stg + row * 132 + c0);
        float4 v = *(const float4*)(xp + (row << 7) + c0);
        *(float4*)(yp + (row << 7) + c0) =
            make_float4(d.x + v.x, d.y + v.y, d.z + v.z, d.w + v.w);
    }
}

// ---------------- launch ----------------
extern "C" void kernel_launch(void* const* d_in, const int* in_sizes, int n_in,
                              void* d_out, int out_size) {
    const float* x  = (const float*)d_in[0];
    const float* W1 = (const float*)d_in[1];
    const float* b1 = (const float*)d_in[2];
    const float* W2 = (const float*)d_in[3];
    const float* b2 = (const float*)d_in[4];
    float* y = (float*)d_out;

    cudaFuncSetAttribute(pgemm_tc_kernel, cudaFuncAttributeMaxDynamicSharedMemorySize, PG_TOTAL);
    cudaFuncSetAttribute(expm_chain_kernel, cudaFuncAttributeMaxDynamicSharedMemorySize, CH_TOTAL);
    cudaFuncSetAttribute(combine_kernel, cudaFuncAttributeMaxDynamicSharedMemorySize, CH_TOTAL);
    cudaFuncSetAttribute(apply_kernel, cudaFuncAttributeMaxDynamicSharedMemorySize, AP_TOTAL);

    mean_partial_kernel<<<dim3(8, B_), 256>>>(x);
    h_kernel<<<B_, H_>>>(W1, b1);
    pgemm_tc_kernel<<<W2ROWS / 128, 256, PG_TOTAL>>>(W2, b2);
    expm_chain_kernel<<<NMAT, 256, CH_TOTAL>>>();
    combine_kernel<<<B_, 256, CH_TOTAL>>>();
    apply_kernel<<<dim3(S_ / 128, B_), 256, AP_TOTAL>>>(x, y);
}

// round 9
// speedup vs baseline: 1.3157x; 1.0867x over previous
#include <cuda_runtime.h>
#include <cuda_bf16.h>
#include <math.h>
#include <stdint.h>

#define B_    16
#define S_    8192
#define D_    128
#define H_    512
#define NROT  3
#define NMAT  (B_ * NROT)          // 48
#define MATSZ (D_ * D_)            // 16384
#define W2ROWS (NROT * D_ * D_)    // 49152

// ---------------- scratch ----------------
__device__ float g_partial[B_ * 8 * D_];
__device__ float g_h[B_ * H_];
__device__ float g_P[B_ * W2ROWS];          // P[b][r]
__device__ float g_Dl[NMAT * MATSZ];        // Delta = expm(g) - I per matrix
__device__ uint32_t g_frag[B_ * 8192];      // bf16 B-fragments of Delta_R per batch

// ---------------- mma.sync / ldmatrix helpers ----------------
__device__ __forceinline__ uint32_t smem_u32(const void* p) {
    uint32_t a;
    asm("{ .reg .u64 t; cvta.to.shared.u64 t, %1; cvt.u32.u64 %0, t; }" : "=r"(a) : "l"(p));
    return a;
}
__device__ __forceinline__ void ldsm_x4(uint32_t* r, uint32_t addr) {
    asm volatile("ldmatrix.sync.aligned.m8n8.x4.shared.b16 {%0,%1,%2,%3}, [%4];"
                 : "=r"(r[0]), "=r"(r[1]), "=r"(r[2]), "=r"(r[3]) : "r"(addr));
}
__device__ __forceinline__ void ldsm_x2_trans(uint32_t* r, uint32_t addr) {
    asm volatile("ldmatrix.sync.aligned.m8n8.x2.trans.shared.b16 {%0,%1}, [%2];"
                 : "=r"(r[0]), "=r"(r[1]) : "r"(addr));
}
__device__ __forceinline__ void mma16816(float* c, const uint32_t* a, const uint32_t* b) {
    asm volatile("mma.sync.aligned.m16n8k16.row.col.f32.bf16.bf16.f32 "
                 "{%0,%1,%2,%3}, {%4,%5,%6,%7}, {%8,%9}, {%0,%1,%2,%3};"
                 : "+f"(c[0]), "+f"(c[1]), "+f"(c[2]), "+f"(c[3])
                 : "r"(a[0]), "r"(a[1]), "r"(a[2]), "r"(a[3]), "r"(b[0]), "r"(b[1]));
}
__device__ __forceinline__ uint32_t pack_bf2(float a, float b) {
    __nv_bfloat162 h = __floats2bfloat162_rn(a, b);
    return *reinterpret_cast<uint32_t*>(&h);
}

#define LDA 136                      // bf16 plane row stride (elements)
// chain/combine smem layout (bytes)
#define CH_AH 0
#define CH_DH 34816
#define CH_AF 69632                  // fp32 [128][128]
#define CH_ST 135168                 // fp32 [128][132]
#define CH_TOTAL 202752
// apply smem: XH bf16 plane reused as fp32 output stage afterward
#define AP_TOTAL 67584
// pgemm smem: 2 bf16 sub-chunk buffers (K=64) + packed h (stride 260)
#define PG_LDB 72
#define PG_BUF2 (128 * PG_LDB * 2)       // 18432
#define PG_HBF  (2 * PG_BUF2)            // 36864
#define PG_TOTAL (PG_HBF + 16 * 260 * 4) // 53504

// 1-pass 128x128x128 bf16 MMA: acc += A(pa) @ B(pb), planes in smem
__device__ __forceinline__ void mma128(uint32_t pa, uint32_t pb,
                                       float acc[2][8][4], int lane, int wid) {
    int m0 = (wid & 3) << 5, n0 = (wid >> 2) << 6;
    int arow = lane & 15, acol = (lane >> 4) << 3;
    #pragma unroll
    for (int ks = 0; ks < 8; ks++) {
        int k0 = ks << 4;
        uint32_t a0[4], a1[4];
        ldsm_x4(a0, pa + (uint32_t)(((m0 + arow) * LDA + k0 + acol) << 1));
        ldsm_x4(a1, pa + (uint32_t)(((m0 + 16 + arow) * LDA + k0 + acol) << 1));
        uint32_t bfr[8][2];
        #pragma unroll
        for (int j = 0; j < 8; j++)
            ldsm_x2_trans(bfr[j], pb + (uint32_t)(((k0 + arow) * LDA + n0 + (j << 3)) << 1));
        #pragma unroll
        for (int j = 0; j < 8; j++) {
            mma16816(acc[0][j], a0, bfr[j]);
            mma16816(acc[1][j], a1, bfr[j]);
        }
    }
}

// ---------------- 1) mean over S (float4) ----------------
__global__ void mean_partial_kernel(const float* __restrict__ x) {
    int b = blockIdx.y, chunk = blockIdx.x;
    int t = threadIdx.x, lane = t & 31, grp = t >> 5;
    const float* xp = x + ((size_t)b * S_ + (size_t)chunk * 1024 + grp) * D_ + lane * 4;
    float4 s = make_float4(0.f, 0.f, 0.f, 0.f);
    #pragma unroll 8
    for (int i = 0; i < 128; i++) {
        float4 v = *(const float4*)xp;
        s.x += v.x; s.y += v.y; s.z += v.z; s.w += v.w;
        xp += 8 * D_;
    }
    __shared__ float4 red[256];
    red[t] = s;
    __syncthreads();
    if (grp < 4) {
        float4 o = red[t + 128];
        red[t] = make_float4(red[t].x + o.x, red[t].y + o.y, red[t].z + o.z, red[t].w + o.w);
    }
    __syncthreads();
    if (grp < 2) {
        float4 o = red[t + 64];
        red[t] = make_float4(red[t].x + o.x, red[t].y + o.y, red[t].z + o.z, red[t].w + o.w);
    }
    __syncthreads();
    if (grp == 0) {
        float4 o = red[t + 32];
        float4 r = make_float4(red[t].x + o.x, red[t].y + o.y, red[t].z + o.z, red[t].w + o.w);
        *(float4*)&g_partial[(b * 8 + chunk) * D_ + lane * 4] = r;
    }
}

// ---------------- 2) h = gelu(pooled @ W1^T + b1) ----------------
__global__ void h_kernel(const float* __restrict__ W1, const float* __restrict__ b1) {
    int b = blockIdx.x, t = threadIdx.x;
    __shared__ float ps[D_];
    if (t < D_) {
        float s = 0.f;
        #pragma unroll
        for (int c = 0; c < 8; c++) s += g_partial[(b * 8 + c) * D_ + t];
        ps[t] = s * (1.0f / (float)S_);
    }
    __syncthreads();
    float acc = b1[t];
    const float* w = W1 + (size_t)t * D_;
    #pragma unroll 8
    for (int k = 0; k < D_; k++) acc = fmaf(ps[k], w[k], acc);
    float z = acc;
    g_h[b * H_ + t] = 0.5f * z * (1.0f + erff(z * 0.70710678118654752f));
}

// ---------------- 3) P = W2 @ h^T + b2, TC, sub-chunk double-buffered ----------------
// Sub-chunks of K=64 keep register pressure low (2 CTAs/SM); hbf stride 260 is
// bank-conflict-free (bank = lane + const).
__global__ __launch_bounds__(256) void pgemm_tc_kernel(const float* __restrict__ W2,
                                                       const float* __restrict__ b2) {
    extern __shared__ char smc[];
    uint32_t sb = smem_u32(smc);
    uint32_t* hbf = (uint32_t*)(smc + PG_HBF);
    int t = threadIdx.x, lane = t & 31, wid = t >> 5;
    int row0 = blockIdx.x * 128;

    // h -> packed bf16 pairs: hbf[n*260 + k/2]
    for (int idx = t; idx < 16 * 256; idx += 256) {
        int n = idx >> 8, kp = idx & 255;
        float2 v = *(const float2*)&g_h[n * H_ + kp * 2];
        hbf[n * 260 + kp] = pack_bf2(v.x, v.y);
    }

    // prefetch sub-chunk 0 (64 k-values)
    float4 pf[8];
    #pragma unroll
    for (int i = 0; i < 8; i++) {
        int idx = t + (i << 8);
        int row = idx >> 4, k4 = (idx & 15) << 2;
        pf[i] = *(const float4*)&W2[(size_t)(row0 + row) * H_ + k4];
    }

    float acc[2][4] = {};
    int mrow = lane & 15, mcol = (lane >> 4) << 3;

    for (int sc = 0; sc < 8; sc++) {
        char* buf = smc + (sc & 1) * PG_BUF2;
        #pragma unroll
        for (int i = 0; i < 8; i++) {
            int idx = t + (i << 8);
            int row = idx >> 4, k4 = (idx & 15) << 2;
            int eo = (row * PG_LDB + k4) << 1;
            *(uint32_t*)(buf + eo)     = pack_bf2(pf[i].x, pf[i].y);
            *(uint32_t*)(buf + eo + 4) = pack_bf2(pf[i].z, pf[i].w);
        }
        __syncthreads();
        if (sc < 7) {
            #pragma unroll
            for (int i = 0; i < 8; i++) {
                int idx = t + (i << 8);
                int row = idx >> 4, k4 = (idx & 15) << 2;
                pf[i] = *(const float4*)&W2[(size_t)(row0 + row) * H_ + (sc + 1) * 64 + k4];
            }
        }
        uint32_t bfrag[2][4][2];
        #pragma unroll
        for (int jn = 0; jn < 2; jn++) {
            int n = jn * 8 + (lane >> 2);
            #pragma unroll
            for (int ks = 0; ks < 4; ks++)
                #pragma unroll
                for (int rg = 0; rg < 2; rg++) {
                    int kp = sc * 32 + ks * 8 + rg * 4 + (lane & 3);
                    bfrag[jn][ks][rg] = hbf[n * 260 + kp];
                }
        }
        uint32_t bufb = sb + (sc & 1) * PG_BUF2;
        #pragma unroll
        for (int ks = 0; ks < 4; ks++) {
            uint32_t a[4];
            ldsm_x4(a, bufb + (uint32_t)(((wid * 16 + mrow) * PG_LDB + ks * 16 + mcol) << 1));
            mma16816(acc[0], a, bfrag[0][ks]);
            mma16816(acc[1], a, bfrag[1][ks]);
        }
        __syncthreads();
    }

    #pragma unroll
    for (int mi = 0; mi < 2; mi++) {
        int r = row0 + wid * 16 + mi * 8 + (lane >> 2);
        float bias = b2[r];
        #pragma unroll
        for (int jn = 0; jn < 2; jn++) {
            int b0 = jn * 8 + ((lane & 3) << 1);
            g_P[(size_t)b0 * W2ROWS + r]       = acc[jn][mi * 2]     + bias;
            g_P[(size_t)(b0 + 1) * W2ROWS + r] = acc[jn][mi * 2 + 1] + bias;
        }
    }
}

// ---------------- 4) fused antisym + expm (order-4 Taylor, fused bf16 repack) ----------
// g = 0.5*(P - P^T); Delta = g + g^2/2 + g^3/6 + g^4/24 via 3 Horner MMA stages.
__global__ __launch_bounds__(256, 1) void expm_chain_kernel() {
    extern __shared__ char smc[];
    uint32_t sb = smem_u32(smc);
    float* AF = (float*)(smc + CH_AF);
    float* ST = (float*)(smc + CH_ST);
    int t = threadIdx.x, lane = t & 31, wid = t >> 5;
    int m = blockIdx.x;
    int b = m / NROT, i = m - b * NROT;
    const float* P = g_P + (size_t)b * W2ROWS + (size_t)i * MATSZ;

    // stage P coalesced into ST
    for (int idx = t; idx < 4096; idx += 256) {
        int row = idx >> 5, c0 = (idx & 31) << 2;
        *(float4*)(ST + row * 132 + c0) = *(const float4*)(P + (row << 7) + c0);
    }
    __syncthreads();
    // A = 0.5*(P - P^T) -> AF (fp32) + AH (bf16) ; Delta_0 = A/4 -> DH (bf16)
    for (int idx = t; idx < 16384; idx += 256) {
        int d = idx >> 7, e = idx & 127;
        float v = (ST[d * 132 + e] - ST[e * 132 + d]) * 0.5f;
        AF[(d << 7) + e] = v;
        int eo = (d * LDA + e) << 1;
        *(__nv_bfloat16*)(smc + CH_AH + eo) = __float2bfloat16(v);
        *(__nv_bfloat16*)(smc + CH_DH + eo) = __float2bfloat16(v * 0.25f);
    }
    __syncthreads();

    int m0 = (wid & 3) << 5, n0 = (wid >> 2) << 6;

    // Horner: Delta <- (A + A@Delta)/c for c = 3, 2, 1
    #pragma unroll 1
    for (int step = 0; step < 3; step++) {
        float invc = (step == 0) ? (1.f / 3.f) : (step == 1 ? 0.5f : 1.0f);
        float acc[2][8][4];
        #pragma unroll
        for (int mi = 0; mi < 2; mi++)
            #pragma unroll
            for (int j = 0; j < 8; j++)
                #pragma unroll
                for (int q = 0; q < 4; q++) acc[mi][j][q] = 0.f;
        mma128(sb + CH_AH, sb + CH_DH, acc, lane, wid);
        __syncthreads();   // all mma reads of DH done before rewrite
        #pragma unroll
        for (int mi = 0; mi < 2; mi++)
            #pragma unroll
            for (int j = 0; j < 8; j++) {
                int r = m0 + (mi << 4) + (lane >> 2);
                int c = n0 + (j << 3) + ((lane & 3) << 1);
                float v0 = (AF[(r << 7) + c]           + acc[mi][j][0]) * invc;
                float v1 = (AF[(r << 7) + c + 1]       + acc[mi][j][1]) * invc;
                float v2 = (AF[((r + 8) << 7) + c]     + acc[mi][j][2]) * invc;
                float v3 = (AF[((r + 8) << 7) + c + 1] + acc[mi][j][3]) * invc;
                if (step < 2) {
                    *(uint32_t*)(smc + CH_DH + ((r * LDA + c) << 1))       = pack_bf2(v0, v1);
                    *(uint32_t*)(smc + CH_DH + (((r + 8) * LDA + c) << 1)) = pack_bf2(v2, v3);
                } else {
                    *(float2*)(ST + r * 132 + c)       = make_float2(v0, v1);
                    *(float2*)(ST + (r + 8) * 132 + c) = make_float2(v2, v3);
                }
            }
        __syncthreads();
    }

    float* out = g_Dl + (size_t)m * MATSZ;
    for (int idx = t; idx < 4096; idx += 256) {
        int row = idx >> 5, c0 = (idx & 31) << 2;
        *(float4*)(out + (row << 7) + c0) = *(const float4*)(ST + row * 132 + c0);
    }
}

// ---------------- 5) combine: Delta_R = D0+D1+D0@D1, then +D2+(.)@D2; emit frags ----
__global__ __launch_bounds__(256, 1) void combine_kernel() {
    extern __shared__ char smc[];
    uint32_t sb = smem_u32(smc);
    float* AF = (float*)(smc + CH_AF);
    float* ST = (float*)(smc + CH_ST);
    int t = threadIdx.x, lane = t & 31, wid = t >> 5;
    int b = blockIdx.x;
    int m0 = (wid & 3) << 5, n0 = (wid >> 2) << 6;

    // phase 1: D0 -> AF + AH;  D1 -> ST + DH
    {
        const float* D0 = g_Dl + (size_t)(b * 3 + 0) * MATSZ;
        const float* D1 = g_Dl + (size_t)(b * 3 + 1) * MATSZ;
        for (int idx = t; idx < 4096; idx += 256) {
            int row = idx >> 5, c0 = (idx & 31) << 2;
            int eo = (row * LDA + c0) << 1;
            float4 v0 = *(const float4*)(D0 + (row << 7) + c0);
            *(float4*)(AF + (row << 7) + c0) = v0;
            *(uint32_t*)(smc + CH_AH + eo)     = pack_bf2(v0.x, v0.y);
            *(uint32_t*)(smc + CH_AH + eo + 4) = pack_bf2(v0.z, v0.w);
            float4 v1 = *(const float4*)(D1 + (row << 7) + c0);
            *(float4*)(ST + row * 132 + c0) = v1;
            *(uint32_t*)(smc + CH_DH + eo)     = pack_bf2(v1.x, v1.y);
            *(uint32_t*)(smc + CH_DH + eo + 4) = pack_bf2(v1.z, v1.w);
        }
        __syncthreads();
        float acc[2][8][4];
        #pragma unroll
        for (int mi = 0; mi < 2; mi++)
            #pragma unroll
            for (int j = 0; j < 8; j++)
                #pragma unroll
                for (int q = 0; q < 4; q++) acc[mi][j][q] = 0.f;
        mma128(sb + CH_AH, sb + CH_DH, acc, lane, wid);
        __syncthreads();
        // epilogue writes fp32 (ST) AND bf16 A-plane (AH) for phase 2 directly
        #pragma unroll
        for (int mi = 0; mi < 2; mi++)
            #pragma unroll
            for (int j = 0; j < 8; j++) {
                int r = m0 + (mi << 4) + (lane >> 2);
                int c = n0 + (j << 3) + ((lane & 3) << 1);
                float v0 = ST[r * 132 + c]           + AF[(r << 7) + c]           + acc[mi][j][0];
                float v1 = ST[r * 132 + c + 1]       + AF[(r << 7) + c + 1]       + acc[mi][j][1];
                float v2 = ST[(r + 8) * 132 + c]     + AF[((r + 8) << 7) + c]     + acc[mi][j][2];
                float v3 = ST[(r + 8) * 132 + c + 1] + AF[((r + 8) << 7) + c + 1] + acc[mi][j][3];
                *(float2*)(ST + r * 132 + c)       = make_float2(v0, v1);
                *(float2*)(ST + (r + 8) * 132 + c) = make_float2(v2, v3);
                *(uint32_t*)(smc + CH_AH + ((r * LDA + c) << 1))       = pack_bf2(v0, v1);
                *(uint32_t*)(smc + CH_AH + (((r + 8) * LDA + c) << 1)) = pack_bf2(v2, v3);
            }
        __syncthreads();
    }
    // phase 2: D2 -> AF + DH; Delta_R = D01 + D2 + D01@D2
    {
        const float* D2 = g_Dl + (size_t)(b * 3 + 2) * MATSZ;
        for (int idx = t; idx < 4096; idx += 256) {
            int row = idx >> 5, c0 = (idx & 31) << 2;
            int eo = (row * LDA + c0) << 1;
            float4 v2 = *(const float4*)(D2 + (row << 7) + c0);
            *(float4*)(AF + (row << 7) + c0) = v2;
            *(uint32_t*)(smc + CH_DH + eo)     = pack_bf2(v2.x, v2.y);
            *(uint32_t*)(smc + CH_DH + eo + 4) = pack_bf2(v2.z, v2.w);
        }
        __syncthreads();
        float acc[2][8][4];
        #pragma unroll
        for (int mi = 0; mi < 2; mi++)
            #pragma unroll
            for (int j = 0; j < 8; j++)
                #pragma unroll
                for (int q = 0; q < 4; q++) acc[mi][j][q] = 0.f;
        mma128(sb + CH_AH, sb + CH_DH, acc, lane, wid);
        #pragma unroll
        for (int mi = 0; mi < 2; mi++)
            #pragma unroll
            for (int j = 0; j < 8; j++) {
                int r = m0 + (mi << 4) + (lane >> 2);
                int c = n0 + (j << 3) + ((lane & 3) << 1);
                ST[r * 132 + c]           += AF[(r << 7) + c]           + acc[mi][j][0];
                ST[r * 132 + c + 1]       += AF[(r << 7) + c + 1]       + acc[mi][j][1];
                ST[(r + 8) * 132 + c]     += AF[((r + 8) << 7) + c]     + acc[mi][j][2];
                ST[(r + 8) * 132 + c + 1] += AF[((r + 8) << 7) + c + 1] + acc[mi][j][3];
            }
        __syncthreads();
    }
    for (int idx = t; idx < 8192; idx += 256) {
        int reg = idx & 1;
        int ln = (idx >> 1) & 31;
        int jg = (idx >> 6) & 15;
        int ks = idx >> 10;
        int k0 = ks * 16 + ((ln & 3) << 1) + reg * 8;
        int n = jg * 8 + (ln >> 2);
        g_frag[(size_t)b * 8192 + idx] = pack_bf2(ST[k0 * 132 + n], ST[(k0 + 1) * 132 + n]);
    }
}

// ---------------- 6) apply: y = x + bf16(x)@Delta_R; coalesced epilogue ----------------
__global__ __launch_bounds__(256) void apply_kernel(const float* __restrict__ x,
                                                    float* __restrict__ y) {
    extern __shared__ char smc[];
    uint32_t sb = smem_u32(smc);
    int t = threadIdx.x, lane = t & 31, wid = t >> 5;
    int st = blockIdx.x, b = blockIdx.y;
    const float* xp = x + ((size_t)b * S_ + (size_t)st * 128) * D_;

    for (int idx = t; idx < 4096; idx += 256) {
        int row = idx >> 5, c0 = (idx & 31) << 2;
        float4 v = *(const float4*)(xp + (row << 7) + c0);
        int eo = (row * LDA + c0) << 1;
        *(uint32_t*)(smc + eo)     = pack_bf2(v.x, v.y);
        *(uint32_t*)(smc + eo + 4) = pack_bf2(v.z, v.w);
    }
    __syncthreads();

    int m0 = (wid & 3) << 5, n0 = (wid >> 2) << 6;
    int arow = lane & 15, acol = (lane >> 4) << 3;
    int jgbase = (wid >> 2) << 3;

    float acc[2][8][4];
    #pragma unroll
    for (int mi = 0; mi < 2; mi++)
        #pragma unroll
        for (int j = 0; j < 8; j++)
            #pragma unroll
            for (int q = 0; q < 4; q++) acc[mi][j][q] = 0.f;

    const uint2* fp = (const uint2*)(g_frag + (size_t)b * 8192);
    #pragma unroll
    for (int ks = 0; ks < 8; ks++) {
        int k0 = ks << 4;
        uint2 bfr[8];
        #pragma unroll
        for (int j = 0; j < 8; j++)
            bfr[j] = fp[(ks * 16 + jgbase + j) * 32 + lane];
        uint32_t a0[4], a1[4];
        ldsm_x4(a0, sb + (uint32_t)(((m0 + arow) * LDA + k0 + acol) << 1));
        ldsm_x4(a1, sb + (uint32_t)(((m0 + 16 + arow) * LDA + k0 + acol) << 1));
        #pragma unroll
        for (int j = 0; j < 8; j++) {
            mma16816(acc[0][j], a0, (const uint32_t*)&bfr[j]);
            mma16816(acc[1][j], a1, (const uint32_t*)&bfr[j]);
        }
    }
    __syncthreads();   // XH dead; reuse smem as fp32 output stage [128][132]

    float* stg = (float*)smc;
    #pragma unroll
    for (int mi = 0; mi < 2; mi++)
        #pragma unroll
        for (int j = 0; j < 8; j++) {
            int r = m0 + (mi << 4) + (lane >> 2);
            int c = n0 + (j << 3) + ((lane & 3) << 1);
            *(float2*)(stg + r * 132 + c)       = make_float2(acc[mi][j][0], acc[mi][j][1]);
            *(float2*)(stg + (r + 8) * 132 + c) = make_float2(acc[mi][j][2], acc[mi][j][3]);
        }
    __syncthreads();

    float* yp = y + ((size_t)b * S_ + (size_t)st * 128) * D_;
    for (int idx = t; idx < 4096; idx += 256) {
        int row = idx >> 5, c0 = (idx & 31) << 2;
        float4 d = *(const float4*)(stg + row * 132 + c0);
        float4 v = *(const float4*)(xp + (row << 7) + c0);
        *(float4*)(yp + (row << 7) + c0) =
            make_float4(d.x + v.x, d.y + v.y, d.z + v.z, d.w + v.w);
    }
}

// ---------------- launch ----------------
extern "C" void kernel_launch(void* const* d_in, const int* in_sizes, int n_in,
                              void* d_out, int out_size) {
    const float* x  = (const float*)d_in[0];
    const float* W1 = (const float*)d_in[1];
    const float* b1 = (const float*)d_in[2];
    const float* W2 = (const float*)d_in[3];
    const float* b2 = (const float*)d_in[4];
    float* y = (float*)d_out;

    cudaFuncSetAttribute(pgemm_tc_kernel, cudaFuncAttributeMaxDynamicSharedMemorySize, PG_TOTAL);
    cudaFuncSetAttribute(expm_chain_kernel, cudaFuncAttributeMaxDynamicSharedMemorySize, CH_TOTAL);
    cudaFuncSetAttribute(combine_kernel, cudaFuncAttributeMaxDynamicSharedMemorySize, CH_TOTAL);
    cudaFuncSetAttribute(apply_kernel, cudaFuncAttributeMaxDynamicSharedMemorySize, AP_TOTAL);

    mean_partial_kernel<<<dim3(8, B_), 256>>>(x);
    h_kernel<<<B_, H_>>>(W1, b1);
    pgemm_tc_kernel<<<W2ROWS / 128, 256, PG_TOTAL>>>(W2, b2);
    expm_chain_kernel<<<NMAT, 256, CH_TOTAL>>>();
    combine_kernel<<<B_, 256, CH_TOTAL>>>();
    apply_kernel<<<dim3(S_ / 128, B_), 256, AP_TOTAL>>>(x, y);
}

// round 10
// speedup vs baseline: 1.4409x; 1.0952x over previous
#include <cuda_runtime.h>
#include <cuda_bf16.h>
#include <math.h>
#include <stdint.h>

#define B_    16
#define S_    8192
#define D_    128
#define H_    512
#define NROT  3
#define NMAT  (B_ * NROT)          // 48
#define MATSZ (D_ * D_)            // 16384
#define W2ROWS (NROT * D_ * D_)    // 49152

// ---------------- scratch ----------------
__device__ float g_partial[B_ * 8 * D_];
__device__ float g_h[B_ * H_];
__device__ float g_P[B_ * W2ROWS];          // P[b][r]
__device__ float g_Dl[NMAT * MATSZ];        // Delta = expm(g) - I per matrix
__device__ uint32_t g_frag[B_ * 8192];      // bf16 B-fragments of Delta_R per batch

// ---------------- mma.sync / ldmatrix helpers ----------------
__device__ __forceinline__ uint32_t smem_u32(const void* p) {
    uint32_t a;
    asm("{ .reg .u64 t; cvta.to.shared.u64 t, %1; cvt.u32.u64 %0, t; }" : "=r"(a) : "l"(p));
    return a;
}
__device__ __forceinline__ void ldsm_x4(uint32_t* r, uint32_t addr) {
    asm volatile("ldmatrix.sync.aligned.m8n8.x4.shared.b16 {%0,%1,%2,%3}, [%4];"
                 : "=r"(r[0]), "=r"(r[1]), "=r"(r[2]), "=r"(r[3]) : "r"(addr));
}
__device__ __forceinline__ void ldsm_x2_trans(uint32_t* r, uint32_t addr) {
    asm volatile("ldmatrix.sync.aligned.m8n8.x2.trans.shared.b16 {%0,%1}, [%2];"
                 : "=r"(r[0]), "=r"(r[1]) : "r"(addr));
}
__device__ __forceinline__ void mma16816(float* c, const uint32_t* a, const uint32_t* b) {
    asm volatile("mma.sync.aligned.m16n8k16.row.col.f32.bf16.bf16.f32 "
                 "{%0,%1,%2,%3}, {%4,%5,%6,%7}, {%8,%9}, {%0,%1,%2,%3};"
                 : "+f"(c[0]), "+f"(c[1]), "+f"(c[2]), "+f"(c[3])
                 : "r"(a[0]), "r"(a[1]), "r"(a[2]), "r"(a[3]), "r"(b[0]), "r"(b[1]));
}
__device__ __forceinline__ uint32_t pack_bf2(float a, float b) {
    __nv_bfloat162 h = __floats2bfloat162_rn(a, b);
    return *reinterpret_cast<uint32_t*>(&h);
}
__device__ __forceinline__ float bflo(uint32_t w) { return __uint_as_float(w << 16); }
__device__ __forceinline__ float bfhi(uint32_t w) { return __uint_as_float(w & 0xffff0000u); }
__device__ __forceinline__ void split_bf(float v, uint16_t& hi, uint16_t& lo) {
    __nv_bfloat16 h = __float2bfloat16(v);
    float hf = __bfloat162float(h);
    __nv_bfloat16 l = __float2bfloat16(v - hf);
    hi = *reinterpret_cast<uint16_t*>(&h);
    lo = *reinterpret_cast<uint16_t*>(&l);
}

#define LDA 136                      // bf16 plane row stride (elements)
// chain/combine smem layout (bytes)
#define CH_AH 0
#define CH_DH 34816
#define CH_AF 69632                  // fp32 [128][128]
#define CH_ST 135168                 // fp32 [128][132]
#define CH_TOTAL 202752
// apply smem: XH + XL bf16 planes (residual reconstructed from both)
#define AP_XH 0
#define AP_XL 34816
#define AP_TOTAL 69632
// pgemm smem
#define PG_LDB 72
#define PG_BUF2 (128 * PG_LDB * 2)       // 18432
#define PG_HBF  (2 * PG_BUF2)            // 36864
#define PG_TOTAL (PG_HBF + 16 * 260 * 4) // 53504

// 16-warp (512 thr) 128x128x128 bf16 MMA: warp tile 32 rows x 32 cols
__device__ __forceinline__ void mma128w16(uint32_t pa, uint32_t pb,
                                          float acc[2][4][4], int lane, int wid) {
    int m0 = (wid & 3) << 5, n0 = (wid >> 2) << 5;
    int arow = lane & 15, acol = (lane >> 4) << 3;
    #pragma unroll
    for (int ks = 0; ks < 8; ks++) {
        int k0 = ks << 4;
        uint32_t a0[4], a1[4];
        ldsm_x4(a0, pa + (uint32_t)(((m0 + arow) * LDA + k0 + acol) << 1));
        ldsm_x4(a1, pa + (uint32_t)(((m0 + 16 + arow) * LDA + k0 + acol) << 1));
        uint32_t bfr[4][2];
        #pragma unroll
        for (int j = 0; j < 4; j++)
            ldsm_x2_trans(bfr[j], pb + (uint32_t)(((k0 + arow) * LDA + n0 + (j << 3)) << 1));
        #pragma unroll
        for (int j = 0; j < 4; j++) {
            mma16816(acc[0][j], a0, bfr[j]);
            mma16816(acc[1][j], a1, bfr[j]);
        }
    }
}

// ---------------- 1) mean over S (float4) ----------------
__global__ void mean_partial_kernel(const float* __restrict__ x) {
    int b = blockIdx.y, chunk = blockIdx.x;
    int t = threadIdx.x, lane = t & 31, grp = t >> 5;
    const float* xp = x + ((size_t)b * S_ + (size_t)chunk * 1024 + grp) * D_ + lane * 4;
    float4 s = make_float4(0.f, 0.f, 0.f, 0.f);
    #pragma unroll 8
    for (int i = 0; i < 128; i++) {
        float4 v = *(const float4*)xp;
        s.x += v.x; s.y += v.y; s.z += v.z; s.w += v.w;
        xp += 8 * D_;
    }
    __shared__ float4 red[256];
    red[t] = s;
    __syncthreads();
    if (grp < 4) {
        float4 o = red[t + 128];
        red[t] = make_float4(red[t].x + o.x, red[t].y + o.y, red[t].z + o.z, red[t].w + o.w);
    }
    __syncthreads();
    if (grp < 2) {
        float4 o = red[t + 64];
        red[t] = make_float4(red[t].x + o.x, red[t].y + o.y, red[t].z + o.z, red[t].w + o.w);
    }
    __syncthreads();
    if (grp == 0) {
        float4 o = red[t + 32];
        float4 r = make_float4(red[t].x + o.x, red[t].y + o.y, red[t].z + o.z, red[t].w + o.w);
        *(float4*)&g_partial[(b * 8 + chunk) * D_ + lane * 4] = r;
    }
}

// ---------------- 2) h = gelu(pooled @ W1^T + b1) ----------------
__global__ void h_kernel(const float* __restrict__ W1, const float* __restrict__ b1) {
    int b = blockIdx.x, t = threadIdx.x;
    __shared__ float ps[D_];
    if (t < D_) {
        float s = 0.f;
        #pragma unroll
        for (int c = 0; c < 8; c++) s += g_partial[(b * 8 + c) * D_ + t];
        ps[t] = s * (1.0f / (float)S_);
    }
    __syncthreads();
    float acc = b1[t];
    const float* w = W1 + (size_t)t * D_;
    #pragma unroll 8
    for (int k = 0; k < D_; k++) acc = fmaf(ps[k], w[k], acc);
    float z = acc;
    g_h[b * H_ + t] = 0.5f * z * (1.0f + erff(z * 0.70710678118654752f));
}

// ---------------- 3) P = W2 @ h^T + b2, TC, sub-chunk double-buffered ----------------
__global__ __launch_bounds__(256) void pgemm_tc_kernel(const float* __restrict__ W2,
                                                       const float* __restrict__ b2) {
    extern __shared__ char smc[];
    uint32_t sb = smem_u32(smc);
    uint32_t* hbf = (uint32_t*)(smc + PG_HBF);
    int t = threadIdx.x, lane = t & 31, wid = t >> 5;
    int row0 = blockIdx.x * 128;

    for (int idx = t; idx < 16 * 256; idx += 256) {
        int n = idx >> 8, kp = idx & 255;
        float2 v = *(const float2*)&g_h[n * H_ + kp * 2];
        hbf[n * 260 + kp] = pack_bf2(v.x, v.y);
    }

    float4 pf[8];
    #pragma unroll
    for (int i = 0; i < 8; i++) {
        int idx = t + (i << 8);
        int row = idx >> 4, k4 = (idx & 15) << 2;
        pf[i] = *(const float4*)&W2[(size_t)(row0 + row) * H_ + k4];
    }

    float acc[2][4] = {};
    int mrow = lane & 15, mcol = (lane >> 4) << 3;

    for (int sc = 0; sc < 8; sc++) {
        char* buf = smc + (sc & 1) * PG_BUF2;
        #pragma unroll
        for (int i = 0; i < 8; i++) {
            int idx = t + (i << 8);
            int row = idx >> 4, k4 = (idx & 15) << 2;
            int eo = (row * PG_LDB + k4) << 1;
            *(uint32_t*)(buf + eo)     = pack_bf2(pf[i].x, pf[i].y);
            *(uint32_t*)(buf + eo + 4) = pack_bf2(pf[i].z, pf[i].w);
        }
        __syncthreads();
        if (sc < 7) {
            #pragma unroll
            for (int i = 0; i < 8; i++) {
                int idx = t + (i << 8);
                int row = idx >> 4, k4 = (idx & 15) << 2;
                pf[i] = *(const float4*)&W2[(size_t)(row0 + row) * H_ + (sc + 1) * 64 + k4];
            }
        }
        uint32_t bfrag[2][4][2];
        #pragma unroll
        for (int jn = 0; jn < 2; jn++) {
            int n = jn * 8 + (lane >> 2);
            #pragma unroll
            for (int ks = 0; ks < 4; ks++)
                #pragma unroll
                for (int rg = 0; rg < 2; rg++) {
                    int kp = sc * 32 + ks * 8 + rg * 4 + (lane & 3);
                    bfrag[jn][ks][rg] = hbf[n * 260 + kp];
                }
        }
        uint32_t bufb = sb + (sc & 1) * PG_BUF2;
        #pragma unroll
        for (int ks = 0; ks < 4; ks++) {
            uint32_t a[4];
            ldsm_x4(a, bufb + (uint32_t)(((wid * 16 + mrow) * PG_LDB + ks * 16 + mcol) << 1));
            mma16816(acc[0], a, bfrag[0][ks]);
            mma16816(acc[1], a, bfrag[1][ks]);
        }
        __syncthreads();
    }

    #pragma unroll
    for (int mi = 0; mi < 2; mi++) {
        int r = row0 + wid * 16 + mi * 8 + (lane >> 2);
        float bias = b2[r];
        #pragma unroll
        for (int jn = 0; jn < 2; jn++) {
            int b0 = jn * 8 + ((lane & 3) << 1);
            g_P[(size_t)b0 * W2ROWS + r]       = acc[jn][mi * 2]     + bias;
            g_P[(size_t)(b0 + 1) * W2ROWS + r] = acc[jn][mi * 2 + 1] + bias;
        }
    }
}

// ---------------- 4) fused antisym + expm (order-4 Taylor), 512 threads ----------------
__global__ __launch_bounds__(512, 1) void expm_chain_kernel() {
    extern __shared__ char smc[];
    uint32_t sb = smem_u32(smc);
    float* AF = (float*)(smc + CH_AF);
    float* ST = (float*)(smc + CH_ST);
    int t = threadIdx.x, lane = t & 31, wid = t >> 5;
    int m = blockIdx.x;
    int b = m / NROT, i = m - b * NROT;
    const float* P = g_P + (size_t)b * W2ROWS + (size_t)i * MATSZ;

    for (int idx = t; idx < 4096; idx += 512) {
        int row = idx >> 5, c0 = (idx & 31) << 2;
        *(float4*)(ST + row * 132 + c0) = *(const float4*)(P + (row << 7) + c0);
    }
    __syncthreads();
    for (int idx = t; idx < 16384; idx += 512) {
        int d = idx >> 7, e = idx & 127;
        float v = (ST[d * 132 + e] - ST[e * 132 + d]) * 0.5f;
        AF[(d << 7) + e] = v;
        int eo = (d * LDA + e) << 1;
        *(__nv_bfloat16*)(smc + CH_AH + eo) = __float2bfloat16(v);
        *(__nv_bfloat16*)(smc + CH_DH + eo) = __float2bfloat16(v * 0.25f);
    }
    __syncthreads();

    int m0 = (wid & 3) << 5, n0 = (wid >> 2) << 5;

    #pragma unroll 1
    for (int step = 0; step < 3; step++) {
        float invc = (step == 0) ? (1.f / 3.f) : (step == 1 ? 0.5f : 1.0f);
        float acc[2][4][4];
        #pragma unroll
        for (int mi = 0; mi < 2; mi++)
            #pragma unroll
            for (int j = 0; j < 4; j++)
                #pragma unroll
                for (int q = 0; q < 4; q++) acc[mi][j][q] = 0.f;
        mma128w16(sb + CH_AH, sb + CH_DH, acc, lane, wid);
        __syncthreads();
        #pragma unroll
        for (int mi = 0; mi < 2; mi++)
            #pragma unroll
            for (int j = 0; j < 4; j++) {
                int r = m0 + (mi << 4) + (lane >> 2);
                int c = n0 + (j << 3) + ((lane & 3) << 1);
                float v0 = (AF[(r << 7) + c]           + acc[mi][j][0]) * invc;
                float v1 = (AF[(r << 7) + c + 1]       + acc[mi][j][1]) * invc;
                float v2 = (AF[((r + 8) << 7) + c]     + acc[mi][j][2]) * invc;
                float v3 = (AF[((r + 8) << 7) + c + 1] + acc[mi][j][3]) * invc;
                if (step < 2) {
                    *(uint32_t*)(smc + CH_DH + ((r * LDA + c) << 1))       = pack_bf2(v0, v1);
                    *(uint32_t*)(smc + CH_DH + (((r + 8) * LDA + c) << 1)) = pack_bf2(v2, v3);
                } else {
                    *(float2*)(ST + r * 132 + c)       = make_float2(v0, v1);
                    *(float2*)(ST + (r + 8) * 132 + c) = make_float2(v2, v3);
                }
            }
        __syncthreads();
    }

    float* out = g_Dl + (size_t)m * MATSZ;
    for (int idx = t; idx < 4096; idx += 512) {
        int row = idx >> 5, c0 = (idx & 31) << 2;
        *(float4*)(out + (row << 7) + c0) = *(const float4*)(ST + row * 132 + c0);
    }
}

// ---------------- 5) combine (512 threads): Delta_R; emit frags ----------------
__global__ __launch_bounds__(512, 1) void combine_kernel() {
    extern __shared__ char smc[];
    uint32_t sb = smem_u32(smc);
    float* AF = (float*)(smc + CH_AF);
    float* ST = (float*)(smc + CH_ST);
    int t = threadIdx.x, lane = t & 31, wid = t >> 5;
    int b = blockIdx.x;
    int m0 = (wid & 3) << 5, n0 = (wid >> 2) << 5;

    // phase 1: D0 -> AF + AH;  D1 -> ST + DH
    {
        const float* D0 = g_Dl + (size_t)(b * 3 + 0) * MATSZ;
        const float* D1 = g_Dl + (size_t)(b * 3 + 1) * MATSZ;
        for (int idx = t; idx < 4096; idx += 512) {
            int row = idx >> 5, c0 = (idx & 31) << 2;
            int eo = (row * LDA + c0) << 1;
            float4 v0 = *(const float4*)(D0 + (row << 7) + c0);
            *(float4*)(AF + (row << 7) + c0) = v0;
            *(uint32_t*)(smc + CH_AH + eo)     = pack_bf2(v0.x, v0.y);
            *(uint32_t*)(smc + CH_AH + eo + 4) = pack_bf2(v0.z, v0.w);
            float4 v1 = *(const float4*)(D1 + (row << 7) + c0);
            *(float4*)(ST + row * 132 + c0) = v1;
            *(uint32_t*)(smc + CH_DH + eo)     = pack_bf2(v1.x, v1.y);
            *(uint32_t*)(smc + CH_DH + eo + 4) = pack_bf2(v1.z, v1.w);
        }
        __syncthreads();
        float acc[2][4][4];
        #pragma unroll
        for (int mi = 0; mi < 2; mi++)
            #pragma unroll
            for (int j = 0; j < 4; j++)
                #pragma unroll
                for (int q = 0; q < 4; q++) acc[mi][j][q] = 0.f;
        mma128w16(sb + CH_AH, sb + CH_DH, acc, lane, wid);
        __syncthreads();
        #pragma unroll
        for (int mi = 0; mi < 2; mi++)
            #pragma unroll
            for (int j = 0; j < 4; j++) {
                int r = m0 + (mi << 4) + (lane >> 2);
                int c = n0 + (j << 3) + ((lane & 3) << 1);
                float v0 = ST[r * 132 + c]           + AF[(r << 7) + c]           + acc[mi][j][0];
                float v1 = ST[r * 132 + c + 1]       + AF[(r << 7) + c + 1]       + acc[mi][j][1];
                float v2 = ST[(r + 8) * 132 + c]     + AF[((r + 8) << 7) + c]     + acc[mi][j][2];
                float v3 = ST[(r + 8) * 132 + c + 1] + AF[((r + 8) << 7) + c + 1] + acc[mi][j][3];
                *(float2*)(ST + r * 132 + c)       = make_float2(v0, v1);
                *(float2*)(ST + (r + 8) * 132 + c) = make_float2(v2, v3);
                *(uint32_t*)(smc + CH_AH + ((r * LDA + c) << 1))       = pack_bf2(v0, v1);
                *(uint32_t*)(smc + CH_AH + (((r + 8) * LDA + c) << 1)) = pack_bf2(v2, v3);
            }
        __syncthreads();
    }
    // phase 2: D2 -> AF + DH; Delta_R = D01 + D2 + D01@D2
    {
        const float* D2 = g_Dl + (size_t)(b * 3 + 2) * MATSZ;
        for (int idx = t; idx < 4096; idx += 512) {
            int row = idx >> 5, c0 = (idx & 31) << 2;
            int eo = (row * LDA + c0) << 1;
            float4 v2 = *(const float4*)(D2 + (row << 7) + c0);
            *(float4*)(AF + (row << 7) + c0) = v2;
            *(uint32_t*)(smc + CH_DH + eo)     = pack_bf2(v2.x, v2.y);
            *(uint32_t*)(smc + CH_DH + eo + 4) = pack_bf2(v2.z, v2.w);
        }
        __syncthreads();
        float acc[2][4][4];
        #pragma unroll
        for (int mi = 0; mi < 2; mi++)
            #pragma unroll
            for (int j = 0; j < 4; j++)
                #pragma unroll
                for (int q = 0; q < 4; q++) acc[mi][j][q] = 0.f;
        mma128w16(sb + CH_AH, sb + CH_DH, acc, lane, wid);
        #pragma unroll
        for (int mi = 0; mi < 2; mi++)
            #pragma unroll
            for (int j = 0; j < 4; j++) {
                int r = m0 + (mi << 4) + (lane >> 2);
                int c = n0 + (j << 3) + ((lane & 3) << 1);
                ST[r * 132 + c]           += AF[(r << 7) + c]           + acc[mi][j][0];
                ST[r * 132 + c + 1]       += AF[(r << 7) + c + 1]       + acc[mi][j][1];
                ST[(r + 8) * 132 + c]     += AF[((r + 8) << 7) + c]     + acc[mi][j][2];
                ST[(r + 8) * 132 + c + 1] += AF[((r + 8) << 7) + c + 1] + acc[mi][j][3];
            }
        __syncthreads();
    }
    for (int idx = t; idx < 8192; idx += 512) {
        int reg = idx & 1;
        int ln = (idx >> 1) & 31;
        int jg = (idx >> 6) & 15;
        int ks = idx >> 10;
        int k0 = ks * 16 + ((ln & 3) << 1) + reg * 8;
        int n = jg * 8 + (ln >> 2);
        g_frag[(size_t)b * 8192 + idx] = pack_bf2(ST[k0 * 132 + n], ST[(k0 + 1) * 132 + n]);
    }
}

// ---------------- 6) apply: y = (xh+xl) + bf16(x)@Delta_R; direct epilogue STG ----------
__global__ __launch_bounds__(256) void apply_kernel(const float* __restrict__ x,
                                                    float* __restrict__ y) {
    extern __shared__ char smc[];
    uint32_t sb = smem_u32(smc);
    int t = threadIdx.x, lane = t & 31, wid = t >> 5;
    int st = blockIdx.x, b = blockIdx.y;
    const float* xp = x + ((size_t)b * S_ + (size_t)st * 128) * D_;

    // single read of x: split into hi/lo bf16 planes
    for (int idx = t; idx < 4096; idx += 256) {
        int row = idx >> 5, c0 = (idx & 31) << 2;
        float4 v = *(const float4*)(xp + (row << 7) + c0);
        uint16_t h0, l0, h1, l1, h2, l2, h3, l3;
        split_bf(v.x, h0, l0); split_bf(v.y, h1, l1);
        split_bf(v.z, h2, l2); split_bf(v.w, h3, l3);
        int eo = (row * LDA + c0) << 1;
        *(uint32_t*)(smc + AP_XH + eo)     = (uint32_t)h0 | ((uint32_t)h1 << 16);
        *(uint32_t*)(smc + AP_XH + eo + 4) = (uint32_t)h2 | ((uint32_t)h3 << 16);
        *(uint32_t*)(smc + AP_XL + eo)     = (uint32_t)l0 | ((uint32_t)l1 << 16);
        *(uint32_t*)(smc + AP_XL + eo + 4) = (uint32_t)l2 | ((uint32_t)l3 << 16);
    }
    __syncthreads();

    int m0 = (wid & 3) << 5, n0 = (wid >> 2) << 6;
    int arow = lane & 15, acol = (lane >> 4) << 3;
    int jgbase = (wid >> 2) << 3;

    float acc[2][8][4];
    #pragma unroll
    for (int mi = 0; mi < 2; mi++)
        #pragma unroll
        for (int j = 0; j < 8; j++)
            #pragma unroll
            for (int q = 0; q < 4; q++) acc[mi][j][q] = 0.f;

    const uint2* fp = (const uint2*)(g_frag + (size_t)b * 8192);
    #pragma unroll
    for (int ks = 0; ks < 8; ks++) {
        int k0 = ks << 4;
        uint2 bfr[8];
        #pragma unroll
        for (int j = 0; j < 8; j++)
            bfr[j] = fp[(ks * 16 + jgbase + j) * 32 + lane];
        uint32_t a0[4], a1[4];
        ldsm_x4(a0, sb + AP_XH + (uint32_t)(((m0 + arow) * LDA + k0 + acol) << 1));
        ldsm_x4(a1, sb + AP_XH + (uint32_t)(((m0 + 16 + arow) * LDA + k0 + acol) << 1));
        #pragma unroll
        for (int j = 0; j < 8; j++) {
            mma16816(acc[0][j], a0, (const uint32_t*)&bfr[j]);
            mma16816(acc[1][j], a1, (const uint32_t*)&bfr[j]);
        }
    }
    // no sync needed: XH/XL are read-only from here (written before the first sync)

    float* yp = y + ((size_t)b * S_ + (size_t)st * 128) * D_;
    #pragma unroll
    for (int mi = 0; mi < 2; mi++)
        #pragma unroll
        for (int j = 0; j < 8; j++) {
            int r = m0 + (mi << 4) + (lane >> 2);
            int c = n0 + (j << 3) + ((lane & 3) << 1);
            uint32_t wh = *(uint32_t*)(smc + AP_XH + ((r * LDA + c) << 1));
            uint32_t wl = *(uint32_t*)(smc + AP_XL + ((r * LDA + c) << 1));
            *(float2*)(yp + (r << 7) + c) =
                make_float2(acc[mi][j][0] + bflo(wh) + bflo(wl),
                            acc[mi][j][1] + bfhi(wh) + bfhi(wl));
            wh = *(uint32_t*)(smc + AP_XH + (((r + 8) * LDA + c) << 1));
            wl = *(uint32_t*)(smc + AP_XL + (((r + 8) * LDA + c) << 1));
            *(float2*)(yp + ((r + 8) << 7) + c) =
                make_float2(acc[mi][j][2] + bflo(wh) + bflo(wl),
                            acc[mi][j][3] + bfhi(wh) + bfhi(wl));
        }
}

// ---------------- launch ----------------
extern "C" void kernel_launch(void* const* d_in, const int* in_sizes, int n_in,
                              void* d_out, int out_size) {
    const float* x  = (const float*)d_in[0];
    const float* W1 = (const float*)d_in[1];
    const float* b1 = (const float*)d_in[2];
    const float* W2 = (const float*)d_in[3];
    const float* b2 = (const float*)d_in[4];
    float* y = (float*)d_out;

    cudaFuncSetAttribute(pgemm_tc_kernel, cudaFuncAttributeMaxDynamicSharedMemorySize, PG_TOTAL);
    cudaFuncSetAttribute(expm_chain_kernel, cudaFuncAttributeMaxDynamicSharedMemorySize, CH_TOTAL);
    cudaFuncSetAttribute(combine_kernel, cudaFuncAttributeMaxDynamicSharedMemorySize, CH_TOTAL);
    cudaFuncSetAttribute(apply_kernel, cudaFuncAttributeMaxDynamicSharedMemorySize, AP_TOTAL);

    mean_partial_kernel<<<dim3(8, B_), 256>>>(x);
    h_kernel<<<B_, H_>>>(W1, b1);
    pgemm_tc_kernel<<<W2ROWS / 128, 256, PG_TOTAL>>>(W2, b2);
    expm_chain_kernel<<<NMAT, 512, CH_TOTAL>>>();
    combine_kernel<<<B_, 512, CH_TOTAL>>>();
    apply_kernel<<<dim3(S_ / 128, B_), 256, AP_TOTAL>>>(x, y);
}

// round 11
// speedup vs baseline: 1.4704x; 1.0204x over previous
#include <cuda_runtime.h>
#include <cuda_bf16.h>
#include <math.h>
#include <stdint.h>

#define B_    16
#define S_    8192
#define D_    128
#define H_    512
#define NROT  3
#define NMAT  (B_ * NROT)          // 48
#define MATSZ (D_ * D_)            // 16384
#define W2ROWS (NROT * D_ * D_)    // 49152

// ---------------- scratch ----------------
__device__ float g_partial[B_ * 8 * D_];
__device__ float g_h[B_ * H_];
__device__ float g_P[B_ * W2ROWS];          // P[b][r]
__device__ float g_Dl[NMAT * MATSZ];        // Delta = expm(g) - I per matrix
__device__ uint32_t g_frag[B_ * 8192];      // bf16 B-fragments of Delta_R per batch

// ---------------- mma.sync / ldmatrix helpers ----------------
__device__ __forceinline__ uint32_t smem_u32(const void* p) {
    uint32_t a;
    asm("{ .reg .u64 t; cvta.to.shared.u64 t, %1; cvt.u32.u64 %0, t; }" : "=r"(a) : "l"(p));
    return a;
}
__device__ __forceinline__ void ldsm_x4(uint32_t* r, uint32_t addr) {
    asm volatile("ldmatrix.sync.aligned.m8n8.x4.shared.b16 {%0,%1,%2,%3}, [%4];"
                 : "=r"(r[0]), "=r"(r[1]), "=r"(r[2]), "=r"(r[3]) : "r"(addr));
}
__device__ __forceinline__ void ldsm_x2_trans(uint32_t* r, uint32_t addr) {
    asm volatile("ldmatrix.sync.aligned.m8n8.x2.trans.shared.b16 {%0,%1}, [%2];"
                 : "=r"(r[0]), "=r"(r[1]) : "r"(addr));
}
__device__ __forceinline__ void mma16816(float* c, const uint32_t* a, const uint32_t* b) {
    asm volatile("mma.sync.aligned.m16n8k16.row.col.f32.bf16.bf16.f32 "
                 "{%0,%1,%2,%3}, {%4,%5,%6,%7}, {%8,%9}, {%0,%1,%2,%3};"
                 : "+f"(c[0]), "+f"(c[1]), "+f"(c[2]), "+f"(c[3])
                 : "r"(a[0]), "r"(a[1]), "r"(a[2]), "r"(a[3]), "r"(b[0]), "r"(b[1]));
}
__device__ __forceinline__ uint32_t pack_bf2(float a, float b) {
    __nv_bfloat162 h = __floats2bfloat162_rn(a, b);
    return *reinterpret_cast<uint32_t*>(&h);
}

#define LDA 136                      // bf16 plane row stride (elements)
// chain/combine smem layout (bytes)
#define CH_AH 0
#define CH_DH 34816
#define CH_AF 69632                  // fp32 [128][128]
#define CH_ST 135168                 // fp32 [128][132]
#define CH_TOTAL 202752
// apply smem: single XH bf16 plane for a 64-row tile
#define AP_TOTAL (64 * LDA * 2)      // 17408
// pgemm smem
#define PG_LDB 72
#define PG_BUF2 (128 * PG_LDB * 2)       // 18432
#define PG_HBF  (2 * PG_BUF2)            // 36864
#define PG_TOTAL (PG_HBF + 16 * 260 * 4) // 53504

// 16-warp (512 thr) 128x128x128 bf16 MMA: warp tile 32 rows x 32 cols
__device__ __forceinline__ void mma128w16(uint32_t pa, uint32_t pb,
                                          float acc[2][4][4], int lane, int wid) {
    int m0 = (wid & 3) << 5, n0 = (wid >> 2) << 5;
    int arow = lane & 15, acol = (lane >> 4) << 3;
    #pragma unroll
    for (int ks = 0; ks < 8; ks++) {
        int k0 = ks << 4;
        uint32_t a0[4], a1[4];
        ldsm_x4(a0, pa + (uint32_t)(((m0 + arow) * LDA + k0 + acol) << 1));
        ldsm_x4(a1, pa + (uint32_t)(((m0 + 16 + arow) * LDA + k0 + acol) << 1));
        uint32_t bfr[4][2];
        #pragma unroll
        for (int j = 0; j < 4; j++)
            ldsm_x2_trans(bfr[j], pb + (uint32_t)(((k0 + arow) * LDA + n0 + (j << 3)) << 1));
        #pragma unroll
        for (int j = 0; j < 4; j++) {
            mma16816(acc[0][j], a0, bfr[j]);
            mma16816(acc[1][j], a1, bfr[j]);
        }
    }
}

// ---------------- 1) mean over S (float4) ----------------
__global__ void mean_partial_kernel(const float* __restrict__ x) {
    int b = blockIdx.y, chunk = blockIdx.x;
    int t = threadIdx.x, lane = t & 31, grp = t >> 5;
    const float* xp = x + ((size_t)b * S_ + (size_t)chunk * 1024 + grp) * D_ + lane * 4;
    float4 s = make_float4(0.f, 0.f, 0.f, 0.f);
    #pragma unroll 8
    for (int i = 0; i < 128; i++) {
        float4 v = *(const float4*)xp;
        s.x += v.x; s.y += v.y; s.z += v.z; s.w += v.w;
        xp += 8 * D_;
    }
    __shared__ float4 red[256];
    red[t] = s;
    __syncthreads();
    if (grp < 4) {
        float4 o = red[t + 128];
        red[t] = make_float4(red[t].x + o.x, red[t].y + o.y, red[t].z + o.z, red[t].w + o.w);
    }
    __syncthreads();
    if (grp < 2) {
        float4 o = red[t + 64];
        red[t] = make_float4(red[t].x + o.x, red[t].y + o.y, red[t].z + o.z, red[t].w + o.w);
    }
    __syncthreads();
    if (grp == 0) {
        float4 o = red[t + 32];
        float4 r = make_float4(red[t].x + o.x, red[t].y + o.y, red[t].z + o.z, red[t].w + o.w);
        *(float4*)&g_partial[(b * 8 + chunk) * D_ + lane * 4] = r;
    }
}

// ---------------- 2) h = gelu(pooled @ W1^T + b1) ----------------
__global__ void h_kernel(const float* __restrict__ W1, const float* __restrict__ b1) {
    int b = blockIdx.x, t = threadIdx.x;
    __shared__ float ps[D_];
    if (t < D_) {
        float s = 0.f;
        #pragma unroll
        for (int c = 0; c < 8; c++) s += g_partial[(b * 8 + c) * D_ + t];
        ps[t] = s * (1.0f / (float)S_);
    }
    __syncthreads();
    float acc = b1[t];
    const float* w = W1 + (size_t)t * D_;
    #pragma unroll 8
    for (int k = 0; k < D_; k++) acc = fmaf(ps[k], w[k], acc);
    float z = acc;
    g_h[b * H_ + t] = 0.5f * z * (1.0f + erff(z * 0.70710678118654752f));
}

// ---------------- 3) P = W2 @ h^T + b2, TC, sub-chunk double-buffered ----------------
__global__ __launch_bounds__(256) void pgemm_tc_kernel(const float* __restrict__ W2,
                                                       const float* __restrict__ b2) {
    extern __shared__ char smc[];
    uint32_t sb = smem_u32(smc);
    uint32_t* hbf = (uint32_t*)(smc + PG_HBF);
    int t = threadIdx.x, lane = t & 31, wid = t >> 5;
    int row0 = blockIdx.x * 128;

    for (int idx = t; idx < 16 * 256; idx += 256) {
        int n = idx >> 8, kp = idx & 255;
        float2 v = *(const float2*)&g_h[n * H_ + kp * 2];
        hbf[n * 260 + kp] = pack_bf2(v.x, v.y);
    }

    float4 pf[8];
    #pragma unroll
    for (int i = 0; i < 8; i++) {
        int idx = t + (i << 8);
        int row = idx >> 4, k4 = (idx & 15) << 2;
        pf[i] = *(const float4*)&W2[(size_t)(row0 + row) * H_ + k4];
    }

    float acc[2][4] = {};
    int mrow = lane & 15, mcol = (lane >> 4) << 3;

    for (int sc = 0; sc < 8; sc++) {
        char* buf = smc + (sc & 1) * PG_BUF2;
        #pragma unroll
        for (int i = 0; i < 8; i++) {
            int idx = t + (i << 8);
            int row = idx >> 4, k4 = (idx & 15) << 2;
            int eo = (row * PG_LDB + k4) << 1;
            *(uint32_t*)(buf + eo)     = pack_bf2(pf[i].x, pf[i].y);
            *(uint32_t*)(buf + eo + 4) = pack_bf2(pf[i].z, pf[i].w);
        }
        __syncthreads();
        if (sc < 7) {
            #pragma unroll
            for (int i = 0; i < 8; i++) {
                int idx = t + (i << 8);
                int row = idx >> 4, k4 = (idx & 15) << 2;
                pf[i] = *(const float4*)&W2[(size_t)(row0 + row) * H_ + (sc + 1) * 64 + k4];
            }
        }
        uint32_t bfrag[2][4][2];
        #pragma unroll
        for (int jn = 0; jn < 2; jn++) {
            int n = jn * 8 + (lane >> 2);
            #pragma unroll
            for (int ks = 0; ks < 4; ks++)
                #pragma unroll
                for (int rg = 0; rg < 2; rg++) {
                    int kp = sc * 32 + ks * 8 + rg * 4 + (lane & 3);
                    bfrag[jn][ks][rg] = hbf[n * 260 + kp];
                }
        }
        uint32_t bufb = sb + (sc & 1) * PG_BUF2;
        #pragma unroll
        for (int ks = 0; ks < 4; ks++) {
            uint32_t a[4];
            ldsm_x4(a, bufb + (uint32_t)(((wid * 16 + mrow) * PG_LDB + ks * 16 + mcol) << 1));
            mma16816(acc[0], a, bfrag[0][ks]);
            mma16816(acc[1], a, bfrag[1][ks]);
        }
        __syncthreads();
    }

    #pragma unroll
    for (int mi = 0; mi < 2; mi++) {
        int r = row0 + wid * 16 + mi * 8 + (lane >> 2);
        float bias = b2[r];
        #pragma unroll
        for (int jn = 0; jn < 2; jn++) {
            int b0 = jn * 8 + ((lane & 3) << 1);
            g_P[(size_t)b0 * W2ROWS + r]       = acc[jn][mi * 2]     + bias;
            g_P[(size_t)(b0 + 1) * W2ROWS + r] = acc[jn][mi * 2 + 1] + bias;
        }
    }
}

// ---------------- 4) fused antisym + expm (order-4 Taylor), 512 threads ----------------
__global__ __launch_bounds__(512, 1) void expm_chain_kernel() {
    extern __shared__ char smc[];
    uint32_t sb = smem_u32(smc);
    float* AF = (float*)(smc + CH_AF);
    float* ST = (float*)(smc + CH_ST);
    int t = threadIdx.x, lane = t & 31, wid = t >> 5;
    int m = blockIdx.x;
    int b = m / NROT, i = m - b * NROT;
    const float* P = g_P + (size_t)b * W2ROWS + (size_t)i * MATSZ;

    for (int idx = t; idx < 4096; idx += 512) {
        int row = idx >> 5, c0 = (idx & 31) << 2;
        *(float4*)(ST + row * 132 + c0) = *(const float4*)(P + (row << 7) + c0);
    }
    __syncthreads();
    for (int idx = t; idx < 16384; idx += 512) {
        int d = idx >> 7, e = idx & 127;
        float v = (ST[d * 132 + e] - ST[e * 132 + d]) * 0.5f;
        AF[(d << 7) + e] = v;
        int eo = (d * LDA + e) << 1;
        *(__nv_bfloat16*)(smc + CH_AH + eo) = __float2bfloat16(v);
        *(__nv_bfloat16*)(smc + CH_DH + eo) = __float2bfloat16(v * 0.25f);
    }
    __syncthreads();

    int m0 = (wid & 3) << 5, n0 = (wid >> 2) << 5;

    #pragma unroll 1
    for (int step = 0; step < 3; step++) {
        float invc = (step == 0) ? (1.f / 3.f) : (step == 1 ? 0.5f : 1.0f);
        float acc[2][4][4];
        #pragma unroll
        for (int mi = 0; mi < 2; mi++)
            #pragma unroll
            for (int j = 0; j < 4; j++)
                #pragma unroll
                for (int q = 0; q < 4; q++) acc[mi][j][q] = 0.f;
        mma128w16(sb + CH_AH, sb + CH_DH, acc, lane, wid);
        __syncthreads();
        #pragma unroll
        for (int mi = 0; mi < 2; mi++)
            #pragma unroll
            for (int j = 0; j < 4; j++) {
                int r = m0 + (mi << 4) + (lane >> 2);
                int c = n0 + (j << 3) + ((lane & 3) << 1);
                float v0 = (AF[(r << 7) + c]           + acc[mi][j][0]) * invc;
                float v1 = (AF[(r << 7) + c + 1]       + acc[mi][j][1]) * invc;
                float v2 = (AF[((r + 8) << 7) + c]     + acc[mi][j][2]) * invc;
                float v3 = (AF[((r + 8) << 7) + c + 1] + acc[mi][j][3]) * invc;
                if (step < 2) {
                    *(uint32_t*)(smc + CH_DH + ((r * LDA + c) << 1))       = pack_bf2(v0, v1);
                    *(uint32_t*)(smc + CH_DH + (((r + 8) * LDA + c) << 1)) = pack_bf2(v2, v3);
                } else {
                    *(float2*)(ST + r * 132 + c)       = make_float2(v0, v1);
                    *(float2*)(ST + (r + 8) * 132 + c) = make_float2(v2, v3);
                }
            }
        __syncthreads();
    }

    float* out = g_Dl + (size_t)m * MATSZ;
    for (int idx = t; idx < 4096; idx += 512) {
        int row = idx >> 5, c0 = (idx & 31) << 2;
        *(float4*)(out + (row << 7) + c0) = *(const float4*)(ST + row * 132 + c0);
    }
}

// ---------------- 5) combine (512 threads): Delta_R; emit frags ----------------
__global__ __launch_bounds__(512, 1) void combine_kernel() {
    extern __shared__ char smc[];
    uint32_t sb = smem_u32(smc);
    float* AF = (float*)(smc + CH_AF);
    float* ST = (float*)(smc + CH_ST);
    int t = threadIdx.x, lane = t & 31, wid = t >> 5;
    int b = blockIdx.x;
    int m0 = (wid & 3) << 5, n0 = (wid >> 2) << 5;

    // phase 1: D0 -> AF + AH;  D1 -> ST + DH
    {
        const float* D0 = g_Dl + (size_t)(b * 3 + 0) * MATSZ;
        const float* D1 = g_Dl + (size_t)(b * 3 + 1) * MATSZ;
        for (int idx = t; idx < 4096; idx += 512) {
            int row = idx >> 5, c0 = (idx & 31) << 2;
            int eo = (row * LDA + c0) << 1;
            float4 v0 = *(const float4*)(D0 + (row << 7) + c0);
            *(float4*)(AF + (row << 7) + c0) = v0;
            *(uint32_t*)(smc + CH_AH + eo)     = pack_bf2(v0.x, v0.y);
            *(uint32_t*)(smc + CH_AH + eo + 4) = pack_bf2(v0.z, v0.w);
            float4 v1 = *(const float4*)(D1 + (row << 7) + c0);
            *(float4*)(ST + row * 132 + c0) = v1;
            *(uint32_t*)(smc + CH_DH + eo)     = pack_bf2(v1.x, v1.y);
            *(uint32_t*)(smc + CH_DH + eo + 4) = pack_bf2(v1.z, v1.w);
        }
        __syncthreads();
        float acc[2][4][4];
        #pragma unroll
        for (int mi = 0; mi < 2; mi++)
            #pragma unroll
            for (int j = 0; j < 4; j++)
                #pragma unroll
                for (int q = 0; q < 4; q++) acc[mi][j][q] = 0.f;
        mma128w16(sb + CH_AH, sb + CH_DH, acc, lane, wid);
        __syncthreads();
        #pragma unroll
        for (int mi = 0; mi < 2; mi++)
            #pragma unroll
            for (int j = 0; j < 4; j++) {
                int r = m0 + (mi << 4) + (lane >> 2);
                int c = n0 + (j << 3) + ((lane & 3) << 1);
                float v0 = ST[r * 132 + c]           + AF[(r << 7) + c]           + acc[mi][j][0];
                float v1 = ST[r * 132 + c + 1]       + AF[(r << 7) + c + 1]       + acc[mi][j][1];
                float v2 = ST[(r + 8) * 132 + c]     + AF[((r + 8) << 7) + c]     + acc[mi][j][2];
                float v3 = ST[(r + 8) * 132 + c + 1] + AF[((r + 8) << 7) + c + 1] + acc[mi][j][3];
                *(float2*)(ST + r * 132 + c)       = make_float2(v0, v1);
                *(float2*)(ST + (r + 8) * 132 + c) = make_float2(v2, v3);
                *(uint32_t*)(smc + CH_AH + ((r * LDA + c) << 1))       = pack_bf2(v0, v1);
                *(uint32_t*)(smc + CH_AH + (((r + 8) * LDA + c) << 1)) = pack_bf2(v2, v3);
            }
        __syncthreads();
    }
    // phase 2: D2 -> AF + DH; Delta_R = D01 + D2 + D01@D2
    {
        const float* D2 = g_Dl + (size_t)(b * 3 + 2) * MATSZ;
        for (int idx = t; idx < 4096; idx += 512) {
            int row = idx >> 5, c0 = (idx & 31) << 2;
            int eo = (row * LDA + c0) << 1;
            float4 v2 = *(const float4*)(D2 + (row << 7) + c0);
            *(float4*)(AF + (row << 7) + c0) = v2;
            *(uint32_t*)(smc + CH_DH + eo)     = pack_bf2(v2.x, v2.y);
            *(uint32_t*)(smc + CH_DH + eo + 4) = pack_bf2(v2.z, v2.w);
        }
        __syncthreads();
        float acc[2][4][4];
        #pragma unroll
        for (int mi = 0; mi < 2; mi++)
            #pragma unroll
            for (int j = 0; j < 4; j++)
                #pragma unroll
                for (int q = 0; q < 4; q++) acc[mi][j][q] = 0.f;
        mma128w16(sb + CH_AH, sb + CH_DH, acc, lane, wid);
        #pragma unroll
        for (int mi = 0; mi < 2; mi++)
            #pragma unroll
            for (int j = 0; j < 4; j++) {
                int r = m0 + (mi << 4) + (lane >> 2);
                int c = n0 + (j << 3) + ((lane & 3) << 1);
                ST[r * 132 + c]           += AF[(r << 7) + c]           + acc[mi][j][0];
                ST[r * 132 + c + 1]       += AF[(r << 7) + c + 1]       + acc[mi][j][1];
                ST[(r + 8) * 132 + c]     += AF[((r + 8) << 7) + c]     + acc[mi][j][2];
                ST[(r + 8) * 132 + c + 1] += AF[((r + 8) << 7) + c + 1] + acc[mi][j][3];
            }
        __syncthreads();
    }
    for (int idx = t; idx < 8192; idx += 512) {
        int reg = idx & 1;
        int ln = (idx >> 1) & 31;
        int jg = (idx >> 6) & 15;
        int ks = idx >> 10;
        int k0 = ks * 16 + ((ln & 3) << 1) + reg * 8;
        int n = jg * 8 + (ln >> 2);
        g_frag[(size_t)b * 8192 + idx] = pack_bf2(ST[k0 * 132 + n], ST[(k0 + 1) * 132 + n]);
    }
}

// ---------------- 6) apply: 64-row tiles; y = x + bf16(x)@Delta_R ----------------
__global__ __launch_bounds__(256, 3) void apply_kernel(const float* __restrict__ x,
                                                       float* __restrict__ y) {
    extern __shared__ char smc[];
    uint32_t sb = smem_u32(smc);
    int t = threadIdx.x, lane = t & 31, wid = t >> 5;
    int st = blockIdx.x, b = blockIdx.y;
    const float* xp = x + ((size_t)b * S_ + (size_t)st * 64) * D_;

    // single read of x tile (64 rows): bf16 hi plane only
    for (int idx = t; idx < 2048; idx += 256) {
        int row = idx >> 5, c0 = (idx & 31) << 2;
        float4 v = *(const float4*)(xp + (row << 7) + c0);
        int eo = (row * LDA + c0) << 1;
        *(uint32_t*)(smc + eo)     = pack_bf2(v.x, v.y);
        *(uint32_t*)(smc + eo + 4) = pack_bf2(v.z, v.w);
    }
    __syncthreads();

    // warp tile: 32 rows x 32 cols (2 m-groups x 4 n-groups)
    int m0 = (wid & 1) << 5, n0 = (wid >> 1) << 5;
    int arow = lane & 15, acol = (lane >> 4) << 3;
    int jgbase = (wid >> 1) << 2;

    float acc[2][4][4];
    #pragma unroll
    for (int mi = 0; mi < 2; mi++)
        #pragma unroll
        for (int j = 0; j < 4; j++)
            #pragma unroll
            for (int q = 0; q < 4; q++) acc[mi][j][q] = 0.f;

    const uint2* fp = (const uint2*)(g_frag + (size_t)b * 8192);
    #pragma unroll
    for (int ks = 0; ks < 8; ks++) {
        int k0 = ks << 4;
        uint2 bfr[4];
        #pragma unroll
        for (int j = 0; j < 4; j++)
            bfr[j] = fp[(ks * 16 + jgbase + j) * 32 + lane];
        uint32_t a0[4], a1[4];
        ldsm_x4(a0, sb + (uint32_t)(((m0 + arow) * LDA + k0 + acol) << 1));
        ldsm_x4(a1, sb + (uint32_t)(((m0 + 16 + arow) * LDA + k0 + acol) << 1));
        #pragma unroll
        for (int j = 0; j < 4; j++) {
            mma16816(acc[0][j], a0, (const uint32_t*)&bfr[j]);
            mma16816(acc[1][j], a1, (const uint32_t*)&bfr[j]);
        }
    }

    // epilogue: residual x re-read from gmem (L2-hot), direct stores
    float* yp = y + ((size_t)b * S_ + (size_t)st * 64) * D_;
    #pragma unroll
    for (int mi = 0; mi < 2; mi++)
        #pragma unroll
        for (int j = 0; j < 4; j++) {
            int r = m0 + (mi << 4) + (lane >> 2);
            int c = n0 + (j << 3) + ((lane & 3) << 1);
            float2 xv = *(const float2*)(xp + (r << 7) + c);
            *(float2*)(yp + (r << 7) + c) =
                make_float2(acc[mi][j][0] + xv.x, acc[mi][j][1] + xv.y);
            xv = *(const float2*)(xp + ((r + 8) << 7) + c);
            *(float2*)(yp + ((r + 8) << 7) + c) =
                make_float2(acc[mi][j][2] + xv.x, acc[mi][j][3] + xv.y);
        }
}

// ---------------- launch ----------------
extern "C" void kernel_launch(void* const* d_in, const int* in_sizes, int n_in,
                              void* d_out, int out_size) {
    const float* x  = (const float*)d_in[0];
    const float* W1 = (const float*)d_in[1];
    const float* b1 = (const float*)d_in[2];
    const float* W2 = (const float*)d_in[3];
    const float* b2 = (const float*)d_in[4];
    float* y = (float*)d_out;

    cudaFuncSetAttribute(pgemm_tc_kernel, cudaFuncAttributeMaxDynamicSharedMemorySize, PG_TOTAL);
    cudaFuncSetAttribute(expm_chain_kernel, cudaFuncAttributeMaxDynamicSharedMemorySize, CH_TOTAL);
    cudaFuncSetAttribute(combine_kernel, cudaFuncAttributeMaxDynamicSharedMemorySize, CH_TOTAL);
    cudaFuncSetAttribute(apply_kernel, cudaFuncAttributeMaxDynamicSharedMemorySize, AP_TOTAL);

    mean_partial_kernel<<<dim3(8, B_), 256>>>(x);
    h_kernel<<<B_, H_>>>(W1, b1);
    pgemm_tc_kernel<<<W2ROWS / 128, 256, PG_TOTAL>>>(W2, b2);
    expm_chain_kernel<<<NMAT, 512, CH_TOTAL>>>();
    combine_kernel<<<B_, 512, CH_TOTAL>>>();
    apply_kernel<<<dim3(S_ / 64, B_), 256, AP_TOTAL>>>(x, y);
}

// round 12
// speedup vs baseline: 1.5315x; 1.0416x over previous
#include <cuda_runtime.h>
#include <cuda_bf16.h>
#include <math.h>
#include <stdint.h>

#define B_    16
#define S_    8192
#define D_    128
#define H_    512
#define NROT  3
#define NMAT  (B_ * NROT)          // 48
#define MATSZ (D_ * D_)            // 16384
#define W2ROWS (NROT * D_ * D_)    // 49152

// ---------------- scratch ----------------
__device__ float g_partial[B_ * 8 * D_];
__device__ float g_h[B_ * H_];
__device__ float g_P[B_ * W2ROWS];          // P[b][r]
__device__ float g_Dl[NMAT * MATSZ];        // Delta = expm(g) - I per matrix
__device__ uint32_t g_frag[B_ * 8192];      // bf16 B-fragments of Delta_R per batch

// ---------------- mma.sync / ldmatrix helpers ----------------
__device__ __forceinline__ uint32_t smem_u32(const void* p) {
    uint32_t a;
    asm("{ .reg .u64 t; cvta.to.shared.u64 t, %1; cvt.u32.u64 %0, t; }" : "=r"(a) : "l"(p));
    return a;
}
__device__ __forceinline__ void ldsm_x4(uint32_t* r, uint32_t addr) {
    asm volatile("ldmatrix.sync.aligned.m8n8.x4.shared.b16 {%0,%1,%2,%3}, [%4];"
                 : "=r"(r[0]), "=r"(r[1]), "=r"(r[2]), "=r"(r[3]) : "r"(addr));
}
__device__ __forceinline__ void ldsm_x2_trans(uint32_t* r, uint32_t addr) {
    asm volatile("ldmatrix.sync.aligned.m8n8.x2.trans.shared.b16 {%0,%1}, [%2];"
                 : "=r"(r[0]), "=r"(r[1]) : "r"(addr));
}
__device__ __forceinline__ void mma16816(float* c, const uint32_t* a, const uint32_t* b) {
    asm volatile("mma.sync.aligned.m16n8k16.row.col.f32.bf16.bf16.f32 "
                 "{%0,%1,%2,%3}, {%4,%5,%6,%7}, {%8,%9}, {%0,%1,%2,%3};"
                 : "+f"(c[0]), "+f"(c[1]), "+f"(c[2]), "+f"(c[3])
                 : "r"(a[0]), "r"(a[1]), "r"(a[2]), "r"(a[3]), "r"(b[0]), "r"(b[1]));
}
__device__ __forceinline__ uint32_t pack_bf2(float a, float b) {
    __nv_bfloat162 h = __floats2bfloat162_rn(a, b);
    return *reinterpret_cast<uint32_t*>(&h);
}

#define LDA 136                      // bf16 plane row stride (elements)
// chain/combine smem layout (bytes)
#define CH_AH 0
#define CH_DH 34816
#define CH_AF 69632                  // fp32 [128][128]
#define CH_ST 135168                 // fp32 [128][132]
#define CH_TOTAL 202752
// apply smem: frag copy (32KB) + XH bf16 plane for a 64-row tile (17408)
#define AP_FR 0
#define AP_XH 32768
#define AP_TOTAL (32768 + 64 * LDA * 2)   // 50176
#define AP_TILES 4
// pgemm smem
#define PG_LDB 72
#define PG_BUF2 (128 * PG_LDB * 2)       // 18432
#define PG_HBF  (2 * PG_BUF2)            // 36864
#define PG_TOTAL (PG_HBF + 16 * 260 * 4) // 53504

// 16-warp (512 thr) 128x128x128 bf16 MMA: warp tile 32 rows x 32 cols
__device__ __forceinline__ void mma128w16(uint32_t pa, uint32_t pb,
                                          float acc[2][4][4], int lane, int wid) {
    int m0 = (wid & 3) << 5, n0 = (wid >> 2) << 5;
    int arow = lane & 15, acol = (lane >> 4) << 3;
    #pragma unroll
    for (int ks = 0; ks < 8; ks++) {
        int k0 = ks << 4;
        uint32_t a0[4], a1[4];
        ldsm_x4(a0, pa + (uint32_t)(((m0 + arow) * LDA + k0 + acol) << 1));
        ldsm_x4(a1, pa + (uint32_t)(((m0 + 16 + arow) * LDA + k0 + acol) << 1));
        uint32_t bfr[4][2];
        #pragma unroll
        for (int j = 0; j < 4; j++)
            ldsm_x2_trans(bfr[j], pb + (uint32_t)(((k0 + arow) * LDA + n0 + (j << 3)) << 1));
        #pragma unroll
        for (int j = 0; j < 4; j++) {
            mma16816(acc[0][j], a0, bfr[j]);
            mma16816(acc[1][j], a1, bfr[j]);
        }
    }
}

// ---------------- 1) mean over S (float4) ----------------
__global__ void mean_partial_kernel(const float* __restrict__ x) {
    int b = blockIdx.y, chunk = blockIdx.x;
    int t = threadIdx.x, lane = t & 31, grp = t >> 5;
    const float* xp = x + ((size_t)b * S_ + (size_t)chunk * 1024 + grp) * D_ + lane * 4;
    float4 s = make_float4(0.f, 0.f, 0.f, 0.f);
    #pragma unroll 8
    for (int i = 0; i < 128; i++) {
        float4 v = *(const float4*)xp;
        s.x += v.x; s.y += v.y; s.z += v.z; s.w += v.w;
        xp += 8 * D_;
    }
    __shared__ float4 red[256];
    red[t] = s;
    __syncthreads();
    if (grp < 4) {
        float4 o = red[t + 128];
        red[t] = make_float4(red[t].x + o.x, red[t].y + o.y, red[t].z + o.z, red[t].w + o.w);
    }
    __syncthreads();
    if (grp < 2) {
        float4 o = red[t + 64];
        red[t] = make_float4(red[t].x + o.x, red[t].y + o.y, red[t].z + o.z, red[t].w + o.w);
    }
    __syncthreads();
    if (grp == 0) {
        float4 o = red[t + 32];
        float4 r = make_float4(red[t].x + o.x, red[t].y + o.y, red[t].z + o.z, red[t].w + o.w);
        *(float4*)&g_partial[(b * 8 + chunk) * D_ + lane * 4] = r;
    }
}

// ---------------- 2) h = gelu(pooled @ W1^T + b1) ----------------
__global__ void h_kernel(const float* __restrict__ W1, const float* __restrict__ b1) {
    int b = blockIdx.x, t = threadIdx.x;
    __shared__ float ps[D_];
    if (t < D_) {
        float s = 0.f;
        #pragma unroll
        for (int c = 0; c < 8; c++) s += g_partial[(b * 8 + c) * D_ + t];
        ps[t] = s * (1.0f / (float)S_);
    }
    __syncthreads();
    float acc = b1[t];
    const float* w = W1 + (size_t)t * D_;
    #pragma unroll 8
    for (int k = 0; k < D_; k++) acc = fmaf(ps[k], w[k], acc);
    float z = acc;
    g_h[b * H_ + t] = 0.5f * z * (1.0f + erff(z * 0.70710678118654752f));
}

// ---------------- 3) P = W2 @ h^T + b2, TC, sub-chunk double-buffered ----------------
__global__ __launch_bounds__(256) void pgemm_tc_kernel(const float* __restrict__ W2,
                                                       const float* __restrict__ b2) {
    extern __shared__ char smc[];
    uint32_t sb = smem_u32(smc);
    uint32_t* hbf = (uint32_t*)(smc + PG_HBF);
    int t = threadIdx.x, lane = t & 31, wid = t >> 5;
    int row0 = blockIdx.x * 128;

    for (int idx = t; idx < 16 * 256; idx += 256) {
        int n = idx >> 8, kp = idx & 255;
        float2 v = *(const float2*)&g_h[n * H_ + kp * 2];
        hbf[n * 260 + kp] = pack_bf2(v.x, v.y);
    }

    float4 pf[8];
    #pragma unroll
    for (int i = 0; i < 8; i++) {
        int idx = t + (i << 8);
        int row = idx >> 4, k4 = (idx & 15) << 2;
        pf[i] = *(const float4*)&W2[(size_t)(row0 + row) * H_ + k4];
    }

    float acc[2][4] = {};
    int mrow = lane & 15, mcol = (lane >> 4) << 3;

    for (int sc = 0; sc < 8; sc++) {
        char* buf = smc + (sc & 1) * PG_BUF2;
        #pragma unroll
        for (int i = 0; i < 8; i++) {
            int idx = t + (i << 8);
            int row = idx >> 4, k4 = (idx & 15) << 2;
            int eo = (row * PG_LDB + k4) << 1;
            *(uint32_t*)(buf + eo)     = pack_bf2(pf[i].x, pf[i].y);
            *(uint32_t*)(buf + eo + 4) = pack_bf2(pf[i].z, pf[i].w);
        }
        __syncthreads();
        if (sc < 7) {
            #pragma unroll
            for (int i = 0; i < 8; i++) {
                int idx = t + (i << 8);
                int row = idx >> 4, k4 = (idx & 15) << 2;
                pf[i] = *(const float4*)&W2[(size_t)(row0 + row) * H_ + (sc + 1) * 64 + k4];
            }
        }
        uint32_t bfrag[2][4][2];
        #pragma unroll
        for (int jn = 0; jn < 2; jn++) {
            int n = jn * 8 + (lane >> 2);
            #pragma unroll
            for (int ks = 0; ks < 4; ks++)
                #pragma unroll
                for (int rg = 0; rg < 2; rg++) {
                    int kp = sc * 32 + ks * 8 + rg * 4 + (lane & 3);
                    bfrag[jn][ks][rg] = hbf[n * 260 + kp];
                }
        }
        uint32_t bufb = sb + (sc & 1) * PG_BUF2;
        #pragma unroll
        for (int ks = 0; ks < 4; ks++) {
            uint32_t a[4];
            ldsm_x4(a, bufb + (uint32_t)(((wid * 16 + mrow) * PG_LDB + ks * 16 + mcol) << 1));
            mma16816(acc[0], a, bfrag[0][ks]);
            mma16816(acc[1], a, bfrag[1][ks]);
        }
        __syncthreads();
    }

    #pragma unroll
    for (int mi = 0; mi < 2; mi++) {
        int r = row0 + wid * 16 + mi * 8 + (lane >> 2);
        float bias = b2[r];
        #pragma unroll
        for (int jn = 0; jn < 2; jn++) {
            int b0 = jn * 8 + ((lane & 3) << 1);
            g_P[(size_t)b0 * W2ROWS + r]       = acc[jn][mi * 2]     + bias;
            g_P[(size_t)(b0 + 1) * W2ROWS + r] = acc[jn][mi * 2 + 1] + bias;
        }
    }
}

// ---------------- 4) fused antisym + expm (order-4 Taylor), 512 threads ----------------
__global__ __launch_bounds__(512, 1) void expm_chain_kernel() {
    extern __shared__ char smc[];
    uint32_t sb = smem_u32(smc);
    float* AF = (float*)(smc + CH_AF);
    float* ST = (float*)(smc + CH_ST);
    int t = threadIdx.x, lane = t & 31, wid = t >> 5;
    int m = blockIdx.x;
    int b = m / NROT, i = m - b * NROT;
    const float* P = g_P + (size_t)b * W2ROWS + (size_t)i * MATSZ;

    for (int idx = t; idx < 4096; idx += 512) {
        int row = idx >> 5, c0 = (idx & 31) << 2;
        *(float4*)(ST + row * 132 + c0) = *(const float4*)(P + (row << 7) + c0);
    }
    __syncthreads();
    for (int idx = t; idx < 16384; idx += 512) {
        int d = idx >> 7, e = idx & 127;
        float v = (ST[d * 132 + e] - ST[e * 132 + d]) * 0.5f;
        AF[(d << 7) + e] = v;
        int eo = (d * LDA + e) << 1;
        *(__nv_bfloat16*)(smc + CH_AH + eo) = __float2bfloat16(v);
        *(__nv_bfloat16*)(smc + CH_DH + eo) = __float2bfloat16(v * 0.25f);
    }
    __syncthreads();

    int m0 = (wid & 3) << 5, n0 = (wid >> 2) << 5;

    #pragma unroll 1
    for (int step = 0; step < 3; step++) {
        float invc = (step == 0) ? (1.f / 3.f) : (step == 1 ? 0.5f : 1.0f);
        float acc[2][4][4];
        #pragma unroll
        for (int mi = 0; mi < 2; mi++)
            #pragma unroll
            for (int j = 0; j < 4; j++)
                #pragma unroll
                for (int q = 0; q < 4; q++) acc[mi][j][q] = 0.f;
        mma128w16(sb + CH_AH, sb + CH_DH, acc, lane, wid);
        __syncthreads();
        #pragma unroll
        for (int mi = 0; mi < 2; mi++)
            #pragma unroll
            for (int j = 0; j < 4; j++) {
                int r = m0 + (mi << 4) + (lane >> 2);
                int c = n0 + (j << 3) + ((lane & 3) << 1);
                float v0 = (AF[(r << 7) + c]           + acc[mi][j][0]) * invc;
                float v1 = (AF[(r << 7) + c + 1]       + acc[mi][j][1]) * invc;
                float v2 = (AF[((r + 8) << 7) + c]     + acc[mi][j][2]) * invc;
                float v3 = (AF[((r + 8) << 7) + c + 1] + acc[mi][j][3]) * invc;
                if (step < 2) {
                    *(uint32_t*)(smc + CH_DH + ((r * LDA + c) << 1))       = pack_bf2(v0, v1);
                    *(uint32_t*)(smc + CH_DH + (((r + 8) * LDA + c) << 1)) = pack_bf2(v2, v3);
                } else {
                    *(float2*)(ST + r * 132 + c)       = make_float2(v0, v1);
                    *(float2*)(ST + (r + 8) * 132 + c) = make_float2(v2, v3);
                }
            }
        __syncthreads();
    }

    float* out = g_Dl + (size_t)m * MATSZ;
    for (int idx = t; idx < 4096; idx += 512) {
        int row = idx >> 5, c0 = (idx & 31) << 2;
        *(float4*)(out + (row << 7) + c0) = *(const float4*)(ST + row * 132 + c0);
    }
}

// ---------------- 5) combine (512 threads): Delta_R; emit frags ----------------
__global__ __launch_bounds__(512, 1) void combine_kernel() {
    extern __shared__ char smc[];
    uint32_t sb = smem_u32(smc);
    float* AF = (float*)(smc + CH_AF);
    float* ST = (float*)(smc + CH_ST);
    int t = threadIdx.x, lane = t & 31, wid = t >> 5;
    int b = blockIdx.x;
    int m0 = (wid & 3) << 5, n0 = (wid >> 2) << 5;

    // phase 1: D0 -> AF + AH;  D1 -> ST + DH
    {
        const float* D0 = g_Dl + (size_t)(b * 3 + 0) * MATSZ;
        const float* D1 = g_Dl + (size_t)(b * 3 + 1) * MATSZ;
        for (int idx = t; idx < 4096; idx += 512) {
            int row = idx >> 5, c0 = (idx & 31) << 2;
            int eo = (row * LDA + c0) << 1;
            float4 v0 = *(const float4*)(D0 + (row << 7) + c0);
            *(float4*)(AF + (row << 7) + c0) = v0;
            *(uint32_t*)(smc + CH_AH + eo)     = pack_bf2(v0.x, v0.y);
            *(uint32_t*)(smc + CH_AH + eo + 4) = pack_bf2(v0.z, v0.w);
            float4 v1 = *(const float4*)(D1 + (row << 7) + c0);
            *(float4*)(ST + row * 132 + c0) = v1;
            *(uint32_t*)(smc + CH_DH + eo)     = pack_bf2(v1.x, v1.y);
            *(uint32_t*)(smc + CH_DH + eo + 4) = pack_bf2(v1.z, v1.w);
        }
        __syncthreads();
        float acc[2][4][4];
        #pragma unroll
        for (int mi = 0; mi < 2; mi++)
            #pragma unroll
            for (int j = 0; j < 4; j++)
                #pragma unroll
                for (int q = 0; q < 4; q++) acc[mi][j][q] = 0.f;
        mma128w16(sb + CH_AH, sb + CH_DH, acc, lane, wid);
        __syncthreads();
        #pragma unroll
        for (int mi = 0; mi < 2; mi++)
            #pragma unroll
            for (int j = 0; j < 4; j++) {
                int r = m0 + (mi << 4) + (lane >> 2);
                int c = n0 + (j << 3) + ((lane & 3) << 1);
                float v0 = ST[r * 132 + c]           + AF[(r << 7) + c]           + acc[mi][j][0];
                float v1 = ST[r * 132 + c + 1]       + AF[(r << 7) + c + 1]       + acc[mi][j][1];
                float v2 = ST[(r + 8) * 132 + c]     + AF[((r + 8) << 7) + c]     + acc[mi][j][2];
                float v3 = ST[(r + 8) * 132 + c + 1] + AF[((r + 8) << 7) + c + 1] + acc[mi][j][3];
                *(float2*)(ST + r * 132 + c)       = make_float2(v0, v1);
                *(float2*)(ST + (r + 8) * 132 + c) = make_float2(v2, v3);
                *(uint32_t*)(smc + CH_AH + ((r * LDA + c) << 1))       = pack_bf2(v0, v1);
                *(uint32_t*)(smc + CH_AH + (((r + 8) * LDA + c) << 1)) = pack_bf2(v2, v3);
            }
        __syncthreads();
    }
    // phase 2: D2 -> AF + DH; Delta_R = D01 + D2 + D01@D2
    {
        const float* D2 = g_Dl + (size_t)(b * 3 + 2) * MATSZ;
        for (int idx = t; idx < 4096; idx += 512) {
            int row = idx >> 5, c0 = (idx & 31) << 2;
            int eo = (row * LDA + c0) << 1;
            float4 v2 = *(const float4*)(D2 + (row << 7) + c0);
            *(float4*)(AF + (row << 7) + c0) = v2;
            *(uint32_t*)(smc + CH_DH + eo)     = pack_bf2(v2.x, v2.y);
            *(uint32_t*)(smc + CH_DH + eo + 4) = pack_bf2(v2.z, v2.w);
        }
        __syncthreads();
        float acc[2][4][4];
        #pragma unroll
        for (int mi = 0; mi < 2; mi++)
            #pragma unroll
            for (int j = 0; j < 4; j++)
                #pragma unroll
                for (int q = 0; q < 4; q++) acc[mi][j][q] = 0.f;
        mma128w16(sb + CH_AH, sb + CH_DH, acc, lane, wid);
        #pragma unroll
        for (int mi = 0; mi < 2; mi++)
            #pragma unroll
            for (int j = 0; j < 4; j++) {
                int r = m0 + (mi << 4) + (lane >> 2);
                int c = n0 + (j << 3) + ((lane & 3) << 1);
                ST[r * 132 + c]           += AF[(r << 7) + c]           + acc[mi][j][0];
                ST[r * 132 + c + 1]       += AF[(r << 7) + c + 1]       + acc[mi][j][1];
                ST[(r + 8) * 132 + c]     += AF[((r + 8) << 7) + c]     + acc[mi][j][2];
                ST[(r + 8) * 132 + c + 1] += AF[((r + 8) << 7) + c + 1] + acc[mi][j][3];
            }
        __syncthreads();
    }
    for (int idx = t; idx < 8192; idx += 512) {
        int reg = idx & 1;
        int ln = (idx >> 1) & 31;
        int jg = (idx >> 6) & 15;
        int ks = idx >> 10;
        int k0 = ks * 16 + ((ln & 3) << 1) + reg * 8;
        int n = jg * 8 + (ln >> 2);
        g_frag[(size_t)b * 8192 + idx] = pack_bf2(ST[k0 * 132 + n], ST[(k0 + 1) * 132 + n]);
    }
}

// ---------------- 6) apply: 4x 64-row tiles per CTA; frags staged in smem ----------------
__global__ __launch_bounds__(256, 3) void apply_kernel(const float* __restrict__ x,
                                                       float* __restrict__ y) {
    extern __shared__ char smc[];
    uint32_t sb = smem_u32(smc);
    int t = threadIdx.x, lane = t & 31, wid = t >> 5;
    int sg = blockIdx.x, b = blockIdx.y;
    int st0 = sg * AP_TILES;

    // stage this batch's frag set once (32KB)
    {
        const uint4* src = (const uint4*)(g_frag + (size_t)b * 8192);
        uint4* dst = (uint4*)(smc + AP_FR);
        for (int i = t; i < 2048; i += 256) dst[i] = src[i];
    }

    int m0 = (wid & 1) << 5, n0 = (wid >> 1) << 5;
    int arow = lane & 15, acol = (lane >> 4) << 3;
    int jgbase = (wid >> 1) << 2;

    #pragma unroll 1
    for (int tile = 0; tile < AP_TILES; tile++) {
        const float* xp = x + ((size_t)b * S_ + (size_t)(st0 + tile) * 64) * D_;
        __syncthreads();   // iter0: frag stores visible; later: prior MMA reads of XH done
        for (int idx = t; idx < 2048; idx += 256) {
            int row = idx >> 5, c0 = (idx & 31) << 2;
            float4 v = *(const float4*)(xp + (row << 7) + c0);
            int eo = (row * LDA + c0) << 1;
            *(uint32_t*)(smc + AP_XH + eo)     = pack_bf2(v.x, v.y);
            *(uint32_t*)(smc + AP_XH + eo + 4) = pack_bf2(v.z, v.w);
        }
        __syncthreads();

        float acc[2][4][4];
        #pragma unroll
        for (int mi = 0; mi < 2; mi++)
            #pragma unroll
            for (int j = 0; j < 4; j++)
                #pragma unroll
                for (int q = 0; q < 4; q++) acc[mi][j][q] = 0.f;

        #pragma unroll
        for (int ks = 0; ks < 8; ks++) {
            int k0 = ks << 4;
            uint2 bfr[4];
            #pragma unroll
            for (int j = 0; j < 4; j++)
                bfr[j] = *(const uint2*)(smc + AP_FR +
                          (((ks * 16 + jgbase + j) * 32 + lane) << 3));
            uint32_t a0[4], a1[4];
            ldsm_x4(a0, sb + AP_XH + (uint32_t)(((m0 + arow) * LDA + k0 + acol) << 1));
            ldsm_x4(a1, sb + AP_XH + (uint32_t)(((m0 + 16 + arow) * LDA + k0 + acol) << 1));
            #pragma unroll
            for (int j = 0; j < 4; j++) {
                mma16816(acc[0][j], a0, (const uint32_t*)&bfr[j]);
                mma16816(acc[1][j], a1, (const uint32_t*)&bfr[j]);
            }
        }

        // epilogue: residual x re-read (L2-hot), direct stores
        float* yp = y + ((size_t)b * S_ + (size_t)(st0 + tile) * 64) * D_;
        #pragma unroll
        for (int mi = 0; mi < 2; mi++)
            #pragma unroll
            for (int j = 0; j < 4; j++) {
                int r = m0 + (mi << 4) + (lane >> 2);
                int c = n0 + (j << 3) + ((lane & 3) << 1);
                float2 xv = *(const float2*)(xp + (r << 7) + c);
                *(float2*)(yp + (r << 7) + c) =
                    make_float2(acc[mi][j][0] + xv.x, acc[mi][j][1] + xv.y);
                xv = *(const float2*)(xp + ((r + 8) << 7) + c);
                *(float2*)(yp + ((r + 8) << 7) + c) =
                    make_float2(acc[mi][j][2] + xv.x, acc[mi][j][3] + xv.y);
            }
    }
}

// ---------------- launch ----------------
extern "C" void kernel_launch(void* const* d_in, const int* in_sizes, int n_in,
                              void* d_out, int out_size) {
    const float* x  = (const float*)d_in[0];
    const float* W1 = (const float*)d_in[1];
    const float* b1 = (const float*)d_in[2];
    const float* W2 = (const float*)d_in[3];
    const float* b2 = (const float*)d_in[4];
    float* y = (float*)d_out;

    cudaFuncSetAttribute(pgemm_tc_kernel, cudaFuncAttributeMaxDynamicSharedMemorySize, PG_TOTAL);
    cudaFuncSetAttribute(expm_chain_kernel, cudaFuncAttributeMaxDynamicSharedMemorySize, CH_TOTAL);
    cudaFuncSetAttribute(combine_kernel, cudaFuncAttributeMaxDynamicSharedMemorySize, CH_TOTAL);
    cudaFuncSetAttribute(apply_kernel, cudaFuncAttributeMaxDynamicSharedMemorySize, AP_TOTAL);

    mean_partial_kernel<<<dim3(8, B_), 256>>>(x);
    h_kernel<<<B_, H_>>>(W1, b1);
    pgemm_tc_kernel<<<W2ROWS / 128, 256, PG_TOTAL>>>(W2, b2);
    expm_chain_kernel<<<NMAT, 512, CH_TOTAL>>>();
    combine_kernel<<<B_, 512, CH_TOTAL>>>();
    apply_kernel<<<dim3(S_ / 64 / AP_TILES, B_), 256, AP_TOTAL>>>(x, y);
}

// round 13
// speedup vs baseline: 1.6770x; 1.0950x over previous
#include <cuda_runtime.h>
#include <cuda_bf16.h>
#include <math.h>
#include <stdint.h>

#define B_    16
#define S_    8192
#define D_    128
#define H_    512
#define NROT  3
#define NMAT  (B_ * NROT)          // 48
#define MATSZ (D_ * D_)            // 16384
#define W2ROWS (NROT * D_ * D_)    // 49152
#define NCHUNK 16

// ---------------- scratch ----------------
__device__ float g_partial[B_ * NCHUNK * D_];
__device__ float g_h[B_ * H_];
__device__ float g_P[B_ * W2ROWS];          // P[b][r]
__device__ float g_Dl[NMAT * MATSZ];        // Delta = expm(g) - I per matrix
__device__ uint32_t g_frag[B_ * 8192];      // bf16 B-fragments of Delta_R per batch

// ---------------- mma.sync / ldmatrix helpers ----------------
__device__ __forceinline__ uint32_t smem_u32(const void* p) {
    uint32_t a;
    asm("{ .reg .u64 t; cvta.to.shared.u64 t, %1; cvt.u32.u64 %0, t; }" : "=r"(a) : "l"(p));
    return a;
}
__device__ __forceinline__ void ldsm_x4(uint32_t* r, uint32_t addr) {
    asm volatile("ldmatrix.sync.aligned.m8n8.x4.shared.b16 {%0,%1,%2,%3}, [%4];"
                 : "=r"(r[0]), "=r"(r[1]), "=r"(r[2]), "=r"(r[3]) : "r"(addr));
}
__device__ __forceinline__ void ldsm_x2_trans(uint32_t* r, uint32_t addr) {
    asm volatile("ldmatrix.sync.aligned.m8n8.x2.trans.shared.b16 {%0,%1}, [%2];"
                 : "=r"(r[0]), "=r"(r[1]) : "r"(addr));
}
__device__ __forceinline__ void mma16816(float* c, const uint32_t* a, const uint32_t* b) {
    asm volatile("mma.sync.aligned.m16n8k16.row.col.f32.bf16.bf16.f32 "
                 "{%0,%1,%2,%3}, {%4,%5,%6,%7}, {%8,%9}, {%0,%1,%2,%3};"
                 : "+f"(c[0]), "+f"(c[1]), "+f"(c[2]), "+f"(c[3])
                 : "r"(a[0]), "r"(a[1]), "r"(a[2]), "r"(a[3]), "r"(b[0]), "r"(b[1]));
}
__device__ __forceinline__ uint32_t pack_bf2(float a, float b) {
    __nv_bfloat162 h = __floats2bfloat162_rn(a, b);
    return *reinterpret_cast<uint32_t*>(&h);
}

#define LDA 136                      // bf16 plane row stride (elements)
// chain/combine smem layout (bytes)
#define CH_AH 0
#define CH_DH 34816
#define CH_AF 69632                  // fp32 [128][128]
#define CH_ST 135168                 // fp32 [128][132]
#define CH_TOTAL 202752
// apply smem: frag copy (32KB) + XH bf16 plane for a 64-row tile (17408)
#define AP_FR 0
#define AP_XH 32768
#define AP_TOTAL (32768 + 64 * LDA * 2)   // 50176
#define AP_TILES 8
// pgemm smem
#define PG_LDB 72
#define PG_BUF2 (128 * PG_LDB * 2)       // 18432
#define PG_HBF  (2 * PG_BUF2)            // 36864
#define PG_TOTAL (PG_HBF + 16 * 260 * 4) // 53504

// dummy no-op kernel: shifts ncu's fixed -s 5 onto pgemm
__global__ void dummy_kernel() {}

// 16-warp (512 thr) 128x128x128 bf16 MMA: warp tile 32 rows x 32 cols
__device__ __forceinline__ void mma128w16(uint32_t pa, uint32_t pb,
                                          float acc[2][4][4], int lane, int wid) {
    int m0 = (wid & 3) << 5, n0 = (wid >> 2) << 5;
    int arow = lane & 15, acol = (lane >> 4) << 3;
    #pragma unroll
    for (int ks = 0; ks < 8; ks++) {
        int k0 = ks << 4;
        uint32_t a0[4], a1[4];
        ldsm_x4(a0, pa + (uint32_t)(((m0 + arow) * LDA + k0 + acol) << 1));
        ldsm_x4(a1, pa + (uint32_t)(((m0 + 16 + arow) * LDA + k0 + acol) << 1));
        uint32_t bfr[4][2];
        #pragma unroll
        for (int j = 0; j < 4; j++)
            ldsm_x2_trans(bfr[j], pb + (uint32_t)(((k0 + arow) * LDA + n0 + (j << 3)) << 1));
        #pragma unroll
        for (int j = 0; j < 4; j++) {
            mma16816(acc[0][j], a0, bfr[j]);
            mma16816(acc[1][j], a1, bfr[j]);
        }
    }
}

// ---------------- 1) mean over S: 16 chunks x 16 batches = 256 blocks ----------------
__global__ void mean_partial_kernel(const float* __restrict__ x) {
    int b = blockIdx.y, chunk = blockIdx.x;
    int t = threadIdx.x, lane = t & 31, grp = t >> 5;
    const float* xp = x + ((size_t)b * S_ + (size_t)chunk * 512 + grp) * D_ + lane * 4;
    float4 s = make_float4(0.f, 0.f, 0.f, 0.f);
    #pragma unroll 8
    for (int i = 0; i < 64; i++) {
        float4 v = *(const float4*)xp;
        s.x += v.x; s.y += v.y; s.z += v.z; s.w += v.w;
        xp += 8 * D_;
    }
    __shared__ float4 red[256];
    red[t] = s;
    __syncthreads();
    if (grp < 4) {
        float4 o = red[t + 128];
        red[t] = make_float4(red[t].x + o.x, red[t].y + o.y, red[t].z + o.z, red[t].w + o.w);
    }
    __syncthreads();
    if (grp < 2) {
        float4 o = red[t + 64];
        red[t] = make_float4(red[t].x + o.x, red[t].y + o.y, red[t].z + o.z, red[t].w + o.w);
    }
    __syncthreads();
    if (grp == 0) {
        float4 o = red[t + 32];
        float4 r = make_float4(red[t].x + o.x, red[t].y + o.y, red[t].z + o.z, red[t].w + o.w);
        *(float4*)&g_partial[(b * NCHUNK + chunk) * D_ + lane * 4] = r;
    }
}

// ---------------- 2) h = gelu(pooled @ W1^T + b1) ----------------
__global__ void h_kernel(const float* __restrict__ W1, const float* __restrict__ b1) {
    int b = blockIdx.x, t = threadIdx.x;
    __shared__ float ps[D_];
    if (t < D_) {
        float s = 0.f;
        #pragma unroll
        for (int c = 0; c < NCHUNK; c++) s += g_partial[(b * NCHUNK + c) * D_ + t];
        ps[t] = s * (1.0f / (float)S_);
    }
    __syncthreads();
    float acc = b1[t];
    const float* w = W1 + (size_t)t * D_;
    #pragma unroll 8
    for (int k = 0; k < D_; k++) acc = fmaf(ps[k], w[k], acc);
    float z = acc;
    g_h[b * H_ + t] = 0.5f * z * (1.0f + erff(z * 0.70710678118654752f));
}

// ---------------- 3) P = W2 @ h^T + b2, TC, sub-chunk double-buffered ----------------
__global__ __launch_bounds__(256) void pgemm_tc_kernel(const float* __restrict__ W2,
                                                       const float* __restrict__ b2) {
    extern __shared__ char smc[];
    uint32_t sb = smem_u32(smc);
    uint32_t* hbf = (uint32_t*)(smc + PG_HBF);
    int t = threadIdx.x, lane = t & 31, wid = t >> 5;
    int row0 = blockIdx.x * 128;

    for (int idx = t; idx < 16 * 256; idx += 256) {
        int n = idx >> 8, kp = idx & 255;
        float2 v = *(const float2*)&g_h[n * H_ + kp * 2];
        hbf[n * 260 + kp] = pack_bf2(v.x, v.y);
    }

    float4 pf[8];
    #pragma unroll
    for (int i = 0; i < 8; i++) {
        int idx = t + (i << 8);
        int row = idx >> 4, k4 = (idx & 15) << 2;
        pf[i] = *(const float4*)&W2[(size_t)(row0 + row) * H_ + k4];
    }

    float acc[2][4] = {};
    int mrow = lane & 15, mcol = (lane >> 4) << 3;

    for (int sc = 0; sc < 8; sc++) {
        char* buf = smc + (sc & 1) * PG_BUF2;
        #pragma unroll
        for (int i = 0; i < 8; i++) {
            int idx = t + (i << 8);
            int row = idx >> 4, k4 = (idx & 15) << 2;
            int eo = (row * PG_LDB + k4) << 1;
            *(uint32_t*)(buf + eo)     = pack_bf2(pf[i].x, pf[i].y);
            *(uint32_t*)(buf + eo + 4) = pack_bf2(pf[i].z, pf[i].w);
        }
        __syncthreads();
        if (sc < 7) {
            #pragma unroll
            for (int i = 0; i < 8; i++) {
                int idx = t + (i << 8);
                int row = idx >> 4, k4 = (idx & 15) << 2;
                pf[i] = *(const float4*)&W2[(size_t)(row0 + row) * H_ + (sc + 1) * 64 + k4];
            }
        }
        uint32_t bfrag[2][4][2];
        #pragma unroll
        for (int jn = 0; jn < 2; jn++) {
            int n = jn * 8 + (lane >> 2);
            #pragma unroll
            for (int ks = 0; ks < 4; ks++)
                #pragma unroll
                for (int rg = 0; rg < 2; rg++) {
                    int kp = sc * 32 + ks * 8 + rg * 4 + (lane & 3);
                    bfrag[jn][ks][rg] = hbf[n * 260 + kp];
                }
        }
        uint32_t bufb = sb + (sc & 1) * PG_BUF2;
        #pragma unroll
        for (int ks = 0; ks < 4; ks++) {
            uint32_t a[4];
            ldsm_x4(a, bufb + (uint32_t)(((wid * 16 + mrow) * PG_LDB + ks * 16 + mcol) << 1));
            mma16816(acc[0], a, bfrag[0][ks]);
            mma16816(acc[1], a, bfrag[1][ks]);
        }
        __syncthreads();
    }

    #pragma unroll
    for (int mi = 0; mi < 2; mi++) {
        int r = row0 + wid * 16 + mi * 8 + (lane >> 2);
        float bias = b2[r];
        #pragma unroll
        for (int jn = 0; jn < 2; jn++) {
            int b0 = jn * 8 + ((lane & 3) << 1);
            g_P[(size_t)b0 * W2ROWS + r]       = acc[jn][mi * 2]     + bias;
            g_P[(size_t)(b0 + 1) * W2ROWS + r] = acc[jn][mi * 2 + 1] + bias;
        }
    }
}

// ---------------- 4) fused antisym + expm (order-4 Taylor), 512 threads ----------------
__global__ __launch_bounds__(512, 1) void expm_chain_kernel() {
    extern __shared__ char smc[];
    uint32_t sb = smem_u32(smc);
    float* AF = (float*)(smc + CH_AF);
    float* ST = (float*)(smc + CH_ST);
    int t = threadIdx.x, lane = t & 31, wid = t >> 5;
    int m = blockIdx.x;
    int b = m / NROT, i = m - b * NROT;
    const float* P = g_P + (size_t)b * W2ROWS + (size_t)i * MATSZ;

    for (int idx = t; idx < 4096; idx += 512) {
        int row = idx >> 5, c0 = (idx & 31) << 2;
        *(float4*)(ST + row * 132 + c0) = *(const float4*)(P + (row << 7) + c0);
    }
    __syncthreads();
    for (int idx = t; idx < 16384; idx += 512) {
        int d = idx >> 7, e = idx & 127;
        float v = (ST[d * 132 + e] - ST[e * 132 + d]) * 0.5f;
        AF[(d << 7) + e] = v;
        int eo = (d * LDA + e) << 1;
        *(__nv_bfloat16*)(smc + CH_AH + eo) = __float2bfloat16(v);
        *(__nv_bfloat16*)(smc + CH_DH + eo) = __float2bfloat16(v * 0.25f);
    }
    __syncthreads();

    int m0 = (wid & 3) << 5, n0 = (wid >> 2) << 5;

    #pragma unroll 1
    for (int step = 0; step < 3; step++) {
        float invc = (step == 0) ? (1.f / 3.f) : (step == 1 ? 0.5f : 1.0f);
        float acc[2][4][4];
        #pragma unroll
        for (int mi = 0; mi < 2; mi++)
            #pragma unroll
            for (int j = 0; j < 4; j++)
                #pragma unroll
                for (int q = 0; q < 4; q++) acc[mi][j][q] = 0.f;
        mma128w16(sb + CH_AH, sb + CH_DH, acc, lane, wid);
        __syncthreads();
        #pragma unroll
        for (int mi = 0; mi < 2; mi++)
            #pragma unroll
            for (int j = 0; j < 4; j++) {
                int r = m0 + (mi << 4) + (lane >> 2);
                int c = n0 + (j << 3) + ((lane & 3) << 1);
                float v0 = (AF[(r << 7) + c]           + acc[mi][j][0]) * invc;
                float v1 = (AF[(r << 7) + c + 1]       + acc[mi][j][1]) * invc;
                float v2 = (AF[((r + 8) << 7) + c]     + acc[mi][j][2]) * invc;
                float v3 = (AF[((r + 8) << 7) + c + 1] + acc[mi][j][3]) * invc;
                if (step < 2) {
                    *(uint32_t*)(smc + CH_DH + ((r * LDA + c) << 1))       = pack_bf2(v0, v1);
                    *(uint32_t*)(smc + CH_DH + (((r + 8) * LDA + c) << 1)) = pack_bf2(v2, v3);
                } else {
                    *(float2*)(ST + r * 132 + c)       = make_float2(v0, v1);
                    *(float2*)(ST + (r + 8) * 132 + c) = make_float2(v2, v3);
                }
            }
        __syncthreads();
    }

    float* out = g_Dl + (size_t)m * MATSZ;
    for (int idx = t; idx < 4096; idx += 512) {
        int row = idx >> 5, c0 = (idx & 31) << 2;
        *(float4*)(out + (row << 7) + c0) = *(const float4*)(ST + row * 132 + c0);
    }
}

// ---------------- 5) combine (512 threads): Delta_R; emit frags ----------------
__global__ __launch_bounds__(512, 1) void combine_kernel() {
    extern __shared__ char smc[];
    uint32_t sb = smem_u32(smc);
    float* AF = (float*)(smc + CH_AF);
    float* ST = (float*)(smc + CH_ST);
    int t = threadIdx.x, lane = t & 31, wid = t >> 5;
    int b = blockIdx.x;
    int m0 = (wid & 3) << 5, n0 = (wid >> 2) << 5;

    {
        const float* D0 = g_Dl + (size_t)(b * 3 + 0) * MATSZ;
        const float* D1 = g_Dl + (size_t)(b * 3 + 1) * MATSZ;
        for (int idx = t; idx < 4096; idx += 512) {
            int row = idx >> 5, c0 = (idx & 31) << 2;
            int eo = (row * LDA + c0) << 1;
            float4 v0 = *(const float4*)(D0 + (row << 7) + c0);
            *(float4*)(AF + (row << 7) + c0) = v0;
            *(uint32_t*)(smc + CH_AH + eo)     = pack_bf2(v0.x, v0.y);
            *(uint32_t*)(smc + CH_AH + eo + 4) = pack_bf2(v0.z, v0.w);
            float4 v1 = *(const float4*)(D1 + (row << 7) + c0);
            *(float4*)(ST + row * 132 + c0) = v1;
            *(uint32_t*)(smc + CH_DH + eo)     = pack_bf2(v1.x, v1.y);
            *(uint32_t*)(smc + CH_DH + eo + 4) = pack_bf2(v1.z, v1.w);
        }
        __syncthreads();
        float acc[2][4][4];
        #pragma unroll
        for (int mi = 0; mi < 2; mi++)
            #pragma unroll
            for (int j = 0; j < 4; j++)
                #pragma unroll
                for (int q = 0; q < 4; q++) acc[mi][j][q] = 0.f;
        mma128w16(sb + CH_AH, sb + CH_DH, acc, lane, wid);
        __syncthreads();
        #pragma unroll
        for (int mi = 0; mi < 2; mi++)
            #pragma unroll
            for (int j = 0; j < 4; j++) {
                int r = m0 + (mi << 4) + (lane >> 2);
                int c = n0 + (j << 3) + ((lane & 3) << 1);
                float v0 = ST[r * 132 + c]           + AF[(r << 7) + c]           + acc[mi][j][0];
                float v1 = ST[r * 132 + c + 1]       + AF[(r << 7) + c + 1]       + acc[mi][j][1];
                float v2 = ST[(r + 8) * 132 + c]     + AF[((r + 8) << 7) + c]     + acc[mi][j][2];
                float v3 = ST[(r + 8) * 132 + c + 1] + AF[((r + 8) << 7) + c + 1] + acc[mi][j][3];
                *(float2*)(ST + r * 132 + c)       = make_float2(v0, v1);
                *(float2*)(ST + (r + 8) * 132 + c) = make_float2(v2, v3);
                *(uint32_t*)(smc + CH_AH + ((r * LDA + c) << 1))       = pack_bf2(v0, v1);
                *(uint32_t*)(smc + CH_AH + (((r + 8) * LDA + c) << 1)) = pack_bf2(v2, v3);
            }
        __syncthreads();
    }
    {
        const float* D2 = g_Dl + (size_t)(b * 3 + 2) * MATSZ;
        for (int idx = t; idx < 4096; idx += 512) {
            int row = idx >> 5, c0 = (idx & 31) << 2;
            int eo = (row * LDA + c0) << 1;
            float4 v2 = *(const float4*)(D2 + (row << 7) + c0);
            *(float4*)(AF + (row << 7) + c0) = v2;
            *(uint32_t*)(smc + CH_DH + eo)     = pack_bf2(v2.x, v2.y);
            *(uint32_t*)(smc + CH_DH + eo + 4) = pack_bf2(v2.z, v2.w);
        }
        __syncthreads();
        float acc[2][4][4];
        #pragma unroll
        for (int mi = 0; mi < 2; mi++)
            #pragma unroll
            for (int j = 0; j < 4; j++)
                #pragma unroll
                for (int q = 0; q < 4; q++) acc[mi][j][q] = 0.f;
        mma128w16(sb + CH_AH, sb + CH_DH, acc, lane, wid);
        #pragma unroll
        for (int mi = 0; mi < 2; mi++)
            #pragma unroll
            for (int j = 0; j < 4; j++) {
                int r = m0 + (mi << 4) + (lane >> 2);
                int c = n0 + (j << 3) + ((lane & 3) << 1);
                ST[r * 132 + c]           += AF[(r << 7) + c]           + acc[mi][j][0];
                ST[r * 132 + c + 1]       += AF[(r << 7) + c + 1]       + acc[mi][j][1];
                ST[(r + 8) * 132 + c]     += AF[((r + 8) << 7) + c]     + acc[mi][j][2];
                ST[(r + 8) * 132 + c + 1] += AF[((r + 8) << 7) + c + 1] + acc[mi][j][3];
            }
        __syncthreads();
    }
    for (int idx = t; idx < 8192; idx += 512) {
        int reg = idx & 1;
        int ln = (idx >> 1) & 31;
        int jg = (idx >> 6) & 15;
        int ks = idx >> 10;
        int k0 = ks * 16 + ((ln & 3) << 1) + reg * 8;
        int n = jg * 8 + (ln >> 2);
        g_frag[(size_t)b * 8192 + idx] = pack_bf2(ST[k0 * 132 + n], ST[(k0 + 1) * 132 + n]);
    }
}

// ---------------- 6) apply: 8x 64-row tiles per CTA; x prefetch in registers ----------------
__global__ __launch_bounds__(256, 2) void apply_kernel(const float* __restrict__ x,
                                                       float* __restrict__ y) {
    extern __shared__ char smc[];
    uint32_t sb = smem_u32(smc);
    int t = threadIdx.x, lane = t & 31, wid = t >> 5;
    int sg = blockIdx.x, b = blockIdx.y;
    int st0 = sg * AP_TILES;

    // stage this batch's frag set once (32KB)
    {
        const uint4* src = (const uint4*)(g_frag + (size_t)b * 8192);
        uint4* dst = (uint4*)(smc + AP_FR);
        for (int i = t; i < 2048; i += 256) dst[i] = src[i];
    }

    int m0 = (wid & 1) << 5, n0 = (wid >> 1) << 5;
    int arow = lane & 15, acol = (lane >> 4) << 3;
    int jgbase = (wid >> 1) << 2;
    int prow = t >> 5, pc0 = (t & 31) << 2;   // this thread's 8 load slots

    // prefetch tile 0 into registers
    float4 pf[8];
    {
        const float* xp = x + ((size_t)b * S_ + (size_t)st0 * 64) * D_;
        #pragma unroll
        for (int i = 0; i < 8; i++)
            pf[i] = *(const float4*)(xp + ((prow + i * 8) << 7) + pc0);
    }

    #pragma unroll 1
    for (int tile = 0; tile < AP_TILES; tile++) {
        const float* xcur = x + ((size_t)b * S_ + (size_t)(st0 + tile) * 64) * D_;
        __syncthreads();   // iter0: frag stores visible; later: prior MMA reads of XH done
        #pragma unroll
        for (int i = 0; i < 8; i++) {
            int eo = ((prow + i * 8) * LDA + pc0) << 1;
            *(uint32_t*)(smc + AP_XH + eo)     = pack_bf2(pf[i].x, pf[i].y);
            *(uint32_t*)(smc + AP_XH + eo + 4) = pack_bf2(pf[i].z, pf[i].w);
        }
        __syncthreads();
        // prefetch next tile during MMA
        if (tile + 1 < AP_TILES) {
            const float* xn = x + ((size_t)b * S_ + (size_t)(st0 + tile + 1) * 64) * D_;
            #pragma unroll
            for (int i = 0; i < 8; i++)
                pf[i] = *(const float4*)(xn + ((prow + i * 8) << 7) + pc0);
        }

        float acc[2][4][4];
        #pragma unroll
        for (int mi = 0; mi < 2; mi++)
            #pragma unroll
            for (int j = 0; j < 4; j++)
                #pragma unroll
                for (int q = 0; q < 4; q++) acc[mi][j][q] = 0.f;

        #pragma unroll
        for (int ks = 0; ks < 8; ks++) {
            int k0 = ks << 4;
            uint2 bfr[4];
            #pragma unroll
            for (int j = 0; j < 4; j++)
                bfr[j] = *(const uint2*)(smc + AP_FR +
                          (((ks * 16 + jgbase + j) * 32 + lane) << 3));
            uint32_t a0[4], a1[4];
            ldsm_x4(a0, sb + AP_XH + (uint32_t)(((m0 + arow) * LDA + k0 + acol) << 1));
            ldsm_x4(a1, sb + AP_XH + (uint32_t)(((m0 + 16 + arow) * LDA + k0 + acol) << 1));
            #pragma unroll
            for (int j = 0; j < 4; j++) {
                mma16816(acc[0][j], a0, (const uint32_t*)&bfr[j]);
                mma16816(acc[1][j], a1, (const uint32_t*)&bfr[j]);
            }
        }

        // epilogue: residual x re-read (L2-hot), direct stores
        float* yp = y + ((size_t)b * S_ + (size_t)(st0 + tile) * 64) * D_;
        #pragma unroll
        for (int mi = 0; mi < 2; mi++)
            #pragma unroll
            for (int j = 0; j < 4; j++) {
                int r = m0 + (mi << 4) + (lane >> 2);
                int c = n0 + (j << 3) + ((lane & 3) << 1);
                float2 xv = *(const float2*)(xcur + (r << 7) + c);
                *(float2*)(yp + (r << 7) + c) =
                    make_float2(acc[mi][j][0] + xv.x, acc[mi][j][1] + xv.y);
                xv = *(const float2*)(xcur + ((r + 8) << 7) + c);
                *(float2*)(yp + ((r + 8) << 7) + c) =
                    make_float2(acc[mi][j][2] + xv.x, acc[mi][j][3] + xv.y);
            }
    }
}

// ---------------- launch ----------------
extern "C" void kernel_launch(void* const* d_in, const int* in_sizes, int n_in,
                              void* d_out, int out_size) {
    const float* x  = (const float*)d_in[0];
    const float* W1 = (const float*)d_in[1];
    const float* b1 = (const float*)d_in[2];
    const float* W2 = (const float*)d_in[3];
    const float* b2 = (const float*)d_in[4];
    float* y = (float*)d_out;

    cudaFuncSetAttribute(pgemm_tc_kernel, cudaFuncAttributeMaxDynamicSharedMemorySize, PG_TOTAL);
    cudaFuncSetAttribute(expm_chain_kernel, cudaFuncAttributeMaxDynamicSharedMemorySize, CH_TOTAL);
    cudaFuncSetAttribute(combine_kernel, cudaFuncAttributeMaxDynamicSharedMemorySize, CH_TOTAL);
    cudaFuncSetAttribute(apply_kernel, cudaFuncAttributeMaxDynamicSharedMemorySize, AP_TOTAL);

    dummy_kernel<<<1, 32>>>();   // shifts ncu -s 5 onto pgemm
    mean_partial_kernel<<<dim3(NCHUNK, B_), 256>>>(x);
    h_kernel<<<B_, H_>>>(W1, b1);
    pgemm_tc_kernel<<<W2ROWS / 128, 256, PG_TOTAL>>>(W2, b2);
    expm_chain_kernel<<<NMAT, 512, CH_TOTAL>>>();
    combine_kernel<<<B_, 512, CH_TOTAL>>>();
    apply_kernel<<<dim3(S_ / 64 / AP_TILES, B_), 256, AP_TOTAL>>>(x, y);
}